// round 9
// baseline (speedup 1.0000x reference)
#include <cuda_runtime.h>
#include <math.h>
#include <stdint.h>

#define BB 4
#define LL 1025
#define NT 1361
#define DD 512
#define HH 8
#define DFF 2048
#define MROWS (BB*NT)         // 5444

// ---------------- scratch (static device allocations) ----------------
__device__ float g_emb [BB*LL*DD];
__device__ float g_d0  [BB*LL*128];
__device__ float g_cc  [BB*336*128];
__device__ float g_pyr [BB*336*DD];
__device__ float g_seq [BB*NT*DD];
__device__ float g_seqr[BB*NT*DD];      // tf32-rounded copy (GEMM A operand)
__device__ float g_qkv [BB*NT*1536];
__device__ float g_o   [BB*NT*DD];      // tf32-rounded at producer
__device__ float g_tmp [BB*NT*DD];
__device__ float g_ffn [BB*NT*DFF];     // tf32-rounded at producer (W1 epilogue)
// tf32-rounded weight packs (original [K][N] layout)
__device__ float g_wqkv[4*512*1536];
__device__ float g_wo  [4*512*512];
__device__ float g_w1  [4*512*2048];
__device__ float g_w2  [4*2048*512];

// ---------------- helpers ----------------
__device__ __forceinline__ uint32_t f2tf(float x) {
    uint32_t r;
    asm("cvt.rna.tf32.f32 %0, %1;" : "=r"(r) : "f"(x));
    return r;
}
__device__ __forceinline__ float f2tf_f(float x) { return __uint_as_float(f2tf(x)); }
__device__ __forceinline__ float gelu_exact(float x) {
    return 0.5f * x * (1.0f + erff(x * 0.70710678118654752f));
}
__device__ __forceinline__ void mma_tf32(float c[4], const uint32_t a[4], const uint32_t b[2]) {
    asm volatile(
        "mma.sync.aligned.m16n8k8.row.col.f32.tf32.tf32.f32 "
        "{%0,%1,%2,%3}, {%4,%5,%6,%7}, {%8,%9}, {%0,%1,%2,%3};\n"
        : "+f"(c[0]), "+f"(c[1]), "+f"(c[2]), "+f"(c[3])
        : "r"(a[0]), "r"(a[1]), "r"(a[2]), "r"(a[3]), "r"(b[0]), "r"(b[1]));
}

// ---------------- weight rounding packs ----------------
__global__ void pack_qkv(const float* __restrict__ Wq,
                         const float* __restrict__ Wk,
                         const float* __restrict__ Wv) {
    int idx = blockIdx.x * blockDim.x + threadIdx.x;   // over 4*512*128 float4s
    if (idx >= 4*512*128) return;
    int n4 = idx & 127;
    int k  = (idx >> 7) & 511;
    int l  = idx >> 16;
    size_t src = ((size_t)l*512 + k)*512;
    float4 q = ((const float4*)(Wq + src))[n4];
    float4 kk = ((const float4*)(Wk + src))[n4];
    float4 v = ((const float4*)(Wv + src))[n4];
    q.x=f2tf_f(q.x); q.y=f2tf_f(q.y); q.z=f2tf_f(q.z); q.w=f2tf_f(q.w);
    kk.x=f2tf_f(kk.x); kk.y=f2tf_f(kk.y); kk.z=f2tf_f(kk.z); kk.w=f2tf_f(kk.w);
    v.x=f2tf_f(v.x); v.y=f2tf_f(v.y); v.z=f2tf_f(v.z); v.w=f2tf_f(v.w);
    float4* dst = (float4*)(g_wqkv + ((size_t)l*512 + k)*1536);
    dst[n4] = q; dst[128 + n4] = kk; dst[256 + n4] = v;
}
__global__ void round_copy(const float* __restrict__ in, float* __restrict__ out, int n4) {
    int i = blockIdx.x*blockDim.x + threadIdx.x;
    if (i >= n4) return;
    float4 v = ((const float4*)in)[i];
    v.x = f2tf_f(v.x); v.y = f2tf_f(v.y); v.z = f2tf_f(v.z); v.w = f2tf_f(v.w);
    ((float4*)out)[i] = v;
}

// ---------------- TF32 mma.sync GEMM: C = A(MxK)@B(KxN) [+bias][+gelu+round] -------
// BM=BN=128, BK=16; 128 threads = 4 warps (2M x 2N), warp tile 64x64.
// 1.0 fragment-LDS per MMA (was 1.5 with 32x64 warp tiles).
// Smem stride 136 (mod 32 == 8) -> conflict-free fragment loads.
// RND=1: loader rounds inputs to tf32; RND=0: inputs pre-rounded (pure copy loader).
template<int ACT, int RND>
__global__ __launch_bounds__(128)
void tgemm_kernel(const float* __restrict__ A, const float* __restrict__ Bm,
                  const float* __restrict__ bias, float* __restrict__ C,
                  int M, int N, int K) {
    __shared__ uint32_t As[2][16][136];
    __shared__ uint32_t Bs[2][16][136];
    int tid = threadIdx.x;
    int bx = blockIdx.x, by = blockIdx.y;
    int w = tid >> 5, lane = tid & 31;
    int wm = w & 1, wn = w >> 1;
    int g = lane >> 2, t4 = lane & 3;

    float c[4][8][4];
    #pragma unroll
    for (int mt = 0; mt < 4; mt++)
        #pragma unroll
        for (int nt = 0; nt < 8; nt++)
            #pragma unroll
            for (int r = 0; r < 4; r++) c[mt][nt][r] = 0.f;

    // A loader: rows am+32i (i=0..3) at k = ak..ak+3 (store transposed k-major)
    int am = tid >> 2;            // 0..31
    int ak = (tid & 3) * 4;       // 0,4,8,12
    const float* Ap = A + (size_t)(by*128 + am) * K + ak;
    bool va[4];
    #pragma unroll
    for (int i = 0; i < 4; i++) va[i] = (by*128 + am + 32*i) < M;

    // B loader: rows bk+4i (i=0..3) at n = bn..bn+3
    int bk = tid >> 5;            // 0..3
    int bn = (tid & 31) * 4;
    const float* Bp = Bm + (size_t)bk * N + bx*128 + bn;

    int nk = K >> 4;
    float4 a[4], b[4];

    #define CVT(x) (RND ? f2tf(x) : __float_as_uint(x))

    // prologue: tile 0
    {
        #pragma unroll
        for (int i = 0; i < 4; i++)
            a[i] = va[i] ? *(const float4*)(Ap + (size_t)(32*i)*K)
                         : make_float4(0.f,0.f,0.f,0.f);
        #pragma unroll
        for (int i = 0; i < 4; i++)
            b[i] = *(const float4*)(Bp + (size_t)(4*i) * N);
        #pragma unroll
        for (int i = 0; i < 4; i++) {
            As[0][ak+0][am+32*i] = CVT(a[i].x); As[0][ak+1][am+32*i] = CVT(a[i].y);
            As[0][ak+2][am+32*i] = CVT(a[i].z); As[0][ak+3][am+32*i] = CVT(a[i].w);
        }
        if (RND) {
            #pragma unroll
            for (int i = 0; i < 4; i++) {
                Bs[0][bk+4*i][bn+0] = CVT(b[i].x); Bs[0][bk+4*i][bn+1] = CVT(b[i].y);
                Bs[0][bk+4*i][bn+2] = CVT(b[i].z); Bs[0][bk+4*i][bn+3] = CVT(b[i].w);
            }
        } else {
            #pragma unroll
            for (int i = 0; i < 4; i++)
                *(float4*)&Bs[0][bk+4*i][bn] = b[i];
        }
    }
    __syncthreads();

    int mb = wm*64 + g;
    int nb = wn*64 + g;
    int buf = 0;
    for (int tile = 1; tile < nk; tile++) {
        // prefetch tile
        #pragma unroll
        for (int i = 0; i < 4; i++)
            a[i] = va[i] ? *(const float4*)(Ap + (size_t)(32*i)*K + tile*16)
                         : make_float4(0.f,0.f,0.f,0.f);
        #pragma unroll
        for (int i = 0; i < 4; i++)
            b[i] = *(const float4*)(Bp + (size_t)(tile*16 + 4*i) * N);

        // compute previous tile
        #pragma unroll
        for (int ks = 0; ks < 16; ks += 8) {
            uint32_t af[4][4], bf[8][2];
            #pragma unroll
            for (int mt = 0; mt < 4; mt++) {
                af[mt][0] = As[buf][ks+t4  ][mb + mt*16];
                af[mt][1] = As[buf][ks+t4  ][mb + mt*16 + 8];
                af[mt][2] = As[buf][ks+t4+4][mb + mt*16];
                af[mt][3] = As[buf][ks+t4+4][mb + mt*16 + 8];
            }
            #pragma unroll
            for (int nt = 0; nt < 8; nt++) {
                bf[nt][0] = Bs[buf][ks+t4  ][nb + nt*8];
                bf[nt][1] = Bs[buf][ks+t4+4][nb + nt*8];
            }
            #pragma unroll
            for (int mt = 0; mt < 4; mt++)
                #pragma unroll
                for (int nt = 0; nt < 8; nt++)
                    mma_tf32(c[mt][nt], af[mt], bf[nt]);
        }

        int nbuf = buf ^ 1;
        #pragma unroll
        for (int i = 0; i < 4; i++) {
            As[nbuf][ak+0][am+32*i] = CVT(a[i].x); As[nbuf][ak+1][am+32*i] = CVT(a[i].y);
            As[nbuf][ak+2][am+32*i] = CVT(a[i].z); As[nbuf][ak+3][am+32*i] = CVT(a[i].w);
        }
        if (RND) {
            #pragma unroll
            for (int i = 0; i < 4; i++) {
                Bs[nbuf][bk+4*i][bn+0] = CVT(b[i].x); Bs[nbuf][bk+4*i][bn+1] = CVT(b[i].y);
                Bs[nbuf][bk+4*i][bn+2] = CVT(b[i].z); Bs[nbuf][bk+4*i][bn+3] = CVT(b[i].w);
            }
        } else {
            #pragma unroll
            for (int i = 0; i < 4; i++)
                *(float4*)&Bs[nbuf][bk+4*i][bn] = b[i];
        }
        __syncthreads();
        buf = nbuf;
    }

    // compute last tile
    #pragma unroll
    for (int ks = 0; ks < 16; ks += 8) {
        uint32_t af[4][4], bf[8][2];
        #pragma unroll
        for (int mt = 0; mt < 4; mt++) {
            af[mt][0] = As[buf][ks+t4  ][mb + mt*16];
            af[mt][1] = As[buf][ks+t4  ][mb + mt*16 + 8];
            af[mt][2] = As[buf][ks+t4+4][mb + mt*16];
            af[mt][3] = As[buf][ks+t4+4][mb + mt*16 + 8];
        }
        #pragma unroll
        for (int nt = 0; nt < 8; nt++) {
            bf[nt][0] = Bs[buf][ks+t4  ][nb + nt*8];
            bf[nt][1] = Bs[buf][ks+t4+4][nb + nt*8];
        }
        #pragma unroll
        for (int mt = 0; mt < 4; mt++)
            #pragma unroll
            for (int nt = 0; nt < 8; nt++)
                mma_tf32(c[mt][nt], af[mt], bf[nt]);
    }
    #undef CVT

    // epilogue
    #pragma unroll
    for (int mt = 0; mt < 4; mt++) {
        int row0 = by*128 + wm*64 + mt*16 + g;
        int row1 = row0 + 8;
        #pragma unroll
        for (int nt = 0; nt < 8; nt++) {
            int col = bx*128 + wn*64 + nt*8 + 2*t4;
            float2 v0o, v1o;
            v0o.x = c[mt][nt][0]; v0o.y = c[mt][nt][1];
            v1o.x = c[mt][nt][2]; v1o.y = c[mt][nt][3];
            if (bias) {
                float bx0 = bias[col], bx1 = bias[col+1];
                v0o.x += bx0; v0o.y += bx1; v1o.x += bx0; v1o.y += bx1;
            }
            if (ACT == 1) {   // gelu + round (output feeds next tf32 GEMM)
                v0o.x = f2tf_f(gelu_exact(v0o.x)); v0o.y = f2tf_f(gelu_exact(v0o.y));
                v1o.x = f2tf_f(gelu_exact(v1o.x)); v1o.y = f2tf_f(gelu_exact(v1o.y));
            }
            if (row0 < M) *(float2*)&C[(size_t)row0*N + col] = v0o;
            if (row1 < M) *(float2*)&C[(size_t)row1*N + col] = v1o;
        }
    }
}

// ---------------- embedding ----------------
__global__ void embed_kernel(const float* __restrict__ x_enc,
                             const float* __restrict__ xme,
                             const float* __restrict__ xmd,
                             const float* __restrict__ tw,
                             const float* __restrict__ tb,
                             const float* __restrict__ tempw,
                             const float* __restrict__ tempb) {
    int t = blockIdx.x, b = blockIdx.y;
    __shared__ float xv[3][7];
    __shared__ float xm[4];
    int tid = threadIdx.x;   // 128
    if (tid < 21) {
        int k = tid / 7, i = tid % 7;
        int r = t - 1 + k;
        int rr = (r + 1025) % 1025;
        float val = 0.f;
        if (rr < 1024) val = x_enc[((size_t)b*1024 + rr)*7 + i];
        xv[k][i] = val;
    }
    if (tid >= 32 && tid < 36) {
        int m = tid - 32;
        xm[m] = (t < 1024) ? xme[((size_t)b*1024 + t)*4 + m]
                           : xmd[((size_t)b*96)*4 + m];
    }
    __syncthreads();
    for (int d = tid; d < DD; d += 128) {
        float acc = tb[d];
        #pragma unroll
        for (int i = 0; i < 7; i++)
            #pragma unroll
            for (int k = 0; k < 3; k++)
                acc += xv[k][i] * tw[(d*7 + i)*3 + k];
        acc += tempb[d];
        #pragma unroll
        for (int m = 0; m < 4; m++) acc += xm[m] * tempw[m*DD + d];
        int m2 = d & ~1;
        float div = expf(-9.210340371976184f / 512.0f * (float)m2);
        float arg = (float)t * div;
        acc += (d & 1) ? cosf(arg) : sinf(arg);
        g_emb[((size_t)b*LL + t)*DD + d] = acc;
    }
}

// ---------------- conv (stride-4, kernel-4, ELU) ----------------
__global__ void conv_kernel(const float* __restrict__ in, int ibs, int inOff,
                            const float* __restrict__ w, const float* __restrict__ bias,
                            float* __restrict__ out, int outOff) {
    int t = blockIdx.x, b = blockIdx.y;
    int tid = threadIdx.x;   // 128 (= oc)
    __shared__ float si[512];
    const float* ip = in + (size_t)(b*ibs + inOff + 4*t) * 128;
    #pragma unroll
    for (int k = 0; k < 4; k++) si[k*128 + tid] = ip[k*128 + tid];
    __syncthreads();
    float acc = bias[tid];
    #pragma unroll 4
    for (int ic = 0; ic < 128; ic++) {
        float4 w4 = *(const float4*)&w[((size_t)tid*128 + ic)*4];
        acc += si[ic]*w4.x + si[128+ic]*w4.y + si[256+ic]*w4.z + si[384+ic]*w4.w;
    }
    acc = (acc > 0.f) ? acc : expm1f(acc);
    out[(size_t)(b*336 + outOff + t)*128 + tid] = acc;
}

// ---------------- layernorm (512 wide, 256 threads) + rounded copy ----------------
__device__ __forceinline__ void ln_core(const float* __restrict__ x0,
                                        const float* __restrict__ x1,
                                        const float* __restrict__ sc,
                                        const float* __restrict__ bb,
                                        float* __restrict__ out,
                                        float* __restrict__ out_r) {
    __shared__ float red[8];
    int tid = threadIdx.x;
    float v0 = x0[tid]       + (x1 ? x1[tid]       : 0.f);
    float v1 = x0[tid + 256] + (x1 ? x1[tid + 256] : 0.f);
    float sum = v0 + v1;
    #pragma unroll
    for (int o = 16; o; o >>= 1) sum += __shfl_xor_sync(0xffffffffu, sum, o);
    if ((tid & 31) == 0) red[tid >> 5] = sum;
    __syncthreads();
    float tot = 0.f;
    #pragma unroll
    for (int w = 0; w < 8; w++) tot += red[w];
    float mean = tot * (1.0f/512.0f);
    __syncthreads();
    float d0 = v0 - mean, d1 = v1 - mean;
    float sq = d0*d0 + d1*d1;
    #pragma unroll
    for (int o = 16; o; o >>= 1) sq += __shfl_xor_sync(0xffffffffu, sq, o);
    if ((tid & 31) == 0) red[tid >> 5] = sq;
    __syncthreads();
    float vtot = 0.f;
    #pragma unroll
    for (int w = 0; w < 8; w++) vtot += red[w];
    float inv = rsqrtf(vtot * (1.0f/512.0f) + 1e-5f);
    float o0 = d0 * inv * sc[tid]       + bb[tid];
    float o1 = d1 * inv * sc[tid + 256] + bb[tid + 256];
    out[tid]       = o0;
    out[tid + 256] = o1;
    out_r[tid]       = f2tf_f(o0);
    out_r[tid + 256] = f2tf_f(o1);
}

__global__ void concat_ln_kernel(const float* __restrict__ sc, const float* __restrict__ bb) {
    int row = blockIdx.x;
    int b = row / NT, n = row % NT;
    const float* src = (n < LL) ? &g_emb[((size_t)b*LL + n)*DD]
                                : &g_pyr[((size_t)b*336 + (n - LL))*DD];
    ln_core(src, nullptr, sc, bb, &g_seq[(size_t)row*DD], &g_seqr[(size_t)row*DD]);
}

__global__ void add_ln_kernel(const float* __restrict__ sc, const float* __restrict__ bb) {
    size_t row = blockIdx.x;
    ln_core(&g_seq[row*DD], &g_tmp[row*DD], sc, bb, &g_seq[row*DD], &g_seqr[row*DD]);
}

// ---------------- fused sparse attention (reads packed qkv, rounds output) ---------
#define MAXN 12
__global__ __launch_bounds__(256)
void attn_kernel() {
    int i = blockIdx.x, b = blockIdx.y;
    __shared__ int s_nbr[MAXN];
    __shared__ int s_nn;
    int tid = threadIdx.x;
    if (tid == 0) {
        const int starts[5] = {0, 1025, 1281, 1345, 1361};
        int li = (i < 1025) ? 0 : (i < 1281) ? 1 : (i < 1345) ? 2 : 3;
        int s = starts[li], e = starts[li+1];
        int nn = 0;
        int jlo = (i - 2 > s) ? i - 2 : s;
        int jhi = (i + 2 < e - 1) ? i + 2 : e - 1;
        for (int j = jlo; j <= jhi; j++) s_nbr[nn++] = j;
        if (li > 0) {
            int ps = starts[li-1];
            int qq = i - s;
            int lo = ps + qq * 4;
            int hi = (i == e - 1) ? s : ps + (qq + 1) * 4;
            for (int j = lo; j < hi; j++) s_nbr[nn++] = j;
        }
        if (li < 3) {
            int su = starts[li+1];
            int szu = starts[li+2] - su;
            int qq = (i - s) / 4;
            s_nbr[nn++] = su + ((qq < szu - 1) ? qq : szu - 1);
        }
        s_nn = nn;
        for (int j = nn; j < MAXN; j++) s_nbr[j] = i;
    }
    __syncthreads();
    int nn = s_nn;
    int h = tid >> 5, lane = tid & 31;
    size_t qbase = ((size_t)b*NT + i)*1536 + h*64;
    float q0 = g_qkv[qbase + lane];
    float q1 = g_qkv[qbase + lane + 32];

    float dots[MAXN];
    #pragma unroll
    for (int jj = 0; jj < MAXN; jj++) {
        size_t kb = ((size_t)b*NT + s_nbr[jj])*1536 + 512 + h*64;
        float p = q0 * g_qkv[kb + lane] + q1 * g_qkv[kb + lane + 32];
        #pragma unroll
        for (int o = 16; o; o >>= 1) p += __shfl_xor_sync(0xffffffffu, p, o);
        dots[jj] = (jj < nn) ? p * 0.125f : -1e30f;
    }
    float mx = -1e30f;
    #pragma unroll
    for (int jj = 0; jj < MAXN; jj++) mx = fmaxf(mx, dots[jj]);
    float sum = 0.f;
    #pragma unroll
    for (int jj = 0; jj < MAXN; jj++) { dots[jj] = expf(dots[jj] - mx); sum += dots[jj]; }
    float inv = 1.f / sum;
    float o0 = 0.f, o1 = 0.f;
    #pragma unroll
    for (int jj = 0; jj < MAXN; jj++) {
        size_t vb = ((size_t)b*NT + s_nbr[jj])*1536 + 1024 + h*64;
        float w = dots[jj] * inv;
        o0 += w * g_qkv[vb + lane];
        o1 += w * g_qkv[vb + lane + 32];
    }
    size_t obase = ((size_t)b*NT + i)*DD + h*64;
    g_o[obase + lane]      = f2tf_f(o0);   // feeds Wo GEMM only
    g_o[obase + lane + 32] = f2tf_f(o1);
}

// ---------------- gather + prediction head ----------------
__global__ void pred_kernel(const float* __restrict__ pw, float* __restrict__ out) {
    int b = blockIdx.x;
    __shared__ float gv[2048];
    const int rows[4] = {1024, 1280, 1344, 1360};
    int tid = threadIdx.x;   // 672
    for (int r = tid; r < 2048; r += 672) {
        int wch = r >> 9, d = r & 511;
        gv[r] = g_seq[((size_t)b*NT + rows[wch])*DD + d];
    }
    __syncthreads();
    float acc = 0.f;
    for (int r = 0; r < 2048; r++) acc += gv[r] * pw[(size_t)r*672 + tid];
    out[(size_t)b*672 + tid] = acc;
}

// ---------------- host ----------------
static void launch_gemm_rnd(const float* A, const float* Bm, const float* bias,
                            float* C, int M, int N, int K, int act) {
    dim3 grid(N / 128, (M + 127) / 128);
    if (act == 1) tgemm_kernel<1,1><<<grid, 128>>>(A, Bm, bias, C, M, N, K);
    else          tgemm_kernel<0,1><<<grid, 128>>>(A, Bm, bias, C, M, N, K);
}
static void launch_gemm_pre(const float* A, const float* Bm, const float* bias,
                            float* C, int M, int N, int K, int act) {
    dim3 grid(N / 128, (M + 127) / 128);
    if (act == 1) tgemm_kernel<1,0><<<grid, 128>>>(A, Bm, bias, C, M, N, K);
    else          tgemm_kernel<0,0><<<grid, 128>>>(A, Bm, bias, C, M, N, K);
}

extern "C" void kernel_launch(void* const* d_in, const int* in_sizes, int n_in,
                              void* d_out, int out_size) {
    const float* x_enc   = (const float*)d_in[0];
    const float* xme     = (const float*)d_in[1];
    // d_in[2] = x_dec (unused by the model math)
    const float* xmd     = (const float*)d_in[3];
    const float* token_w = (const float*)d_in[4];
    const float* token_b = (const float*)d_in[5];
    const float* temp_w  = (const float*)d_in[6];
    const float* temp_b  = (const float*)d_in[7];
    const float* down_w  = (const float*)d_in[8];
    const float* down_b  = (const float*)d_in[9];
    const float* conv_w  = (const float*)d_in[10];
    const float* conv_b  = (const float*)d_in[11];
    const float* up_w    = (const float*)d_in[12];
    const float* up_b    = (const float*)d_in[13];
    const float* cln_s   = (const float*)d_in[14];
    const float* cln_b   = (const float*)d_in[15];
    const float* Wq      = (const float*)d_in[16];
    const float* Wk      = (const float*)d_in[17];
    const float* Wv      = (const float*)d_in[18];
    const float* Wo      = (const float*)d_in[19];
    const float* bo      = (const float*)d_in[20];
    const float* ln1_s   = (const float*)d_in[21];
    const float* ln1_b   = (const float*)d_in[22];
    const float* W1      = (const float*)d_in[23];
    const float* b1      = (const float*)d_in[24];
    const float* W2      = (const float*)d_in[25];
    const float* b2      = (const float*)d_in[26];
    const float* ln2_s   = (const float*)d_in[27];
    const float* ln2_b   = (const float*)d_in[28];
    const float* pred_w  = (const float*)d_in[29];

    float *emb, *d0, *cc, *pyr, *seq, *seqr, *qkv, *o, *tmp, *ffn;
    float *wqkv, *wo, *w1, *w2;
    cudaGetSymbolAddress((void**)&emb,  g_emb);
    cudaGetSymbolAddress((void**)&d0,   g_d0);
    cudaGetSymbolAddress((void**)&cc,   g_cc);
    cudaGetSymbolAddress((void**)&pyr,  g_pyr);
    cudaGetSymbolAddress((void**)&seq,  g_seq);
    cudaGetSymbolAddress((void**)&seqr, g_seqr);
    cudaGetSymbolAddress((void**)&qkv,  g_qkv);
    cudaGetSymbolAddress((void**)&o,    g_o);
    cudaGetSymbolAddress((void**)&tmp,  g_tmp);
    cudaGetSymbolAddress((void**)&ffn,  g_ffn);
    cudaGetSymbolAddress((void**)&wqkv, g_wqkv);
    cudaGetSymbolAddress((void**)&wo,   g_wo);
    cudaGetSymbolAddress((void**)&w1,   g_w1);
    cudaGetSymbolAddress((void**)&w2,   g_w2);

    // 0) round+pack all encoder weights (tf32 pre-rounding)
    pack_qkv<<<(4*512*128 + 255)/256, 256>>>(Wq, Wk, Wv);
    round_copy<<<(4*512*512/4 + 255)/256, 256>>>(Wo, wo, 4*512*512/4);
    round_copy<<<(4*512*2048/4 + 255)/256, 256>>>(W1, w1, 4*512*2048/4);
    round_copy<<<(4*2048*512/4 + 255)/256, 256>>>(W2, w2, 4*2048*512/4);

    // 1) embedding (token conv + PE + temporal)
    embed_kernel<<<dim3(LL, BB), 128>>>(x_enc, xme, xmd, token_w, token_b, temp_w, temp_b);

    // 2) bottleneck down-projection (loader-rounded path)
    launch_gemm_rnd(emb, down_w, down_b, d0, BB*LL, 128, DD, 0);

    // 3) pyramid convs (stride4/k4 + ELU)
    conv_kernel<<<dim3(256, BB), 128>>>(d0, LL, 0,   conv_w,               conv_b,       cc, 0);
    conv_kernel<<<dim3(64,  BB), 128>>>(cc, 336, 0,  conv_w + 128*128*4,   conv_b + 128, cc, 256);
    conv_kernel<<<dim3(16,  BB), 128>>>(cc, 336, 256,conv_w + 2*128*128*4, conv_b + 256, cc, 320);

    // 4) up-projection (loader-rounded path)
    launch_gemm_rnd(cc, up_w, up_b, pyr, BB*336, DD, 128, 0);

    // 5) concat + LayerNorm -> seq (+ rounded copy)
    concat_ln_kernel<<<MROWS, 256>>>(cln_s, cln_b);

    // 6) encoder layers (pre-rounded operands, CVT-free GEMM loader)
    for (int i = 0; i < 4; i++) {
        launch_gemm_pre(seqr, wqkv + (size_t)i*512*1536, nullptr, qkv, MROWS, 1536, 512, 0);

        attn_kernel<<<dim3(NT, BB), 256>>>();

        launch_gemm_pre(o, wo + (size_t)i*DD*DD, bo + i*DD, tmp, MROWS, DD, DD, 0);
        add_ln_kernel<<<MROWS, 256>>>(ln1_s + i*DD, ln1_b + i*DD);

        launch_gemm_pre(seqr, w1 + (size_t)i*DD*DFF, b1 + i*DFF, ffn, MROWS, DFF, DD, 1);
        launch_gemm_pre(ffn, w2 + (size_t)i*DFF*DD, b2 + i*DD, tmp, MROWS, DD, DFF, 0);
        add_ln_kernel<<<MROWS, 256>>>(ln2_s + i*DD, ln2_b + i*DD);
    }

    // 7) gather pyramid nodes of the last step + prediction head
    pred_kernel<<<BB, 672>>>(pred_w, (float*)d_out);
}

// round 11
// speedup vs baseline: 1.8703x; 1.8703x over previous
#include <cuda_runtime.h>
#include <cuda_fp16.h>
#include <math.h>
#include <stdint.h>

#define BB 4
#define LL 1025
#define NT 1361
#define DD 512
#define HH 8
#define DFF 2048
#define MROWS (BB*NT)         // 5444

// ---------------- scratch (static device allocations) ----------------
__device__ float g_emb [BB*LL*DD];
__device__ float g_d0  [BB*LL*128];
__device__ float g_cc  [BB*336*128];
__device__ float g_pyr [BB*336*DD];
__device__ float g_seq [BB*NT*DD];
__device__ float g_qkv [BB*NT*1536];
__device__ float g_tmp [BB*NT*DD];
// fp16 activations (uint4 arrays => 16B alignment guaranteed)
__device__ uint4 g_seqr_h[MROWS*DD/8];     // half copy of seq (GEMM A)
__device__ uint4 g_o_h   [MROWS*DD/8];     // attention output (half)
__device__ uint4 g_ffn_h [MROWS*DFF/8];    // W1+gelu output (half)
// fp16 weight packs: uint32 pairs, layout [K/2][N] per layer
__device__ uint4 g_wqkvh[4*256*1536/4];
__device__ uint4 g_woh  [4*256*512/4];
__device__ uint4 g_w1h  [4*256*2048/4];
__device__ uint4 g_w2h  [4*1024*512/4];

// ---------------- helpers ----------------
__device__ __forceinline__ uint32_t f2tf(float x) {
    uint32_t r;
    asm("cvt.rna.tf32.f32 %0, %1;" : "=r"(r) : "f"(x));
    return r;
}
__device__ __forceinline__ float gelu_exact(float x) {
    return 0.5f * x * (1.0f + erff(x * 0.70710678118654752f));
}
__device__ __forceinline__ uint32_t packh2(float a, float b) {
    __half2 h = __halves2half2(__float2half_rn(a), __float2half_rn(b));
    return *(uint32_t*)&h;
}
__device__ __forceinline__ void mma_tf32(float c[4], const uint32_t a[4], const uint32_t b[2]) {
    asm volatile(
        "mma.sync.aligned.m16n8k8.row.col.f32.tf32.tf32.f32 "
        "{%0,%1,%2,%3}, {%4,%5,%6,%7}, {%8,%9}, {%0,%1,%2,%3};\n"
        : "+f"(c[0]), "+f"(c[1]), "+f"(c[2]), "+f"(c[3])
        : "r"(a[0]), "r"(a[1]), "r"(a[2]), "r"(a[3]), "r"(b[0]), "r"(b[1]));
}
__device__ __forceinline__ void mma_f16(float c[4], const uint32_t a[4], const uint32_t b[2]) {
    asm volatile(
        "mma.sync.aligned.m16n8k16.row.col.f32.f16.f16.f32 "
        "{%0,%1,%2,%3}, {%4,%5,%6,%7}, {%8,%9}, {%0,%1,%2,%3};\n"
        : "+f"(c[0]), "+f"(c[1]), "+f"(c[2]), "+f"(c[3])
        : "r"(a[0]), "r"(a[1]), "r"(a[2]), "r"(a[3]), "r"(b[0]), "r"(b[1]));
}

// ---------------- fp16 weight packing: [K][N] fp32 -> [K/2][N] half2-pair -------
__global__ void packh(const float* __restrict__ in, uint32_t* __restrict__ out,
                      int K, int N, int total) {
    int idx = blockIdx.x*blockDim.x + threadIdx.x;
    if (idx >= total) return;
    int K2 = K >> 1;
    int n  = idx % N;
    int k2 = (idx / N) % K2;
    int l  = idx / (N * K2);
    const float* src = in + ((size_t)l*K + 2*k2)*N + n;
    out[idx] = packh2(src[0], src[N]);
}
__global__ void pack_qkvh(const float* __restrict__ Wq,
                          const float* __restrict__ Wk,
                          const float* __restrict__ Wv,
                          uint32_t* __restrict__ out) {
    int idx = blockIdx.x*blockDim.x + threadIdx.x;   // 4*256*1536
    if (idx >= 4*256*1536) return;
    int n  = idx % 1536;
    int t  = idx / 1536;        // l*256 + k2
    int k2 = t & 255;
    int l  = t >> 8;            // FIX: per-layer extent is 256*1536, not 2^19
    const float* src = (n < 512) ? Wq : (n < 1024) ? Wk : Wv;
    int nn = n & 511;
    size_t base = ((size_t)l*512 + 2*k2)*512 + nn;
    out[idx] = packh2(src[base], src[base + 512]);
}

// ---------------- FP16 mma.sync GEMM: C = A(MxK)@B(KxN) [+bias][+gelu] ----------
// BM=BN=128, BK=32 halfs (16 half2 rows); 256 thr = 8 warps (4M x 2N), warp 32x64.
// Smem: [k2][m]/[k2][n] uint32 (half2 pairs), stride 136 -> conflict-free frags.
template<int ACT, int OUTH>
__global__ __launch_bounds__(256)
void hgemm_kernel(const uint32_t* __restrict__ A32, const uint32_t* __restrict__ Bw,
                  const float* __restrict__ bias, void* __restrict__ Cv,
                  int M, int N, int K) {
    __shared__ uint32_t As[2][16][136];
    __shared__ uint32_t Bs[2][16][136];
    int tid = threadIdx.x;
    int bx = blockIdx.x, by = blockIdx.y;
    int w = tid >> 5, lane = tid & 31;
    int wm = w & 3, wn = w >> 2;
    int g = lane >> 2, t4 = lane & 3;
    int K2 = K >> 1;

    float c[2][8][4];
    #pragma unroll
    for (int mt = 0; mt < 2; mt++)
        #pragma unroll
        for (int nt = 0; nt < 8; nt++)
            #pragma unroll
            for (int r = 0; r < 4; r++) c[mt][nt][r] = 0.f;

    // A loader: rows am, am+64; uint4 = 4 half2-pairs (8 k) at k2 offset aq
    int am = tid >> 2;            // 0..63
    int aq = (tid & 3) * 4;       // 0,4,8,12
    int arow0 = by*128 + am, arow1 = arow0 + 64;
    const uint32_t* Ap0 = A32 + (size_t)arow0 * K2 + aq;
    const uint32_t* Ap1 = A32 + (size_t)arow1 * K2 + aq;
    bool v0 = (arow0 < M), v1 = (arow1 < M);

    // B loader: k2-row br, two uint4 col-chunks at bu, bu+64
    int br = tid >> 4;            // 0..15
    int bu = (tid & 15) * 4;      // 0..60
    const uint32_t* Bp = Bw + (size_t)br * N + bx*128 + bu;

    int nk = K2 >> 4;
    uint4 a0, a1, b0, b1;
    const uint4 z4 = make_uint4(0,0,0,0);

    // prologue: tile 0
    a0 = v0 ? *(const uint4*)(Ap0) : z4;
    a1 = v1 ? *(const uint4*)(Ap1) : z4;
    b0 = *(const uint4*)(Bp);
    b1 = *(const uint4*)(Bp + 64);
    As[0][aq+0][am] = a0.x; As[0][aq+1][am] = a0.y; As[0][aq+2][am] = a0.z; As[0][aq+3][am] = a0.w;
    As[0][aq+0][am+64] = a1.x; As[0][aq+1][am+64] = a1.y; As[0][aq+2][am+64] = a1.z; As[0][aq+3][am+64] = a1.w;
    *(uint4*)&Bs[0][br][bu] = b0;
    *(uint4*)&Bs[0][br][bu+64] = b1;
    __syncthreads();

    int mb = wm*32 + g;
    int nb = wn*64 + g;
    int buf = 0;
    for (int tile = 1; tile < nk; tile++) {
        a0 = v0 ? *(const uint4*)(Ap0 + tile*16) : z4;
        a1 = v1 ? *(const uint4*)(Ap1 + tile*16) : z4;
        b0 = *(const uint4*)(Bp + (size_t)(tile*16)*N);
        b1 = *(const uint4*)(Bp + (size_t)(tile*16)*N + 64);

        #pragma unroll
        for (int ks = 0; ks < 16; ks += 8) {
            uint32_t af[2][4], bf[8][2];
            #pragma unroll
            for (int mt = 0; mt < 2; mt++) {
                af[mt][0] = As[buf][ks+t4  ][mb + mt*16];
                af[mt][1] = As[buf][ks+t4  ][mb + mt*16 + 8];
                af[mt][2] = As[buf][ks+t4+4][mb + mt*16];
                af[mt][3] = As[buf][ks+t4+4][mb + mt*16 + 8];
            }
            #pragma unroll
            for (int nt = 0; nt < 8; nt++) {
                bf[nt][0] = Bs[buf][ks+t4  ][nb + nt*8];
                bf[nt][1] = Bs[buf][ks+t4+4][nb + nt*8];
            }
            #pragma unroll
            for (int mt = 0; mt < 2; mt++)
                #pragma unroll
                for (int nt = 0; nt < 8; nt++)
                    mma_f16(c[mt][nt], af[mt], bf[nt]);
        }

        int nbuf = buf ^ 1;
        As[nbuf][aq+0][am] = a0.x; As[nbuf][aq+1][am] = a0.y; As[nbuf][aq+2][am] = a0.z; As[nbuf][aq+3][am] = a0.w;
        As[nbuf][aq+0][am+64] = a1.x; As[nbuf][aq+1][am+64] = a1.y; As[nbuf][aq+2][am+64] = a1.z; As[nbuf][aq+3][am+64] = a1.w;
        *(uint4*)&Bs[nbuf][br][bu] = b0;
        *(uint4*)&Bs[nbuf][br][bu+64] = b1;
        __syncthreads();
        buf = nbuf;
    }

    // last tile
    #pragma unroll
    for (int ks = 0; ks < 16; ks += 8) {
        uint32_t af[2][4], bf[8][2];
        #pragma unroll
        for (int mt = 0; mt < 2; mt++) {
            af[mt][0] = As[buf][ks+t4  ][mb + mt*16];
            af[mt][1] = As[buf][ks+t4  ][mb + mt*16 + 8];
            af[mt][2] = As[buf][ks+t4+4][mb + mt*16];
            af[mt][3] = As[buf][ks+t4+4][mb + mt*16 + 8];
        }
        #pragma unroll
        for (int nt = 0; nt < 8; nt++) {
            bf[nt][0] = Bs[buf][ks+t4  ][nb + nt*8];
            bf[nt][1] = Bs[buf][ks+t4+4][nb + nt*8];
        }
        #pragma unroll
        for (int mt = 0; mt < 2; mt++)
            #pragma unroll
            for (int nt = 0; nt < 8; nt++)
                mma_f16(c[mt][nt], af[mt], bf[nt]);
    }

    // epilogue
    #pragma unroll
    for (int mt = 0; mt < 2; mt++) {
        int row0 = by*128 + wm*32 + mt*16 + g;
        int row1 = row0 + 8;
        #pragma unroll
        for (int nt = 0; nt < 8; nt++) {
            int col = bx*128 + wn*64 + nt*8 + 2*t4;
            float x0 = c[mt][nt][0], x1 = c[mt][nt][1];
            float y0 = c[mt][nt][2], y1 = c[mt][nt][3];
            if (bias) {
                float bx0 = bias[col], bx1 = bias[col+1];
                x0 += bx0; x1 += bx1; y0 += bx0; y1 += bx1;
            }
            if (ACT == 1) {
                x0 = gelu_exact(x0); x1 = gelu_exact(x1);
                y0 = gelu_exact(y0); y1 = gelu_exact(y1);
            }
            if (OUTH) {
                uint32_t* Ch = (uint32_t*)Cv;
                if (row0 < M) Ch[((size_t)row0*N + col) >> 1] = packh2(x0, x1);
                if (row1 < M) Ch[((size_t)row1*N + col) >> 1] = packh2(y0, y1);
            } else {
                float* Cf = (float*)Cv;
                if (row0 < M) { float2 v; v.x = x0; v.y = x1; *(float2*)&Cf[(size_t)row0*N + col] = v; }
                if (row1 < M) { float2 v; v.x = y0; v.y = y1; *(float2*)&Cf[(size_t)row1*N + col] = v; }
            }
        }
    }
}

// ---------------- TF32 mma.sync GEMM (round-7 proven; down/up projections) -------
template<int ACT>
__global__ __launch_bounds__(256)
void tgemm_kernel(const float* __restrict__ A, const float* __restrict__ Bm,
                  const float* __restrict__ bias, float* __restrict__ C,
                  int M, int N, int K) {
    __shared__ uint32_t As[2][16][136];
    __shared__ uint32_t Bs[2][16][136];
    int tid = threadIdx.x;
    int bx = blockIdx.x, by = blockIdx.y;
    int w = tid >> 5, lane = tid & 31;
    int wm = w & 3, wn = w >> 2;
    int g = lane >> 2, t4 = lane & 3;

    float c[2][8][4];
    #pragma unroll
    for (int mt = 0; mt < 2; mt++)
        #pragma unroll
        for (int nt = 0; nt < 8; nt++)
            #pragma unroll
            for (int r = 0; r < 4; r++) c[mt][nt][r] = 0.f;

    int am = tid >> 2;
    int ak = (tid & 3) * 4;
    int arow0 = by*128 + am;
    int arow1 = arow0 + 64;
    const float* Ap0 = A + (size_t)arow0 * K + ak;
    const float* Ap1 = A + (size_t)arow1 * K + ak;
    bool v0 = (arow0 < M), v1 = (arow1 < M);

    int bk = tid >> 5;
    int bn = (tid & 31) * 4;
    const float* Bp = Bm + (size_t)bk * N + bx*128 + bn;

    int nk = K >> 4;
    float4 a0, a1, b0, b1;

    a0 = v0 ? *(const float4*)(Ap0) : make_float4(0,0,0,0);
    a1 = v1 ? *(const float4*)(Ap1) : make_float4(0,0,0,0);
    b0 = *(const float4*)(Bp);
    b1 = *(const float4*)(Bp + (size_t)8*N);
    As[0][ak+0][am] = f2tf(a0.x); As[0][ak+1][am] = f2tf(a0.y);
    As[0][ak+2][am] = f2tf(a0.z); As[0][ak+3][am] = f2tf(a0.w);
    As[0][ak+0][am+64] = f2tf(a1.x); As[0][ak+1][am+64] = f2tf(a1.y);
    As[0][ak+2][am+64] = f2tf(a1.z); As[0][ak+3][am+64] = f2tf(a1.w);
    Bs[0][bk][bn+0] = f2tf(b0.x); Bs[0][bk][bn+1] = f2tf(b0.y);
    Bs[0][bk][bn+2] = f2tf(b0.z); Bs[0][bk][bn+3] = f2tf(b0.w);
    Bs[0][bk+8][bn+0] = f2tf(b1.x); Bs[0][bk+8][bn+1] = f2tf(b1.y);
    Bs[0][bk+8][bn+2] = f2tf(b1.z); Bs[0][bk+8][bn+3] = f2tf(b1.w);
    __syncthreads();

    int mb = wm*32 + g;
    int nb = wn*64 + g;
    int buf = 0;
    for (int tile = 1; tile < nk; tile++) {
        const float* ap0 = Ap0 + tile*16;
        const float* ap1 = Ap1 + tile*16;
        const float* bp  = Bp + (size_t)(tile*16) * N;
        a0 = v0 ? *(const float4*)(ap0) : make_float4(0,0,0,0);
        a1 = v1 ? *(const float4*)(ap1) : make_float4(0,0,0,0);
        b0 = *(const float4*)(bp);
        b1 = *(const float4*)(bp + (size_t)8*N);

        #pragma unroll
        for (int ks = 0; ks < 16; ks += 8) {
            uint32_t af[2][4], bf[8][2];
            #pragma unroll
            for (int mt = 0; mt < 2; mt++) {
                af[mt][0] = As[buf][ks+t4  ][mb + mt*16];
                af[mt][1] = As[buf][ks+t4  ][mb + mt*16 + 8];
                af[mt][2] = As[buf][ks+t4+4][mb + mt*16];
                af[mt][3] = As[buf][ks+t4+4][mb + mt*16 + 8];
            }
            #pragma unroll
            for (int nt = 0; nt < 8; nt++) {
                bf[nt][0] = Bs[buf][ks+t4  ][nb + nt*8];
                bf[nt][1] = Bs[buf][ks+t4+4][nb + nt*8];
            }
            #pragma unroll
            for (int mt = 0; mt < 2; mt++)
                #pragma unroll
                for (int nt = 0; nt < 8; nt++)
                    mma_tf32(c[mt][nt], af[mt], bf[nt]);
        }

        int nbuf = buf ^ 1;
        As[nbuf][ak+0][am] = f2tf(a0.x); As[nbuf][ak+1][am] = f2tf(a0.y);
        As[nbuf][ak+2][am] = f2tf(a0.z); As[nbuf][ak+3][am] = f2tf(a0.w);
        As[nbuf][ak+0][am+64] = f2tf(a1.x); As[nbuf][ak+1][am+64] = f2tf(a1.y);
        As[nbuf][ak+2][am+64] = f2tf(a1.z); As[nbuf][ak+3][am+64] = f2tf(a1.w);
        Bs[nbuf][bk][bn+0] = f2tf(b0.x); Bs[nbuf][bk][bn+1] = f2tf(b0.y);
        Bs[nbuf][bk][bn+2] = f2tf(b0.z); Bs[nbuf][bk][bn+3] = f2tf(b0.w);
        Bs[nbuf][bk+8][bn+0] = f2tf(b1.x); Bs[nbuf][bk+8][bn+1] = f2tf(b1.y);
        Bs[nbuf][bk+8][bn+2] = f2tf(b1.z); Bs[nbuf][bk+8][bn+3] = f2tf(b1.w);
        __syncthreads();
        buf = nbuf;
    }

    #pragma unroll
    for (int ks = 0; ks < 16; ks += 8) {
        uint32_t af[2][4], bf[8][2];
        #pragma unroll
        for (int mt = 0; mt < 2; mt++) {
            af[mt][0] = As[buf][ks+t4  ][mb + mt*16];
            af[mt][1] = As[buf][ks+t4  ][mb + mt*16 + 8];
            af[mt][2] = As[buf][ks+t4+4][mb + mt*16];
            af[mt][3] = As[buf][ks+t4+4][mb + mt*16 + 8];
        }
        #pragma unroll
        for (int nt = 0; nt < 8; nt++) {
            bf[nt][0] = Bs[buf][ks+t4  ][nb + nt*8];
            bf[nt][1] = Bs[buf][ks+t4+4][nb + nt*8];
        }
        #pragma unroll
        for (int mt = 0; mt < 2; mt++)
            #pragma unroll
            for (int nt = 0; nt < 8; nt++)
                mma_tf32(c[mt][nt], af[mt], bf[nt]);
    }

    #pragma unroll
    for (int mt = 0; mt < 2; mt++) {
        int row0 = by*128 + wm*32 + mt*16 + g;
        int row1 = row0 + 8;
        #pragma unroll
        for (int nt = 0; nt < 8; nt++) {
            int col = bx*128 + wn*64 + nt*8 + 2*t4;
            float2 v0o, v1o;
            v0o.x = c[mt][nt][0]; v0o.y = c[mt][nt][1];
            v1o.x = c[mt][nt][2]; v1o.y = c[mt][nt][3];
            if (bias) {
                float bx0 = bias[col], bx1 = bias[col+1];
                v0o.x += bx0; v0o.y += bx1; v1o.x += bx0; v1o.y += bx1;
            }
            if (ACT == 1) {
                v0o.x = gelu_exact(v0o.x); v0o.y = gelu_exact(v0o.y);
                v1o.x = gelu_exact(v1o.x); v1o.y = gelu_exact(v1o.y);
            }
            if (row0 < M) *(float2*)&C[(size_t)row0*N + col] = v0o;
            if (row1 < M) *(float2*)&C[(size_t)row1*N + col] = v1o;
        }
    }
}

// ---------------- embedding ----------------
__global__ void embed_kernel(const float* __restrict__ x_enc,
                             const float* __restrict__ xme,
                             const float* __restrict__ xmd,
                             const float* __restrict__ tw,
                             const float* __restrict__ tb,
                             const float* __restrict__ tempw,
                             const float* __restrict__ tempb) {
    int t = blockIdx.x, b = blockIdx.y;
    __shared__ float xv[3][7];
    __shared__ float xm[4];
    int tid = threadIdx.x;   // 128
    if (tid < 21) {
        int k = tid / 7, i = tid % 7;
        int r = t - 1 + k;
        int rr = (r + 1025) % 1025;
        float val = 0.f;
        if (rr < 1024) val = x_enc[((size_t)b*1024 + rr)*7 + i];
        xv[k][i] = val;
    }
    if (tid >= 32 && tid < 36) {
        int m = tid - 32;
        xm[m] = (t < 1024) ? xme[((size_t)b*1024 + t)*4 + m]
                           : xmd[((size_t)b*96)*4 + m];
    }
    __syncthreads();
    for (int d = tid; d < DD; d += 128) {
        float acc = tb[d];
        #pragma unroll
        for (int i = 0; i < 7; i++)
            #pragma unroll
            for (int k = 0; k < 3; k++)
                acc += xv[k][i] * tw[(d*7 + i)*3 + k];
        acc += tempb[d];
        #pragma unroll
        for (int m = 0; m < 4; m++) acc += xm[m] * tempw[m*DD + d];
        int m2 = d & ~1;
        float div = expf(-9.210340371976184f / 512.0f * (float)m2);
        float arg = (float)t * div;
        acc += (d & 1) ? cosf(arg) : sinf(arg);
        g_emb[((size_t)b*LL + t)*DD + d] = acc;
    }
}

// ---------------- conv (stride-4, kernel-4, ELU) ----------------
__global__ void conv_kernel(const float* __restrict__ in, int ibs, int inOff,
                            const float* __restrict__ w, const float* __restrict__ bias,
                            float* __restrict__ out, int outOff) {
    int t = blockIdx.x, b = blockIdx.y;
    int tid = threadIdx.x;   // 128 (= oc)
    __shared__ float si[512];
    const float* ip = in + (size_t)(b*ibs + inOff + 4*t) * 128;
    #pragma unroll
    for (int k = 0; k < 4; k++) si[k*128 + tid] = ip[k*128 + tid];
    __syncthreads();
    float acc = bias[tid];
    #pragma unroll 4
    for (int ic = 0; ic < 128; ic++) {
        float4 w4 = *(const float4*)&w[((size_t)tid*128 + ic)*4];
        acc += si[ic]*w4.x + si[128+ic]*w4.y + si[256+ic]*w4.z + si[384+ic]*w4.w;
    }
    acc = (acc > 0.f) ? acc : expm1f(acc);
    out[(size_t)(b*336 + outOff + t)*128 + tid] = acc;
}

// ---------------- layernorm (512 wide, 256 threads) + half copy ----------------
__device__ __forceinline__ void ln_core(const float* __restrict__ x0,
                                        const float* __restrict__ x1,
                                        const float* __restrict__ sc,
                                        const float* __restrict__ bb,
                                        float* __restrict__ out,
                                        __half* __restrict__ out_h) {
    __shared__ float red[8];
    int tid = threadIdx.x;
    float v0 = x0[tid]       + (x1 ? x1[tid]       : 0.f);
    float v1 = x0[tid + 256] + (x1 ? x1[tid + 256] : 0.f);
    float sum = v0 + v1;
    #pragma unroll
    for (int o = 16; o; o >>= 1) sum += __shfl_xor_sync(0xffffffffu, sum, o);
    if ((tid & 31) == 0) red[tid >> 5] = sum;
    __syncthreads();
    float tot = 0.f;
    #pragma unroll
    for (int w = 0; w < 8; w++) tot += red[w];
    float mean = tot * (1.0f/512.0f);
    __syncthreads();
    float d0 = v0 - mean, d1 = v1 - mean;
    float sq = d0*d0 + d1*d1;
    #pragma unroll
    for (int o = 16; o; o >>= 1) sq += __shfl_xor_sync(0xffffffffu, sq, o);
    if ((tid & 31) == 0) red[tid >> 5] = sq;
    __syncthreads();
    float vtot = 0.f;
    #pragma unroll
    for (int w = 0; w < 8; w++) vtot += red[w];
    float inv = rsqrtf(vtot * (1.0f/512.0f) + 1e-5f);
    float o0 = d0 * inv * sc[tid]       + bb[tid];
    float o1 = d1 * inv * sc[tid + 256] + bb[tid + 256];
    out[tid]       = o0;
    out[tid + 256] = o1;
    out_h[tid]       = __float2half_rn(o0);
    out_h[tid + 256] = __float2half_rn(o1);
}

__global__ void concat_ln_kernel(const float* __restrict__ sc, const float* __restrict__ bb) {
    int row = blockIdx.x;
    int b = row / NT, n = row % NT;
    const float* src = (n < LL) ? &g_emb[((size_t)b*LL + n)*DD]
                                : &g_pyr[((size_t)b*336 + (n - LL))*DD];
    ln_core(src, nullptr, sc, bb, &g_seq[(size_t)row*DD],
            (__half*)g_seqr_h + (size_t)row*DD);
}

__global__ void add_ln_kernel(const float* __restrict__ sc, const float* __restrict__ bb) {
    size_t row = blockIdx.x;
    ln_core(&g_seq[row*DD], &g_tmp[row*DD], sc, bb, &g_seq[row*DD],
            (__half*)g_seqr_h + row*DD);
}

// ---------------- fused sparse attention (fp32 qkv in, half out) ---------------
#define MAXN 12
__global__ __launch_bounds__(256)
void attn_kernel() {
    int i = blockIdx.x, b = blockIdx.y;
    __shared__ int s_nbr[MAXN];
    __shared__ int s_nn;
    int tid = threadIdx.x;
    if (tid == 0) {
        const int starts[5] = {0, 1025, 1281, 1345, 1361};
        int li = (i < 1025) ? 0 : (i < 1281) ? 1 : (i < 1345) ? 2 : 3;
        int s = starts[li], e = starts[li+1];
        int nn = 0;
        int jlo = (i - 2 > s) ? i - 2 : s;
        int jhi = (i + 2 < e - 1) ? i + 2 : e - 1;
        for (int j = jlo; j <= jhi; j++) s_nbr[nn++] = j;
        if (li > 0) {
            int ps = starts[li-1];
            int qq = i - s;
            int lo = ps + qq * 4;
            int hi = (i == e - 1) ? s : ps + (qq + 1) * 4;
            for (int j = lo; j < hi; j++) s_nbr[nn++] = j;
        }
        if (li < 3) {
            int su = starts[li+1];
            int szu = starts[li+2] - su;
            int qq = (i - s) / 4;
            s_nbr[nn++] = su + ((qq < szu - 1) ? qq : szu - 1);
        }
        s_nn = nn;
        for (int j = nn; j < MAXN; j++) s_nbr[j] = i;
    }
    __syncthreads();
    int nn = s_nn;
    int h = tid >> 5, lane = tid & 31;
    size_t qbase = ((size_t)b*NT + i)*1536 + h*64;
    float q0 = g_qkv[qbase + lane];
    float q1 = g_qkv[qbase + lane + 32];

    float dots[MAXN];
    #pragma unroll
    for (int jj = 0; jj < MAXN; jj++) {
        size_t kb = ((size_t)b*NT + s_nbr[jj])*1536 + 512 + h*64;
        float p = q0 * g_qkv[kb + lane] + q1 * g_qkv[kb + lane + 32];
        #pragma unroll
        for (int o = 16; o; o >>= 1) p += __shfl_xor_sync(0xffffffffu, p, o);
        dots[jj] = (jj < nn) ? p * 0.125f : -1e30f;
    }
    float mx = -1e30f;
    #pragma unroll
    for (int jj = 0; jj < MAXN; jj++) mx = fmaxf(mx, dots[jj]);
    float sum = 0.f;
    #pragma unroll
    for (int jj = 0; jj < MAXN; jj++) { dots[jj] = expf(dots[jj] - mx); sum += dots[jj]; }
    float inv = 1.f / sum;
    float o0 = 0.f, o1 = 0.f;
    #pragma unroll
    for (int jj = 0; jj < MAXN; jj++) {
        size_t vb = ((size_t)b*NT + s_nbr[jj])*1536 + 1024 + h*64;
        float w = dots[jj] * inv;
        o0 += w * g_qkv[vb + lane];
        o1 += w * g_qkv[vb + lane + 32];
    }
    size_t obase = ((size_t)b*NT + i)*DD + h*64;
    __half* oh = (__half*)g_o_h;
    oh[obase + lane]      = __float2half_rn(o0);
    oh[obase + lane + 32] = __float2half_rn(o1);
}

// ---------------- gather + prediction head ----------------
__global__ void pred_kernel(const float* __restrict__ pw, float* __restrict__ out) {
    int b = blockIdx.x;
    __shared__ float gv[2048];
    const int rows[4] = {1024, 1280, 1344, 1360};
    int tid = threadIdx.x;   // 672
    for (int r = tid; r < 2048; r += 672) {
        int wch = r >> 9, d = r & 511;
        gv[r] = g_seq[((size_t)b*NT + rows[wch])*DD + d];
    }
    __syncthreads();
    float acc = 0.f;
    for (int r = 0; r < 2048; r++) acc += gv[r] * pw[(size_t)r*672 + tid];
    out[(size_t)b*672 + tid] = acc;
}

// ---------------- host ----------------
static void launch_tf32(const float* A, const float* Bm, const float* bias,
                        float* C, int M, int N, int K) {
    dim3 grid(N / 128, (M + 127) / 128);
    tgemm_kernel<0><<<grid, 256>>>(A, Bm, bias, C, M, N, K);
}

extern "C" void kernel_launch(void* const* d_in, const int* in_sizes, int n_in,
                              void* d_out, int out_size) {
    const float* x_enc   = (const float*)d_in[0];
    const float* xme     = (const float*)d_in[1];
    // d_in[2] = x_dec (unused by the model math)
    const float* xmd     = (const float*)d_in[3];
    const float* token_w = (const float*)d_in[4];
    const float* token_b = (const float*)d_in[5];
    const float* temp_w  = (const float*)d_in[6];
    const float* temp_b  = (const float*)d_in[7];
    const float* down_w  = (const float*)d_in[8];
    const float* down_b  = (const float*)d_in[9];
    const float* conv_w  = (const float*)d_in[10];
    const float* conv_b  = (const float*)d_in[11];
    const float* up_w    = (const float*)d_in[12];
    const float* up_b    = (const float*)d_in[13];
    const float* cln_s   = (const float*)d_in[14];
    const float* cln_b   = (const float*)d_in[15];
    const float* Wq      = (const float*)d_in[16];
    const float* Wk      = (const float*)d_in[17];
    const float* Wv      = (const float*)d_in[18];
    const float* Wo      = (const float*)d_in[19];
    const float* bo      = (const float*)d_in[20];
    const float* ln1_s   = (const float*)d_in[21];
    const float* ln1_b   = (const float*)d_in[22];
    const float* W1      = (const float*)d_in[23];
    const float* b1      = (const float*)d_in[24];
    const float* W2      = (const float*)d_in[25];
    const float* b2      = (const float*)d_in[26];
    const float* ln2_s   = (const float*)d_in[27];
    const float* ln2_b   = (const float*)d_in[28];
    const float* pred_w  = (const float*)d_in[29];

    float *emb, *d0, *cc, *pyr, *seq, *qkv, *tmp;
    uint32_t *seqr_h, *o_h, *ffn_h, *wqkvh, *woh, *w1h, *w2h;
    cudaGetSymbolAddress((void**)&emb,  g_emb);
    cudaGetSymbolAddress((void**)&d0,   g_d0);
    cudaGetSymbolAddress((void**)&cc,   g_cc);
    cudaGetSymbolAddress((void**)&pyr,  g_pyr);
    cudaGetSymbolAddress((void**)&seq,  g_seq);
    cudaGetSymbolAddress((void**)&qkv,  g_qkv);
    cudaGetSymbolAddress((void**)&tmp,  g_tmp);
    cudaGetSymbolAddress((void**)&seqr_h, g_seqr_h);
    cudaGetSymbolAddress((void**)&o_h,    g_o_h);
    cudaGetSymbolAddress((void**)&ffn_h,  g_ffn_h);
    cudaGetSymbolAddress((void**)&wqkvh,  g_wqkvh);
    cudaGetSymbolAddress((void**)&woh,    g_woh);
    cudaGetSymbolAddress((void**)&w1h,    g_w1h);
    cudaGetSymbolAddress((void**)&w2h,    g_w2h);

    // 0) pack all encoder weights to fp16 pair layout [K/2][N]
    pack_qkvh<<<(4*256*1536 + 255)/256, 256>>>(Wq, Wk, Wv, wqkvh);
    packh<<<(4*256*512  + 255)/256, 256>>>(Wo, woh, 512, 512, 4*256*512);
    packh<<<(4*256*2048 + 255)/256, 256>>>(W1, w1h, 512, 2048, 4*256*2048);
    packh<<<(4*1024*512 + 255)/256, 256>>>(W2, w2h, 2048, 512, 4*1024*512);

    // 1) embedding
    embed_kernel<<<dim3(LL, BB), 128>>>(x_enc, xme, xmd, token_w, token_b, temp_w, temp_b);

    // 2) bottleneck down-projection (tf32 path)
    launch_tf32(emb, down_w, down_b, d0, BB*LL, 128, DD);

    // 3) pyramid convs
    conv_kernel<<<dim3(256, BB), 128>>>(d0, LL, 0,   conv_w,               conv_b,       cc, 0);
    conv_kernel<<<dim3(64,  BB), 128>>>(cc, 336, 0,  conv_w + 128*128*4,   conv_b + 128, cc, 256);
    conv_kernel<<<dim3(16,  BB), 128>>>(cc, 336, 256,conv_w + 2*128*128*4, conv_b + 256, cc, 320);

    // 4) up-projection (tf32 path)
    launch_tf32(cc, up_w, up_b, pyr, BB*336, DD, 128);

    // 5) concat + LayerNorm -> seq (+ half copy)
    concat_ln_kernel<<<MROWS, 256>>>(cln_s, cln_b);

    // 6) encoder layers (fp16 GEMMs)
    const int MT = (MROWS + 127) / 128;   // 43
    for (int i = 0; i < 4; i++) {
        hgemm_kernel<0,0><<<dim3(12, MT), 256>>>(
            seqr_h, wqkvh + (size_t)i*256*1536, nullptr, qkv, MROWS, 1536, 512);

        attn_kernel<<<dim3(NT, BB), 256>>>();

        hgemm_kernel<0,0><<<dim3(4, MT), 256>>>(
            o_h, woh + (size_t)i*256*512, bo + i*DD, tmp, MROWS, 512, 512);
        add_ln_kernel<<<MROWS, 256>>>(ln1_s + i*DD, ln1_b + i*DD);

        hgemm_kernel<1,1><<<dim3(16, MT), 256>>>(
            seqr_h, w1h + (size_t)i*256*2048, b1 + i*DFF, ffn_h, MROWS, 2048, 512);
        hgemm_kernel<0,0><<<dim3(4, MT), 256>>>(
            ffn_h, w2h + (size_t)i*1024*512, b2 + i*DD, tmp, MROWS, 512, 2048);
        add_ln_kernel<<<MROWS, 256>>>(ln2_s + i*DD, ln2_b + i*DD);
    }

    // 7) gather + prediction head
    pred_kernel<<<BB, 672>>>(pred_w, (float*)d_out);
}

// round 12
// speedup vs baseline: 2.0097x; 1.0745x over previous
#include <cuda_runtime.h>
#include <cuda_fp16.h>
#include <math.h>
#include <stdint.h>

#define BB 4
#define LL 1025
#define NT 1361
#define DD 512
#define HH 8
#define DFF 2048
#define MROWS (BB*NT)         // 5444

// ---------------- scratch (static device allocations) ----------------
__device__ float g_emb [BB*LL*DD];
__device__ float g_d0  [BB*LL*128];
__device__ float g_cc  [BB*336*128];
__device__ float g_pyr [BB*336*DD];
__device__ float g_seq [BB*NT*DD];
__device__ float g_qkv [BB*NT*1536];
__device__ float g_tmp [BB*NT*DD];
__device__ float g_predp[BB*8*672];
// fp16 activations (uint4 arrays => 16B alignment guaranteed)
__device__ uint4 g_seqr_h[MROWS*DD/8];     // half copy of seq (GEMM A)
__device__ uint4 g_o_h   [MROWS*DD/8];     // attention output (half)
__device__ uint4 g_ffn_h [MROWS*DFF/8];    // W1+gelu output (half)
// fp16 weight packs: uint32 pairs, layout [K/2][N] per layer
__device__ uint4 g_wqkvh[4*256*1536/4];
__device__ uint4 g_woh  [4*256*512/4];
__device__ uint4 g_w1h  [4*256*2048/4];
__device__ uint4 g_w2h  [4*1024*512/4];

// ---------------- helpers ----------------
__device__ __forceinline__ uint32_t f2tf(float x) {
    uint32_t r;
    asm("cvt.rna.tf32.f32 %0, %1;" : "=r"(r) : "f"(x));
    return r;
}
__device__ __forceinline__ float gelu_exact(float x) {
    return 0.5f * x * (1.0f + erff(x * 0.70710678118654752f));
}
__device__ __forceinline__ uint32_t packh2(float a, float b) {
    __half2 h = __halves2half2(__float2half_rn(a), __float2half_rn(b));
    return *(uint32_t*)&h;
}
__device__ __forceinline__ void mma_tf32(float c[4], const uint32_t a[4], const uint32_t b[2]) {
    asm volatile(
        "mma.sync.aligned.m16n8k8.row.col.f32.tf32.tf32.f32 "
        "{%0,%1,%2,%3}, {%4,%5,%6,%7}, {%8,%9}, {%0,%1,%2,%3};\n"
        : "+f"(c[0]), "+f"(c[1]), "+f"(c[2]), "+f"(c[3])
        : "r"(a[0]), "r"(a[1]), "r"(a[2]), "r"(a[3]), "r"(b[0]), "r"(b[1]));
}
__device__ __forceinline__ void mma_f16(float c[4], const uint32_t a[4], const uint32_t b[2]) {
    asm volatile(
        "mma.sync.aligned.m16n8k16.row.col.f32.f16.f16.f32 "
        "{%0,%1,%2,%3}, {%4,%5,%6,%7}, {%8,%9}, {%0,%1,%2,%3};\n"
        : "+f"(c[0]), "+f"(c[1]), "+f"(c[2]), "+f"(c[3])
        : "r"(a[0]), "r"(a[1]), "r"(a[2]), "r"(a[3]), "r"(b[0]), "r"(b[1]));
}

// ---------------- fp16 weight packing (vectorized, 4 outputs/thread) -------------
__global__ void packh(const float* __restrict__ in, uint32_t* __restrict__ out,
                      int K, int N, int total4) {
    int idx = blockIdx.x*blockDim.x + threadIdx.x;   // over total/4
    if (idx >= total4) return;
    int K2 = K >> 1, N4 = N >> 2;
    int n4 = idx % N4;
    int k2 = (idx / N4) % K2;
    int l  = idx / (N4 * K2);
    const float* src = in + ((size_t)l*K + 2*k2)*N + n4*4;
    float4 r0 = *(const float4*)src;
    float4 r1 = *(const float4*)(src + N);
    uint4 o;
    o.x = packh2(r0.x, r1.x); o.y = packh2(r0.y, r1.y);
    o.z = packh2(r0.z, r1.z); o.w = packh2(r0.w, r1.w);
    *(uint4*)(out + (size_t)idx*4) = o;
}
__global__ void pack_qkvh(const float* __restrict__ Wq,
                          const float* __restrict__ Wk,
                          const float* __restrict__ Wv,
                          uint32_t* __restrict__ out) {
    int idx = blockIdx.x*blockDim.x + threadIdx.x;   // 4*256*384
    if (idx >= 4*256*384) return;
    int n4 = idx % 384;
    int t  = idx / 384;         // l*256 + k2
    int k2 = t & 255;
    int l  = t >> 8;
    int n  = n4 * 4;
    const float* src = (n < 512) ? Wq : (n < 1024) ? Wk : Wv;
    int nn = n & 511;
    size_t base = ((size_t)l*512 + 2*k2)*512 + nn;
    float4 r0 = *(const float4*)(src + base);
    float4 r1 = *(const float4*)(src + base + 512);
    uint4 o;
    o.x = packh2(r0.x, r1.x); o.y = packh2(r0.y, r1.y);
    o.z = packh2(r0.z, r1.z); o.w = packh2(r0.w, r1.w);
    *(uint4*)(out + (size_t)idx*4) = o;
}

// ---------------- FP16 mma.sync GEMM: C = A(MxK)@B(KxN) [+bias][+gelu] ----------
// BM=BN=128, BK=32 halfs (16 half2 rows); 256 thr = 8 warps (4M x 2N), warp 32x64.
template<int ACT, int OUTH>
__global__ __launch_bounds__(256)
void hgemm_kernel(const uint32_t* __restrict__ A32, const uint32_t* __restrict__ Bw,
                  const float* __restrict__ bias, void* __restrict__ Cv,
                  int M, int N, int K) {
    __shared__ uint32_t As[2][16][136];
    __shared__ uint32_t Bs[2][16][136];
    int tid = threadIdx.x;
    int bx = blockIdx.x, by = blockIdx.y;
    int w = tid >> 5, lane = tid & 31;
    int wm = w & 3, wn = w >> 2;
    int g = lane >> 2, t4 = lane & 3;
    int K2 = K >> 1;

    float c[2][8][4];
    #pragma unroll
    for (int mt = 0; mt < 2; mt++)
        #pragma unroll
        for (int nt = 0; nt < 8; nt++)
            #pragma unroll
            for (int r = 0; r < 4; r++) c[mt][nt][r] = 0.f;

    int am = tid >> 2;            // 0..63
    int aq = (tid & 3) * 4;       // 0,4,8,12
    int arow0 = by*128 + am, arow1 = arow0 + 64;
    const uint32_t* Ap0 = A32 + (size_t)arow0 * K2 + aq;
    const uint32_t* Ap1 = A32 + (size_t)arow1 * K2 + aq;
    bool v0 = (arow0 < M), v1 = (arow1 < M);

    int br = tid >> 4;            // 0..15
    int bu = (tid & 15) * 4;      // 0..60
    const uint32_t* Bp = Bw + (size_t)br * N + bx*128 + bu;

    int nk = K2 >> 4;
    uint4 a0, a1, b0, b1;
    const uint4 z4 = make_uint4(0,0,0,0);

    a0 = v0 ? *(const uint4*)(Ap0) : z4;
    a1 = v1 ? *(const uint4*)(Ap1) : z4;
    b0 = *(const uint4*)(Bp);
    b1 = *(const uint4*)(Bp + 64);
    As[0][aq+0][am] = a0.x; As[0][aq+1][am] = a0.y; As[0][aq+2][am] = a0.z; As[0][aq+3][am] = a0.w;
    As[0][aq+0][am+64] = a1.x; As[0][aq+1][am+64] = a1.y; As[0][aq+2][am+64] = a1.z; As[0][aq+3][am+64] = a1.w;
    *(uint4*)&Bs[0][br][bu] = b0;
    *(uint4*)&Bs[0][br][bu+64] = b1;
    __syncthreads();

    int mb = wm*32 + g;
    int nb = wn*64 + g;
    int buf = 0;
    for (int tile = 1; tile < nk; tile++) {
        a0 = v0 ? *(const uint4*)(Ap0 + tile*16) : z4;
        a1 = v1 ? *(const uint4*)(Ap1 + tile*16) : z4;
        b0 = *(const uint4*)(Bp + (size_t)(tile*16)*N);
        b1 = *(const uint4*)(Bp + (size_t)(tile*16)*N + 64);

        #pragma unroll
        for (int ks = 0; ks < 16; ks += 8) {
            uint32_t af[2][4], bf[8][2];
            #pragma unroll
            for (int mt = 0; mt < 2; mt++) {
                af[mt][0] = As[buf][ks+t4  ][mb + mt*16];
                af[mt][1] = As[buf][ks+t4  ][mb + mt*16 + 8];
                af[mt][2] = As[buf][ks+t4+4][mb + mt*16];
                af[mt][3] = As[buf][ks+t4+4][mb + mt*16 + 8];
            }
            #pragma unroll
            for (int nt = 0; nt < 8; nt++) {
                bf[nt][0] = Bs[buf][ks+t4  ][nb + nt*8];
                bf[nt][1] = Bs[buf][ks+t4+4][nb + nt*8];
            }
            #pragma unroll
            for (int mt = 0; mt < 2; mt++)
                #pragma unroll
                for (int nt = 0; nt < 8; nt++)
                    mma_f16(c[mt][nt], af[mt], bf[nt]);
        }

        int nbuf = buf ^ 1;
        As[nbuf][aq+0][am] = a0.x; As[nbuf][aq+1][am] = a0.y; As[nbuf][aq+2][am] = a0.z; As[nbuf][aq+3][am] = a0.w;
        As[nbuf][aq+0][am+64] = a1.x; As[nbuf][aq+1][am+64] = a1.y; As[nbuf][aq+2][am+64] = a1.z; As[nbuf][aq+3][am+64] = a1.w;
        *(uint4*)&Bs[nbuf][br][bu] = b0;
        *(uint4*)&Bs[nbuf][br][bu+64] = b1;
        __syncthreads();
        buf = nbuf;
    }

    #pragma unroll
    for (int ks = 0; ks < 16; ks += 8) {
        uint32_t af[2][4], bf[8][2];
        #pragma unroll
        for (int mt = 0; mt < 2; mt++) {
            af[mt][0] = As[buf][ks+t4  ][mb + mt*16];
            af[mt][1] = As[buf][ks+t4  ][mb + mt*16 + 8];
            af[mt][2] = As[buf][ks+t4+4][mb + mt*16];
            af[mt][3] = As[buf][ks+t4+4][mb + mt*16 + 8];
        }
        #pragma unroll
        for (int nt = 0; nt < 8; nt++) {
            bf[nt][0] = Bs[buf][ks+t4  ][nb + nt*8];
            bf[nt][1] = Bs[buf][ks+t4+4][nb + nt*8];
        }
        #pragma unroll
        for (int mt = 0; mt < 2; mt++)
            #pragma unroll
            for (int nt = 0; nt < 8; nt++)
                mma_f16(c[mt][nt], af[mt], bf[nt]);
    }

    #pragma unroll
    for (int mt = 0; mt < 2; mt++) {
        int row0 = by*128 + wm*32 + mt*16 + g;
        int row1 = row0 + 8;
        #pragma unroll
        for (int nt = 0; nt < 8; nt++) {
            int col = bx*128 + wn*64 + nt*8 + 2*t4;
            float x0 = c[mt][nt][0], x1 = c[mt][nt][1];
            float y0 = c[mt][nt][2], y1 = c[mt][nt][3];
            if (bias) {
                float bx0 = bias[col], bx1 = bias[col+1];
                x0 += bx0; x1 += bx1; y0 += bx0; y1 += bx1;
            }
            if (ACT == 1) {
                x0 = gelu_exact(x0); x1 = gelu_exact(x1);
                y0 = gelu_exact(y0); y1 = gelu_exact(y1);
            }
            if (OUTH) {
                uint32_t* Ch = (uint32_t*)Cv;
                if (row0 < M) Ch[((size_t)row0*N + col) >> 1] = packh2(x0, x1);
                if (row1 < M) Ch[((size_t)row1*N + col) >> 1] = packh2(y0, y1);
            } else {
                float* Cf = (float*)Cv;
                if (row0 < M) { float2 v; v.x = x0; v.y = x1; *(float2*)&Cf[(size_t)row0*N + col] = v; }
                if (row1 < M) { float2 v; v.x = y0; v.y = y1; *(float2*)&Cf[(size_t)row1*N + col] = v; }
            }
        }
    }
}

// ---------------- TF32 mma.sync GEMM (down/up projections) ----------------------
template<int ACT>
__global__ __launch_bounds__(256)
void tgemm_kernel(const float* __restrict__ A, const float* __restrict__ Bm,
                  const float* __restrict__ bias, float* __restrict__ C,
                  int M, int N, int K) {
    __shared__ uint32_t As[2][16][136];
    __shared__ uint32_t Bs[2][16][136];
    int tid = threadIdx.x;
    int bx = blockIdx.x, by = blockIdx.y;
    int w = tid >> 5, lane = tid & 31;
    int wm = w & 3, wn = w >> 2;
    int g = lane >> 2, t4 = lane & 3;

    float c[2][8][4];
    #pragma unroll
    for (int mt = 0; mt < 2; mt++)
        #pragma unroll
        for (int nt = 0; nt < 8; nt++)
            #pragma unroll
            for (int r = 0; r < 4; r++) c[mt][nt][r] = 0.f;

    int am = tid >> 2;
    int ak = (tid & 3) * 4;
    int arow0 = by*128 + am;
    int arow1 = arow0 + 64;
    const float* Ap0 = A + (size_t)arow0 * K + ak;
    const float* Ap1 = A + (size_t)arow1 * K + ak;
    bool v0 = (arow0 < M), v1 = (arow1 < M);

    int bk = tid >> 5;
    int bn = (tid & 31) * 4;
    const float* Bp = Bm + (size_t)bk * N + bx*128 + bn;

    int nk = K >> 4;
    float4 a0, a1, b0, b1;

    a0 = v0 ? *(const float4*)(Ap0) : make_float4(0,0,0,0);
    a1 = v1 ? *(const float4*)(Ap1) : make_float4(0,0,0,0);
    b0 = *(const float4*)(Bp);
    b1 = *(const float4*)(Bp + (size_t)8*N);
    As[0][ak+0][am] = f2tf(a0.x); As[0][ak+1][am] = f2tf(a0.y);
    As[0][ak+2][am] = f2tf(a0.z); As[0][ak+3][am] = f2tf(a0.w);
    As[0][ak+0][am+64] = f2tf(a1.x); As[0][ak+1][am+64] = f2tf(a1.y);
    As[0][ak+2][am+64] = f2tf(a1.z); As[0][ak+3][am+64] = f2tf(a1.w);
    Bs[0][bk][bn+0] = f2tf(b0.x); Bs[0][bk][bn+1] = f2tf(b0.y);
    Bs[0][bk][bn+2] = f2tf(b0.z); Bs[0][bk][bn+3] = f2tf(b0.w);
    Bs[0][bk+8][bn+0] = f2tf(b1.x); Bs[0][bk+8][bn+1] = f2tf(b1.y);
    Bs[0][bk+8][bn+2] = f2tf(b1.z); Bs[0][bk+8][bn+3] = f2tf(b1.w);
    __syncthreads();

    int mb = wm*32 + g;
    int nb = wn*64 + g;
    int buf = 0;
    for (int tile = 1; tile < nk; tile++) {
        const float* ap0 = Ap0 + tile*16;
        const float* ap1 = Ap1 + tile*16;
        const float* bp  = Bp + (size_t)(tile*16) * N;
        a0 = v0 ? *(const float4*)(ap0) : make_float4(0,0,0,0);
        a1 = v1 ? *(const float4*)(ap1) : make_float4(0,0,0,0);
        b0 = *(const float4*)(bp);
        b1 = *(const float4*)(bp + (size_t)8*N);

        #pragma unroll
        for (int ks = 0; ks < 16; ks += 8) {
            uint32_t af[2][4], bf[8][2];
            #pragma unroll
            for (int mt = 0; mt < 2; mt++) {
                af[mt][0] = As[buf][ks+t4  ][mb + mt*16];
                af[mt][1] = As[buf][ks+t4  ][mb + mt*16 + 8];
                af[mt][2] = As[buf][ks+t4+4][mb + mt*16];
                af[mt][3] = As[buf][ks+t4+4][mb + mt*16 + 8];
            }
            #pragma unroll
            for (int nt = 0; nt < 8; nt++) {
                bf[nt][0] = Bs[buf][ks+t4  ][nb + nt*8];
                bf[nt][1] = Bs[buf][ks+t4+4][nb + nt*8];
            }
            #pragma unroll
            for (int mt = 0; mt < 2; mt++)
                #pragma unroll
                for (int nt = 0; nt < 8; nt++)
                    mma_tf32(c[mt][nt], af[mt], bf[nt]);
        }

        int nbuf = buf ^ 1;
        As[nbuf][ak+0][am] = f2tf(a0.x); As[nbuf][ak+1][am] = f2tf(a0.y);
        As[nbuf][ak+2][am] = f2tf(a0.z); As[nbuf][ak+3][am] = f2tf(a0.w);
        As[nbuf][ak+0][am+64] = f2tf(a1.x); As[nbuf][ak+1][am+64] = f2tf(a1.y);
        As[nbuf][ak+2][am+64] = f2tf(a1.z); As[nbuf][ak+3][am+64] = f2tf(a1.w);
        Bs[nbuf][bk][bn+0] = f2tf(b0.x); Bs[nbuf][bk][bn+1] = f2tf(b0.y);
        Bs[nbuf][bk][bn+2] = f2tf(b0.z); Bs[nbuf][bk][bn+3] = f2tf(b0.w);
        Bs[nbuf][bk+8][bn+0] = f2tf(b1.x); Bs[nbuf][bk+8][bn+1] = f2tf(b1.y);
        Bs[nbuf][bk+8][bn+2] = f2tf(b1.z); Bs[nbuf][bk+8][bn+3] = f2tf(b1.w);
        __syncthreads();
        buf = nbuf;
    }

    #pragma unroll
    for (int ks = 0; ks < 16; ks += 8) {
        uint32_t af[2][4], bf[8][2];
        #pragma unroll
        for (int mt = 0; mt < 2; mt++) {
            af[mt][0] = As[buf][ks+t4  ][mb + mt*16];
            af[mt][1] = As[buf][ks+t4  ][mb + mt*16 + 8];
            af[mt][2] = As[buf][ks+t4+4][mb + mt*16];
            af[mt][3] = As[buf][ks+t4+4][mb + mt*16 + 8];
        }
        #pragma unroll
        for (int nt = 0; nt < 8; nt++) {
            bf[nt][0] = Bs[buf][ks+t4  ][nb + nt*8];
            bf[nt][1] = Bs[buf][ks+t4+4][nb + nt*8];
        }
        #pragma unroll
        for (int mt = 0; mt < 2; mt++)
            #pragma unroll
            for (int nt = 0; nt < 8; nt++)
                mma_tf32(c[mt][nt], af[mt], bf[nt]);
    }

    #pragma unroll
    for (int mt = 0; mt < 2; mt++) {
        int row0 = by*128 + wm*32 + mt*16 + g;
        int row1 = row0 + 8;
        #pragma unroll
        for (int nt = 0; nt < 8; nt++) {
            int col = bx*128 + wn*64 + nt*8 + 2*t4;
            float2 v0o, v1o;
            v0o.x = c[mt][nt][0]; v0o.y = c[mt][nt][1];
            v1o.x = c[mt][nt][2]; v1o.y = c[mt][nt][3];
            if (bias) {
                float bx0 = bias[col], bx1 = bias[col+1];
                v0o.x += bx0; v0o.y += bx1; v1o.x += bx0; v1o.y += bx1;
            }
            if (ACT == 1) {
                v0o.x = gelu_exact(v0o.x); v0o.y = gelu_exact(v0o.y);
                v1o.x = gelu_exact(v1o.x); v1o.y = gelu_exact(v1o.y);
            }
            if (row0 < M) *(float2*)&C[(size_t)row0*N + col] = v0o;
            if (row1 < M) *(float2*)&C[(size_t)row1*N + col] = v1o;
        }
    }
}

// ---------------- embedding ----------------
__global__ void embed_kernel(const float* __restrict__ x_enc,
                             const float* __restrict__ xme,
                             const float* __restrict__ xmd,
                             const float* __restrict__ tw,
                             const float* __restrict__ tb,
                             const float* __restrict__ tempw,
                             const float* __restrict__ tempb) {
    int t = blockIdx.x, b = blockIdx.y;
    __shared__ float xv[3][7];
    __shared__ float xm[4];
    int tid = threadIdx.x;   // 128
    if (tid < 21) {
        int k = tid / 7, i = tid % 7;
        int r = t - 1 + k;
        int rr = (r + 1025) % 1025;
        float val = 0.f;
        if (rr < 1024) val = x_enc[((size_t)b*1024 + rr)*7 + i];
        xv[k][i] = val;
    }
    if (tid >= 32 && tid < 36) {
        int m = tid - 32;
        xm[m] = (t < 1024) ? xme[((size_t)b*1024 + t)*4 + m]
                           : xmd[((size_t)b*96)*4 + m];
    }
    __syncthreads();
    for (int d = tid; d < DD; d += 128) {
        float acc = tb[d];
        #pragma unroll
        for (int i = 0; i < 7; i++)
            #pragma unroll
            for (int k = 0; k < 3; k++)
                acc += xv[k][i] * tw[(d*7 + i)*3 + k];
        acc += tempb[d];
        #pragma unroll
        for (int m = 0; m < 4; m++) acc += xm[m] * tempw[m*DD + d];
        int m2 = d & ~1;
        float div = expf(-9.210340371976184f / 512.0f * (float)m2);
        float arg = (float)t * div;
        acc += (d & 1) ? cosf(arg) : sinf(arg);
        g_emb[((size_t)b*LL + t)*DD + d] = acc;
    }
}

// ---------------- conv (stride-4, kernel-4, ELU): 8 outputs per block ----------
__global__ void conv_kernel(const float* __restrict__ in, int ibs, int inOff,
                            const float* __restrict__ w, const float* __restrict__ bias,
                            float* __restrict__ out, int outOff) {
    int t0 = blockIdx.x * 8, b = blockIdx.y;
    int tid = threadIdx.x;   // 128 (= oc)
    __shared__ float si[8*512];
    const float* ip = in + (size_t)(b*ibs + inOff + 4*t0) * 128;
    #pragma unroll
    for (int i = 0; i < 32; i++) si[i*128 + tid] = ip[i*128 + tid];
    __syncthreads();
    float bv = bias[tid];
    float acc[8];
    #pragma unroll
    for (int t = 0; t < 8; t++) acc[t] = bv;
    #pragma unroll 2
    for (int ic = 0; ic < 128; ic++) {
        float4 w4 = *(const float4*)&w[((size_t)tid*128 + ic)*4];
        #pragma unroll
        for (int t = 0; t < 8; t++) {
            const float* s = si + t*512;
            acc[t] += s[ic]*w4.x + s[128+ic]*w4.y + s[256+ic]*w4.z + s[384+ic]*w4.w;
        }
    }
    #pragma unroll
    for (int t = 0; t < 8; t++) {
        float a = acc[t];
        a = (a > 0.f) ? a : expm1f(a);
        out[(size_t)(b*336 + outOff + t0 + t)*128 + tid] = a;
    }
}

// ---------------- layernorm (512 wide, 256 threads) + half copy ----------------
__device__ __forceinline__ void ln_core(const float* __restrict__ x0,
                                        const float* __restrict__ x1,
                                        const float* __restrict__ sc,
                                        const float* __restrict__ bb,
                                        float* __restrict__ out,
                                        __half* __restrict__ out_h) {
    __shared__ float red[8];
    int tid = threadIdx.x;
    float v0 = x0[tid]       + (x1 ? x1[tid]       : 0.f);
    float v1 = x0[tid + 256] + (x1 ? x1[tid + 256] : 0.f);
    float sum = v0 + v1;
    #pragma unroll
    for (int o = 16; o; o >>= 1) sum += __shfl_xor_sync(0xffffffffu, sum, o);
    if ((tid & 31) == 0) red[tid >> 5] = sum;
    __syncthreads();
    float tot = 0.f;
    #pragma unroll
    for (int w = 0; w < 8; w++) tot += red[w];
    float mean = tot * (1.0f/512.0f);
    __syncthreads();
    float d0 = v0 - mean, d1 = v1 - mean;
    float sq = d0*d0 + d1*d1;
    #pragma unroll
    for (int o = 16; o; o >>= 1) sq += __shfl_xor_sync(0xffffffffu, sq, o);
    if ((tid & 31) == 0) red[tid >> 5] = sq;
    __syncthreads();
    float vtot = 0.f;
    #pragma unroll
    for (int w = 0; w < 8; w++) vtot += red[w];
    float inv = rsqrtf(vtot * (1.0f/512.0f) + 1e-5f);
    float o0 = d0 * inv * sc[tid]       + bb[tid];
    float o1 = d1 * inv * sc[tid + 256] + bb[tid + 256];
    out[tid]       = o0;
    out[tid + 256] = o1;
    out_h[tid]       = __float2half_rn(o0);
    out_h[tid + 256] = __float2half_rn(o1);
}

__global__ void concat_ln_kernel(const float* __restrict__ sc, const float* __restrict__ bb) {
    int row = blockIdx.x;
    int b = row / NT, n = row % NT;
    const float* src = (n < LL) ? &g_emb[((size_t)b*LL + n)*DD]
                                : &g_pyr[((size_t)b*336 + (n - LL))*DD];
    ln_core(src, nullptr, sc, bb, &g_seq[(size_t)row*DD],
            (__half*)g_seqr_h + (size_t)row*DD);
}

__global__ void add_ln_kernel(const float* __restrict__ sc, const float* __restrict__ bb) {
    size_t row = blockIdx.x;
    ln_core(&g_seq[row*DD], &g_tmp[row*DD], sc, bb, &g_seq[row*DD],
            (__half*)g_seqr_h + row*DD);
}

// ---------------- fused sparse attention (fp32 qkv in, half out) ---------------
#define MAXN 12
__global__ __launch_bounds__(256)
void attn_kernel() {
    int i = blockIdx.x, b = blockIdx.y;
    __shared__ int s_nbr[MAXN];
    __shared__ int s_nn;
    int tid = threadIdx.x;
    if (tid == 0) {
        const int starts[5] = {0, 1025, 1281, 1345, 1361};
        int li = (i < 1025) ? 0 : (i < 1281) ? 1 : (i < 1345) ? 2 : 3;
        int s = starts[li], e = starts[li+1];
        int nn = 0;
        int jlo = (i - 2 > s) ? i - 2 : s;
        int jhi = (i + 2 < e - 1) ? i + 2 : e - 1;
        for (int j = jlo; j <= jhi; j++) s_nbr[nn++] = j;
        if (li > 0) {
            int ps = starts[li-1];
            int qq = i - s;
            int lo = ps + qq * 4;
            int hi = (i == e - 1) ? s : ps + (qq + 1) * 4;
            for (int j = lo; j < hi; j++) s_nbr[nn++] = j;
        }
        if (li < 3) {
            int su = starts[li+1];
            int szu = starts[li+2] - su;
            int qq = (i - s) / 4;
            s_nbr[nn++] = su + ((qq < szu - 1) ? qq : szu - 1);
        }
        s_nn = nn;
        for (int j = nn; j < MAXN; j++) s_nbr[j] = i;
    }
    __syncthreads();
    int nn = s_nn;
    int h = tid >> 5, lane = tid & 31;
    size_t qbase = ((size_t)b*NT + i)*1536 + h*64;
    float q0 = g_qkv[qbase + lane];
    float q1 = g_qkv[qbase + lane + 32];

    float dots[MAXN];
    #pragma unroll
    for (int jj = 0; jj < MAXN; jj++) {
        size_t kb = ((size_t)b*NT + s_nbr[jj])*1536 + 512 + h*64;
        float p = q0 * g_qkv[kb + lane] + q1 * g_qkv[kb + lane + 32];
        #pragma unroll
        for (int o = 16; o; o >>= 1) p += __shfl_xor_sync(0xffffffffu, p, o);
        dots[jj] = (jj < nn) ? p * 0.125f : -1e30f;
    }
    float mx = -1e30f;
    #pragma unroll
    for (int jj = 0; jj < MAXN; jj++) mx = fmaxf(mx, dots[jj]);
    float sum = 0.f;
    #pragma unroll
    for (int jj = 0; jj < MAXN; jj++) { dots[jj] = expf(dots[jj] - mx); sum += dots[jj]; }
    float inv = 1.f / sum;
    float o0 = 0.f, o1 = 0.f;
    #pragma unroll
    for (int jj = 0; jj < MAXN; jj++) {
        size_t vb = ((size_t)b*NT + s_nbr[jj])*1536 + 1024 + h*64;
        float w = dots[jj] * inv;
        o0 += w * g_qkv[vb + lane];
        o1 += w * g_qkv[vb + lane + 32];
    }
    size_t obase = ((size_t)b*NT + i)*DD + h*64;
    __half* oh = (__half*)g_o_h;
    oh[obase + lane]      = __float2half_rn(o0);
    oh[obase + lane + 32] = __float2half_rn(o1);
}

// ---------------- gather + prediction head (split-r partials + reduce) ---------
__global__ void pred_part(const float* __restrict__ pw) {
    int b = blockIdx.x, ch = blockIdx.y;   // 8 chunks of 256 rows
    __shared__ float gv[256];
    const int rows[4] = {1024, 1280, 1344, 1360};
    int tid = threadIdx.x;   // 672
    if (tid < 256) {
        int r = ch*256 + tid;
        int wch = r >> 9, d = r & 511;
        gv[tid] = g_seq[((size_t)b*NT + rows[wch])*DD + d];
    }
    __syncthreads();
    float acc = 0.f;
    const float* p = pw + (size_t)(ch*256)*672 + tid;
    #pragma unroll 8
    for (int j = 0; j < 256; j++) acc += gv[j] * p[(size_t)j*672];
    g_predp[(b*8 + ch)*672 + tid] = acc;
}
__global__ void pred_reduce(float* __restrict__ out) {
    int idx = blockIdx.x*blockDim.x + threadIdx.x;   // BB*672
    if (idx >= BB*672) return;
    int b = idx / 672, c = idx % 672;
    float s = 0.f;
    #pragma unroll
    for (int ch = 0; ch < 8; ch++) s += g_predp[(b*8 + ch)*672 + c];
    out[idx] = s;
}

// ---------------- host ----------------
static void launch_tf32(const float* A, const float* Bm, const float* bias,
                        float* C, int M, int N, int K) {
    dim3 grid(N / 128, (M + 127) / 128);
    tgemm_kernel<0><<<grid, 256>>>(A, Bm, bias, C, M, N, K);
}

extern "C" void kernel_launch(void* const* d_in, const int* in_sizes, int n_in,
                              void* d_out, int out_size) {
    const float* x_enc   = (const float*)d_in[0];
    const float* xme     = (const float*)d_in[1];
    // d_in[2] = x_dec (unused by the model math)
    const float* xmd     = (const float*)d_in[3];
    const float* token_w = (const float*)d_in[4];
    const float* token_b = (const float*)d_in[5];
    const float* temp_w  = (const float*)d_in[6];
    const float* temp_b  = (const float*)d_in[7];
    const float* down_w  = (const float*)d_in[8];
    const float* down_b  = (const float*)d_in[9];
    const float* conv_w  = (const float*)d_in[10];
    const float* conv_b  = (const float*)d_in[11];
    const float* up_w    = (const float*)d_in[12];
    const float* up_b    = (const float*)d_in[13];
    const float* cln_s   = (const float*)d_in[14];
    const float* cln_b   = (const float*)d_in[15];
    const float* Wq      = (const float*)d_in[16];
    const float* Wk      = (const float*)d_in[17];
    const float* Wv      = (const float*)d_in[18];
    const float* Wo      = (const float*)d_in[19];
    const float* bo      = (const float*)d_in[20];
    const float* ln1_s   = (const float*)d_in[21];
    const float* ln1_b   = (const float*)d_in[22];
    const float* W1      = (const float*)d_in[23];
    const float* b1      = (const float*)d_in[24];
    const float* W2      = (const float*)d_in[25];
    const float* b2      = (const float*)d_in[26];
    const float* ln2_s   = (const float*)d_in[27];
    const float* ln2_b   = (const float*)d_in[28];
    const float* pred_w  = (const float*)d_in[29];

    float *emb, *d0, *cc, *pyr, *seq, *qkv, *tmp;
    uint32_t *seqr_h, *o_h, *ffn_h, *wqkvh, *woh, *w1h, *w2h;
    cudaGetSymbolAddress((void**)&emb,  g_emb);
    cudaGetSymbolAddress((void**)&d0,   g_d0);
    cudaGetSymbolAddress((void**)&cc,   g_cc);
    cudaGetSymbolAddress((void**)&pyr,  g_pyr);
    cudaGetSymbolAddress((void**)&seq,  g_seq);
    cudaGetSymbolAddress((void**)&qkv,  g_qkv);
    cudaGetSymbolAddress((void**)&tmp,  g_tmp);
    cudaGetSymbolAddress((void**)&seqr_h, g_seqr_h);
    cudaGetSymbolAddress((void**)&o_h,    g_o_h);
    cudaGetSymbolAddress((void**)&ffn_h,  g_ffn_h);
    cudaGetSymbolAddress((void**)&wqkvh,  g_wqkvh);
    cudaGetSymbolAddress((void**)&woh,    g_woh);
    cudaGetSymbolAddress((void**)&w1h,    g_w1h);
    cudaGetSymbolAddress((void**)&w2h,    g_w2h);

    // 0) pack all encoder weights to fp16 pair layout [K/2][N] (vectorized)
    pack_qkvh<<<(4*256*384 + 255)/256, 256>>>(Wq, Wk, Wv, wqkvh);
    packh<<<(4*256*128 + 255)/256, 256>>>(Wo, woh, 512, 512, 4*256*128);
    packh<<<(4*256*512 + 255)/256, 256>>>(W1, w1h, 512, 2048, 4*256*512);
    packh<<<(4*1024*128 + 255)/256, 256>>>(W2, w2h, 2048, 512, 4*1024*128);

    // 1) embedding
    embed_kernel<<<dim3(LL, BB), 128>>>(x_enc, xme, xmd, token_w, token_b, temp_w, temp_b);

    // 2) bottleneck down-projection (tf32 path)
    launch_tf32(emb, down_w, down_b, d0, BB*LL, 128, DD);

    // 3) pyramid convs (8 outputs per block)
    conv_kernel<<<dim3(32, BB), 128>>>(d0, LL, 0,   conv_w,               conv_b,       cc, 0);
    conv_kernel<<<dim3(8,  BB), 128>>>(cc, 336, 0,  conv_w + 128*128*4,   conv_b + 128, cc, 256);
    conv_kernel<<<dim3(2,  BB), 128>>>(cc, 336, 256,conv_w + 2*128*128*4, conv_b + 256, cc, 320);

    // 4) up-projection (tf32 path)
    launch_tf32(cc, up_w, up_b, pyr, BB*336, DD, 128);

    // 5) concat + LayerNorm -> seq (+ half copy)
    concat_ln_kernel<<<MROWS, 256>>>(cln_s, cln_b);

    // 6) encoder layers (fp16 GEMMs)
    const int MT = (MROWS + 127) / 128;   // 43
    for (int i = 0; i < 4; i++) {
        hgemm_kernel<0,0><<<dim3(12, MT), 256>>>(
            seqr_h, wqkvh + (size_t)i*256*1536, nullptr, qkv, MROWS, 1536, 512);

        attn_kernel<<<dim3(NT, BB), 256>>>();

        hgemm_kernel<0,0><<<dim3(4, MT), 256>>>(
            o_h, woh + (size_t)i*256*512, bo + i*DD, tmp, MROWS, 512, 512);
        add_ln_kernel<<<MROWS, 256>>>(ln1_s + i*DD, ln1_b + i*DD);

        hgemm_kernel<1,1><<<dim3(16, MT), 256>>>(
            seqr_h, w1h + (size_t)i*256*2048, b1 + i*DFF, ffn_h, MROWS, 2048, 512);
        hgemm_kernel<0,0><<<dim3(4, MT), 256>>>(
            ffn_h, w2h + (size_t)i*1024*512, b2 + i*DD, tmp, MROWS, 512, 2048);
        add_ln_kernel<<<MROWS, 256>>>(ln2_s + i*DD, ln2_b + i*DD);
    }

    // 7) gather + prediction head (split partials, deterministic reduce)
    pred_part<<<dim3(BB, 8), 672>>>(pred_w);
    pred_reduce<<<(BB*672 + 255)/256, 256>>>((float*)d_out);
}

// round 13
// speedup vs baseline: 2.1013x; 1.0456x over previous
#include <cuda_runtime.h>
#include <cuda_fp16.h>
#include <math.h>
#include <stdint.h>

#define BB 4
#define LL 1025
#define NT 1361
#define DD 512
#define HH 8
#define DFF 2048
#define MROWS (BB*NT)         // 5444

// ---------------- scratch (static device allocations) ----------------
__device__ float g_emb [BB*LL*DD];
__device__ float g_d0  [BB*LL*128];
__device__ float g_cc  [BB*336*128];
__device__ float g_pyr [BB*336*DD];
__device__ float g_seq [BB*NT*DD];
__device__ float g_qkv [BB*NT*1536];
__device__ float g_tmp [BB*NT*DD];
__device__ float g_predp[BB*8*672];
// fp16 activations (uint4 arrays => 16B alignment guaranteed)
__device__ uint4 g_seqr_h[MROWS*DD/8];     // half copy of seq (GEMM A)
__device__ uint4 g_o_h   [MROWS*DD/8];     // attention output (half)
__device__ uint4 g_ffn_h [MROWS*DFF/8];    // W1+gelu output (half)
// fp16 weight packs: uint32 pairs, layout [K/2][N] per layer
__device__ uint4 g_wqkvh[4*256*1536/4];
__device__ uint4 g_woh  [4*256*512/4];
__device__ uint4 g_w1h  [4*256*2048/4];
__device__ uint4 g_w2h  [4*1024*512/4];

// ---------------- helpers ----------------
__device__ __forceinline__ uint32_t f2tf(float x) {
    uint32_t r;
    asm("cvt.rna.tf32.f32 %0, %1;" : "=r"(r) : "f"(x));
    return r;
}
__device__ __forceinline__ float gelu_exact(float x) {
    return 0.5f * x * (1.0f + erff(x * 0.70710678118654752f));
}
__device__ __forceinline__ uint32_t packh2(float a, float b) {
    __half2 h = __halves2half2(__float2half_rn(a), __float2half_rn(b));
    return *(uint32_t*)&h;
}
__device__ __forceinline__ void mma_tf32(float c[4], const uint32_t a[4], const uint32_t b[2]) {
    asm volatile(
        "mma.sync.aligned.m16n8k8.row.col.f32.tf32.tf32.f32 "
        "{%0,%1,%2,%3}, {%4,%5,%6,%7}, {%8,%9}, {%0,%1,%2,%3};\n"
        : "+f"(c[0]), "+f"(c[1]), "+f"(c[2]), "+f"(c[3])
        : "r"(a[0]), "r"(a[1]), "r"(a[2]), "r"(a[3]), "r"(b[0]), "r"(b[1]));
}
__device__ __forceinline__ void mma_f16(float c[4], const uint32_t a[4], const uint32_t b[2]) {
    asm volatile(
        "mma.sync.aligned.m16n8k16.row.col.f32.f16.f16.f32 "
        "{%0,%1,%2,%3}, {%4,%5,%6,%7}, {%8,%9}, {%0,%1,%2,%3};\n"
        : "+f"(c[0]), "+f"(c[1]), "+f"(c[2]), "+f"(c[3])
        : "r"(a[0]), "r"(a[1]), "r"(a[2]), "r"(a[3]), "r"(b[0]), "r"(b[1]));
}
__device__ __forceinline__ void cp16(uint32_t dst, const void* src, bool v) {
    int sz = v ? 16 : 0;
    asm volatile("cp.async.cg.shared.global [%0], [%1], 16, %2;"
                 :: "r"(dst), "l"(src), "r"(sz));
}
#define CP_COMMIT()  asm volatile("cp.async.commit_group;" ::: "memory")
#define CP_WAIT(n)   asm volatile("cp.async.wait_group %0;" :: "n"(n) : "memory")

// ---------------- fp16 weight packing (vectorized, 4 outputs/thread) -------------
__global__ void packh(const float* __restrict__ in, uint32_t* __restrict__ out,
                      int K, int N, int total4) {
    int idx = blockIdx.x*blockDim.x + threadIdx.x;   // over total/4
    if (idx >= total4) return;
    int K2 = K >> 1, N4 = N >> 2;
    int n4 = idx % N4;
    int k2 = (idx / N4) % K2;
    int l  = idx / (N4 * K2);
    const float* src = in + ((size_t)l*K + 2*k2)*N + n4*4;
    float4 r0 = *(const float4*)src;
    float4 r1 = *(const float4*)(src + N);
    uint4 o;
    o.x = packh2(r0.x, r1.x); o.y = packh2(r0.y, r1.y);
    o.z = packh2(r0.z, r1.z); o.w = packh2(r0.w, r1.w);
    *(uint4*)(out + (size_t)idx*4) = o;
}
__global__ void pack_qkvh(const float* __restrict__ Wq,
                          const float* __restrict__ Wk,
                          const float* __restrict__ Wv,
                          uint32_t* __restrict__ out) {
    int idx = blockIdx.x*blockDim.x + threadIdx.x;   // 4*256*384
    if (idx >= 4*256*384) return;
    int n4 = idx % 384;
    int t  = idx / 384;         // l*256 + k2
    int k2 = t & 255;
    int l  = t >> 8;
    int n  = n4 * 4;
    const float* src = (n < 512) ? Wq : (n < 1024) ? Wk : Wv;
    int nn = n & 511;
    size_t base = ((size_t)l*512 + 2*k2)*512 + nn;
    float4 r0 = *(const float4*)(src + base);
    float4 r1 = *(const float4*)(src + base + 512);
    uint4 o;
    o.x = packh2(r0.x, r1.x); o.y = packh2(r0.y, r1.y);
    o.z = packh2(r0.z, r1.z); o.w = packh2(r0.w, r1.w);
    *(uint4*)(out + (size_t)idx*4) = o;
}

// ---------------- FP16 mma.sync GEMM, 4-stage cp.async pipeline -----------------
// BM=BN=128, BK=32 halfs; 256 thr = 8 warps (4M x 2N), warp 32x64.
// A smem m-major [m][k2] stride 20 (conflict-free); B smem [k2][n] stride 136.
// Stage = A(128*20) + B(16*136) uint32 = 4736 u32 = 18944 B; 4 stages = 75776 B.
#define HG_STG   4736
#define HG_ASZ   2560
#define HG_SMEM  (4*HG_STG*4)
template<int ACT, int OUTH>
__global__ __launch_bounds__(256)
void hgemm_kernel(const uint32_t* __restrict__ A32, const uint32_t* __restrict__ Bw,
                  const float* __restrict__ bias, void* __restrict__ Cv,
                  int M, int N, int K) {
    extern __shared__ uint32_t sm[];
    uint32_t smbase;
    asm("{ .reg .u64 t; cvta.to.shared.u64 t, %1; cvt.u32.u64 %0, t; }"
        : "=r"(smbase) : "l"(sm));
    int tid = threadIdx.x;
    int bx = blockIdx.x, by = blockIdx.y;
    int w = tid >> 5, lane = tid & 31;
    int wm = w & 3, wn = w >> 2;
    int g = lane >> 2, t4 = lane & 3;
    int K2 = K >> 1;

    float c[2][8][4];
    #pragma unroll
    for (int mt = 0; mt < 2; mt++)
        #pragma unroll
        for (int nt = 0; nt < 8; nt++)
            #pragma unroll
            for (int r = 0; r < 4; r++) c[mt][nt][r] = 0.f;

    // A loader: rows am, am+64; 16B (4 uint32 = 8 k) at k2 offset aq
    int am = tid >> 2;            // 0..63
    int aq = (tid & 3) * 4;       // 0,4,8,12
    int arow0 = by*128 + am, arow1 = arow0 + 64;
    bool v0 = (arow0 < M), v1 = (arow1 < M);
    const uint32_t* Ap0 = A32 + (size_t)(v0 ? arow0 : 0) * K2 + aq;
    const uint32_t* Ap1 = A32 + (size_t)(v1 ? arow1 : 0) * K2 + aq;

    // B loader: k2-row br, two 16B chunks at bu, bu+64
    int br = tid >> 4;            // 0..15
    int bu = (tid & 15) * 4;      // 0..60
    const uint32_t* Bp = Bw + (size_t)br * N + bx*128 + bu;

    uint32_t adst0 = smbase + (am*20 + aq)*4;
    uint32_t adst1 = smbase + ((am+64)*20 + aq)*4;
    uint32_t bdst0 = smbase + (HG_ASZ + br*136 + bu)*4;
    uint32_t bdst1 = bdst0 + 64*4;
    const uint32_t STGB = HG_STG*4;

    int nk = K2 >> 4;

    #define HG_ISSUE(T_) do { \
        int _t = (T_); \
        if (_t < nk) { \
            uint32_t off = (uint32_t)(_t & 3) * STGB; \
            cp16(adst0 + off, Ap0 + _t*16, v0); \
            cp16(adst1 + off, Ap1 + _t*16, v1); \
            cp16(bdst0 + off, Bp + (size_t)(_t*16)*N, true); \
            cp16(bdst1 + off, Bp + (size_t)(_t*16)*N + 64, true); \
        } \
        CP_COMMIT(); \
    } while (0)

    HG_ISSUE(0); HG_ISSUE(1); HG_ISSUE(2);

    int mb = wm*32 + g;
    int nb = wn*64 + g;
    for (int t = 0; t < nk; t++) {
        CP_WAIT(2);
        __syncthreads();
        HG_ISSUE(t + 3);
        const uint32_t* Sa = sm + (t & 3)*HG_STG;
        const uint32_t* Sb = Sa + HG_ASZ;
        #pragma unroll
        for (int ks = 0; ks < 16; ks += 8) {
            uint32_t af[2][4], bf[8][2];
            #pragma unroll
            for (int mt = 0; mt < 2; mt++) {
                int mrow = mb + mt*16;
                af[mt][0] = Sa[(mrow  )*20 + ks+t4  ];
                af[mt][1] = Sa[(mrow+8)*20 + ks+t4  ];
                af[mt][2] = Sa[(mrow  )*20 + ks+t4+4];
                af[mt][3] = Sa[(mrow+8)*20 + ks+t4+4];
            }
            #pragma unroll
            for (int nt = 0; nt < 8; nt++) {
                bf[nt][0] = Sb[(ks+t4  )*136 + nb + nt*8];
                bf[nt][1] = Sb[(ks+t4+4)*136 + nb + nt*8];
            }
            #pragma unroll
            for (int mt = 0; mt < 2; mt++)
                #pragma unroll
                for (int nt = 0; nt < 8; nt++)
                    mma_f16(c[mt][nt], af[mt], bf[nt]);
        }
    }
    #undef HG_ISSUE

    // epilogue
    #pragma unroll
    for (int mt = 0; mt < 2; mt++) {
        int row0 = by*128 + wm*32 + mt*16 + g;
        int row1 = row0 + 8;
        #pragma unroll
        for (int nt = 0; nt < 8; nt++) {
            int col = bx*128 + wn*64 + nt*8 + 2*t4;
            float x0 = c[mt][nt][0], x1 = c[mt][nt][1];
            float y0 = c[mt][nt][2], y1 = c[mt][nt][3];
            if (bias) {
                float bx0 = bias[col], bx1 = bias[col+1];
                x0 += bx0; x1 += bx1; y0 += bx0; y1 += bx1;
            }
            if (ACT == 1) {
                x0 = gelu_exact(x0); x1 = gelu_exact(x1);
                y0 = gelu_exact(y0); y1 = gelu_exact(y1);
            }
            if (OUTH) {
                uint32_t* Ch = (uint32_t*)Cv;
                if (row0 < M) Ch[((size_t)row0*N + col) >> 1] = packh2(x0, x1);
                if (row1 < M) Ch[((size_t)row1*N + col) >> 1] = packh2(y0, y1);
            } else {
                float* Cf = (float*)Cv;
                if (row0 < M) { float2 v; v.x = x0; v.y = x1; *(float2*)&Cf[(size_t)row0*N + col] = v; }
                if (row1 < M) { float2 v; v.x = y0; v.y = y1; *(float2*)&Cf[(size_t)row1*N + col] = v; }
            }
        }
    }
}

// ---------------- TF32 mma.sync GEMM (down/up projections) ----------------------
template<int ACT>
__global__ __launch_bounds__(256)
void tgemm_kernel(const float* __restrict__ A, const float* __restrict__ Bm,
                  const float* __restrict__ bias, float* __restrict__ C,
                  int M, int N, int K) {
    __shared__ uint32_t As[2][16][136];
    __shared__ uint32_t Bs[2][16][136];
    int tid = threadIdx.x;
    int bx = blockIdx.x, by = blockIdx.y;
    int w = tid >> 5, lane = tid & 31;
    int wm = w & 3, wn = w >> 2;
    int g = lane >> 2, t4 = lane & 3;

    float c[2][8][4];
    #pragma unroll
    for (int mt = 0; mt < 2; mt++)
        #pragma unroll
        for (int nt = 0; nt < 8; nt++)
            #pragma unroll
            for (int r = 0; r < 4; r++) c[mt][nt][r] = 0.f;

    int am = tid >> 2;
    int ak = (tid & 3) * 4;
    int arow0 = by*128 + am;
    int arow1 = arow0 + 64;
    const float* Ap0 = A + (size_t)arow0 * K + ak;
    const float* Ap1 = A + (size_t)arow1 * K + ak;
    bool v0 = (arow0 < M), v1 = (arow1 < M);

    int bk = tid >> 5;
    int bn = (tid & 31) * 4;
    const float* Bp = Bm + (size_t)bk * N + bx*128 + bn;

    int nk = K >> 4;
    float4 a0, a1, b0, b1;

    a0 = v0 ? *(const float4*)(Ap0) : make_float4(0,0,0,0);
    a1 = v1 ? *(const float4*)(Ap1) : make_float4(0,0,0,0);
    b0 = *(const float4*)(Bp);
    b1 = *(const float4*)(Bp + (size_t)8*N);
    As[0][ak+0][am] = f2tf(a0.x); As[0][ak+1][am] = f2tf(a0.y);
    As[0][ak+2][am] = f2tf(a0.z); As[0][ak+3][am] = f2tf(a0.w);
    As[0][ak+0][am+64] = f2tf(a1.x); As[0][ak+1][am+64] = f2tf(a1.y);
    As[0][ak+2][am+64] = f2tf(a1.z); As[0][ak+3][am+64] = f2tf(a1.w);
    Bs[0][bk][bn+0] = f2tf(b0.x); Bs[0][bk][bn+1] = f2tf(b0.y);
    Bs[0][bk][bn+2] = f2tf(b0.z); Bs[0][bk][bn+3] = f2tf(b0.w);
    Bs[0][bk+8][bn+0] = f2tf(b1.x); Bs[0][bk+8][bn+1] = f2tf(b1.y);
    Bs[0][bk+8][bn+2] = f2tf(b1.z); Bs[0][bk+8][bn+3] = f2tf(b1.w);
    __syncthreads();

    int mb = wm*32 + g;
    int nb = wn*64 + g;
    int buf = 0;
    for (int tile = 1; tile < nk; tile++) {
        const float* ap0 = Ap0 + tile*16;
        const float* ap1 = Ap1 + tile*16;
        const float* bp  = Bp + (size_t)(tile*16) * N;
        a0 = v0 ? *(const float4*)(ap0) : make_float4(0,0,0,0);
        a1 = v1 ? *(const float4*)(ap1) : make_float4(0,0,0,0);
        b0 = *(const float4*)(bp);
        b1 = *(const float4*)(bp + (size_t)8*N);

        #pragma unroll
        for (int ks = 0; ks < 16; ks += 8) {
            uint32_t af[2][4], bf[8][2];
            #pragma unroll
            for (int mt = 0; mt < 2; mt++) {
                af[mt][0] = As[buf][ks+t4  ][mb + mt*16];
                af[mt][1] = As[buf][ks+t4  ][mb + mt*16 + 8];
                af[mt][2] = As[buf][ks+t4+4][mb + mt*16];
                af[mt][3] = As[buf][ks+t4+4][mb + mt*16 + 8];
            }
            #pragma unroll
            for (int nt = 0; nt < 8; nt++) {
                bf[nt][0] = Bs[buf][ks+t4  ][nb + nt*8];
                bf[nt][1] = Bs[buf][ks+t4+4][nb + nt*8];
            }
            #pragma unroll
            for (int mt = 0; mt < 2; mt++)
                #pragma unroll
                for (int nt = 0; nt < 8; nt++)
                    mma_tf32(c[mt][nt], af[mt], bf[nt]);
        }

        int nbuf = buf ^ 1;
        As[nbuf][ak+0][am] = f2tf(a0.x); As[nbuf][ak+1][am] = f2tf(a0.y);
        As[nbuf][ak+2][am] = f2tf(a0.z); As[nbuf][ak+3][am] = f2tf(a0.w);
        As[nbuf][ak+0][am+64] = f2tf(a1.x); As[nbuf][ak+1][am+64] = f2tf(a1.y);
        As[nbuf][ak+2][am+64] = f2tf(a1.z); As[nbuf][ak+3][am+64] = f2tf(a1.w);
        Bs[nbuf][bk][bn+0] = f2tf(b0.x); Bs[nbuf][bk][bn+1] = f2tf(b0.y);
        Bs[nbuf][bk][bn+2] = f2tf(b0.z); Bs[nbuf][bk][bn+3] = f2tf(b0.w);
        Bs[nbuf][bk+8][bn+0] = f2tf(b1.x); Bs[nbuf][bk+8][bn+1] = f2tf(b1.y);
        Bs[nbuf][bk+8][bn+2] = f2tf(b1.z); Bs[nbuf][bk+8][bn+3] = f2tf(b1.w);
        __syncthreads();
        buf = nbuf;
    }

    #pragma unroll
    for (int ks = 0; ks < 16; ks += 8) {
        uint32_t af[2][4], bf[8][2];
        #pragma unroll
        for (int mt = 0; mt < 2; mt++) {
            af[mt][0] = As[buf][ks+t4  ][mb + mt*16];
            af[mt][1] = As[buf][ks+t4  ][mb + mt*16 + 8];
            af[mt][2] = As[buf][ks+t4+4][mb + mt*16];
            af[mt][3] = As[buf][ks+t4+4][mb + mt*16 + 8];
        }
        #pragma unroll
        for (int nt = 0; nt < 8; nt++) {
            bf[nt][0] = Bs[buf][ks+t4  ][nb + nt*8];
            bf[nt][1] = Bs[buf][ks+t4+4][nb + nt*8];
        }
        #pragma unroll
        for (int mt = 0; mt < 2; mt++)
            #pragma unroll
            for (int nt = 0; nt < 8; nt++)
                mma_tf32(c[mt][nt], af[mt], bf[nt]);
    }

    #pragma unroll
    for (int mt = 0; mt < 2; mt++) {
        int row0 = by*128 + wm*32 + mt*16 + g;
        int row1 = row0 + 8;
        #pragma unroll
        for (int nt = 0; nt < 8; nt++) {
            int col = bx*128 + wn*64 + nt*8 + 2*t4;
            float2 v0o, v1o;
            v0o.x = c[mt][nt][0]; v0o.y = c[mt][nt][1];
            v1o.x = c[mt][nt][2]; v1o.y = c[mt][nt][3];
            if (bias) {
                float bx0 = bias[col], bx1 = bias[col+1];
                v0o.x += bx0; v0o.y += bx1; v1o.x += bx0; v1o.y += bx1;
            }
            if (ACT == 1) {
                v0o.x = gelu_exact(v0o.x); v0o.y = gelu_exact(v0o.y);
                v1o.x = gelu_exact(v1o.x); v1o.y = gelu_exact(v1o.y);
            }
            if (row0 < M) *(float2*)&C[(size_t)row0*N + col] = v0o;
            if (row1 < M) *(float2*)&C[(size_t)row1*N + col] = v1o;
        }
    }
}

// ---------------- embedding ----------------
__global__ void embed_kernel(const float* __restrict__ x_enc,
                             const float* __restrict__ xme,
                             const float* __restrict__ xmd,
                             const float* __restrict__ tw,
                             const float* __restrict__ tb,
                             const float* __restrict__ tempw,
                             const float* __restrict__ tempb) {
    int t = blockIdx.x, b = blockIdx.y;
    __shared__ float xv[3][7];
    __shared__ float xm[4];
    int tid = threadIdx.x;   // 128
    if (tid < 21) {
        int k = tid / 7, i = tid % 7;
        int r = t - 1 + k;
        int rr = (r + 1025) % 1025;
        float val = 0.f;
        if (rr < 1024) val = x_enc[((size_t)b*1024 + rr)*7 + i];
        xv[k][i] = val;
    }
    if (tid >= 32 && tid < 36) {
        int m = tid - 32;
        xm[m] = (t < 1024) ? xme[((size_t)b*1024 + t)*4 + m]
                           : xmd[((size_t)b*96)*4 + m];
    }
    __syncthreads();
    for (int d = tid; d < DD; d += 128) {
        float acc = tb[d];
        #pragma unroll
        for (int i = 0; i < 7; i++)
            #pragma unroll
            for (int k = 0; k < 3; k++)
                acc += xv[k][i] * tw[(d*7 + i)*3 + k];
        acc += tempb[d];
        #pragma unroll
        for (int m = 0; m < 4; m++) acc += xm[m] * tempw[m*DD + d];
        int m2 = d & ~1;
        float div = expf(-9.210340371976184f / 512.0f * (float)m2);
        float arg = (float)t * div;
        acc += (d & 1) ? cosf(arg) : sinf(arg);
        g_emb[((size_t)b*LL + t)*DD + d] = acc;
    }
}

// ---------------- conv (stride-4, kernel-4, ELU): 8 outputs per block ----------
__global__ void conv_kernel(const float* __restrict__ in, int ibs, int inOff,
                            const float* __restrict__ w, const float* __restrict__ bias,
                            float* __restrict__ out, int outOff) {
    int t0 = blockIdx.x * 8, b = blockIdx.y;
    int tid = threadIdx.x;   // 128 (= oc)
    __shared__ float si[8*512];
    const float* ip = in + (size_t)(b*ibs + inOff + 4*t0) * 128;
    #pragma unroll
    for (int i = 0; i < 32; i++) si[i*128 + tid] = ip[i*128 + tid];
    __syncthreads();
    float bv = bias[tid];
    float acc[8];
    #pragma unroll
    for (int t = 0; t < 8; t++) acc[t] = bv;
    #pragma unroll 2
    for (int ic = 0; ic < 128; ic++) {
        float4 w4 = *(const float4*)&w[((size_t)tid*128 + ic)*4];
        #pragma unroll
        for (int t = 0; t < 8; t++) {
            const float* s = si + t*512;
            acc[t] += s[ic]*w4.x + s[128+ic]*w4.y + s[256+ic]*w4.z + s[384+ic]*w4.w;
        }
    }
    #pragma unroll
    for (int t = 0; t < 8; t++) {
        float a = acc[t];
        a = (a > 0.f) ? a : expm1f(a);
        out[(size_t)(b*336 + outOff + t0 + t)*128 + tid] = a;
    }
}

// ---------------- layernorm (512 wide, 256 threads) + half copy ----------------
__device__ __forceinline__ void ln_core(const float* __restrict__ x0,
                                        const float* __restrict__ x1,
                                        const float* __restrict__ sc,
                                        const float* __restrict__ bb,
                                        float* __restrict__ out,
                                        __half* __restrict__ out_h) {
    __shared__ float red[8];
    int tid = threadIdx.x;
    float v0 = x0[tid]       + (x1 ? x1[tid]       : 0.f);
    float v1 = x0[tid + 256] + (x1 ? x1[tid + 256] : 0.f);
    float sum = v0 + v1;
    #pragma unroll
    for (int o = 16; o; o >>= 1) sum += __shfl_xor_sync(0xffffffffu, sum, o);
    if ((tid & 31) == 0) red[tid >> 5] = sum;
    __syncthreads();
    float tot = 0.f;
    #pragma unroll
    for (int w = 0; w < 8; w++) tot += red[w];
    float mean = tot * (1.0f/512.0f);
    __syncthreads();
    float d0 = v0 - mean, d1 = v1 - mean;
    float sq = d0*d0 + d1*d1;
    #pragma unroll
    for (int o = 16; o; o >>= 1) sq += __shfl_xor_sync(0xffffffffu, sq, o);
    if ((tid & 31) == 0) red[tid >> 5] = sq;
    __syncthreads();
    float vtot = 0.f;
    #pragma unroll
    for (int w = 0; w < 8; w++) vtot += red[w];
    float inv = rsqrtf(vtot * (1.0f/512.0f) + 1e-5f);
    float o0 = d0 * inv * sc[tid]       + bb[tid];
    float o1 = d1 * inv * sc[tid + 256] + bb[tid + 256];
    out[tid]       = o0;
    out[tid + 256] = o1;
    out_h[tid]       = __float2half_rn(o0);
    out_h[tid + 256] = __float2half_rn(o1);
}

__global__ void concat_ln_kernel(const float* __restrict__ sc, const float* __restrict__ bb) {
    int row = blockIdx.x;
    int b = row / NT, n = row % NT;
    const float* src = (n < LL) ? &g_emb[((size_t)b*LL + n)*DD]
                                : &g_pyr[((size_t)b*336 + (n - LL))*DD];
    ln_core(src, nullptr, sc, bb, &g_seq[(size_t)row*DD],
            (__half*)g_seqr_h + (size_t)row*DD);
}

__global__ void add_ln_kernel(const float* __restrict__ sc, const float* __restrict__ bb) {
    size_t row = blockIdx.x;
    ln_core(&g_seq[row*DD], &g_tmp[row*DD], sc, bb, &g_seq[row*DD],
            (__half*)g_seqr_h + row*DD);
}

// ---------------- fused sparse attention (fp32 qkv in, half out) ---------------
#define MAXN 12
__global__ __launch_bounds__(256)
void attn_kernel() {
    int i = blockIdx.x, b = blockIdx.y;
    __shared__ int s_nbr[MAXN];
    __shared__ int s_nn;
    int tid = threadIdx.x;
    if (tid == 0) {
        const int starts[5] = {0, 1025, 1281, 1345, 1361};
        int li = (i < 1025) ? 0 : (i < 1281) ? 1 : (i < 1345) ? 2 : 3;
        int s = starts[li], e = starts[li+1];
        int nn = 0;
        int jlo = (i - 2 > s) ? i - 2 : s;
        int jhi = (i + 2 < e - 1) ? i + 2 : e - 1;
        for (int j = jlo; j <= jhi; j++) s_nbr[nn++] = j;
        if (li > 0) {
            int ps = starts[li-1];
            int qq = i - s;
            int lo = ps + qq * 4;
            int hi = (i == e - 1) ? s : ps + (qq + 1) * 4;
            for (int j = lo; j < hi; j++) s_nbr[nn++] = j;
        }
        if (li < 3) {
            int su = starts[li+1];
            int szu = starts[li+2] - su;
            int qq = (i - s) / 4;
            s_nbr[nn++] = su + ((qq < szu - 1) ? qq : szu - 1);
        }
        s_nn = nn;
        for (int j = nn; j < MAXN; j++) s_nbr[j] = i;
    }
    __syncthreads();
    int nn = s_nn;
    int h = tid >> 5, lane = tid & 31;
    size_t qbase = ((size_t)b*NT + i)*1536 + h*64;
    float q0 = g_qkv[qbase + lane];
    float q1 = g_qkv[qbase + lane + 32];

    float dots[MAXN];
    #pragma unroll
    for (int jj = 0; jj < MAXN; jj++) {
        size_t kb = ((size_t)b*NT + s_nbr[jj])*1536 + 512 + h*64;
        float p = q0 * g_qkv[kb + lane] + q1 * g_qkv[kb + lane + 32];
        #pragma unroll
        for (int o = 16; o; o >>= 1) p += __shfl_xor_sync(0xffffffffu, p, o);
        dots[jj] = (jj < nn) ? p * 0.125f : -1e30f;
    }
    float mx = -1e30f;
    #pragma unroll
    for (int jj = 0; jj < MAXN; jj++) mx = fmaxf(mx, dots[jj]);
    float sum = 0.f;
    #pragma unroll
    for (int jj = 0; jj < MAXN; jj++) { dots[jj] = expf(dots[jj] - mx); sum += dots[jj]; }
    float inv = 1.f / sum;
    float o0 = 0.f, o1 = 0.f;
    #pragma unroll
    for (int jj = 0; jj < MAXN; jj++) {
        size_t vb = ((size_t)b*NT + s_nbr[jj])*1536 + 1024 + h*64;
        float w = dots[jj] * inv;
        o0 += w * g_qkv[vb + lane];
        o1 += w * g_qkv[vb + lane + 32];
    }
    size_t obase = ((size_t)b*NT + i)*DD + h*64;
    __half* oh = (__half*)g_o_h;
    oh[obase + lane]      = __float2half_rn(o0);
    oh[obase + lane + 32] = __float2half_rn(o1);
}

// ---------------- gather + prediction head (split-r partials + reduce) ---------
__global__ void pred_part(const float* __restrict__ pw) {
    int b = blockIdx.x, ch = blockIdx.y;   // 8 chunks of 256 rows
    __shared__ float gv[256];
    const int rows[4] = {1024, 1280, 1344, 1360};
    int tid = threadIdx.x;   // 672
    if (tid < 256) {
        int r = ch*256 + tid;
        int wch = r >> 9, d = r & 511;
        gv[tid] = g_seq[((size_t)b*NT + rows[wch])*DD + d];
    }
    __syncthreads();
    float acc = 0.f;
    const float* p = pw + (size_t)(ch*256)*672 + tid;
    #pragma unroll 8
    for (int j = 0; j < 256; j++) acc += gv[j] * p[(size_t)j*672];
    g_predp[(b*8 + ch)*672 + tid] = acc;
}
__global__ void pred_reduce(float* __restrict__ out) {
    int idx = blockIdx.x*blockDim.x + threadIdx.x;   // BB*672
    if (idx >= BB*672) return;
    int b = idx / 672, c = idx % 672;
    float s = 0.f;
    #pragma unroll
    for (int ch = 0; ch < 8; ch++) s += g_predp[(b*8 + ch)*672 + c];
    out[idx] = s;
}

// ---------------- host ----------------
static void launch_tf32(const float* A, const float* Bm, const float* bias,
                        float* C, int M, int N, int K) {
    dim3 grid(N / 128, (M + 127) / 128);
    tgemm_kernel<0><<<grid, 256>>>(A, Bm, bias, C, M, N, K);
}

extern "C" void kernel_launch(void* const* d_in, const int* in_sizes, int n_in,
                              void* d_out, int out_size) {
    const float* x_enc   = (const float*)d_in[0];
    const float* xme     = (const float*)d_in[1];
    // d_in[2] = x_dec (unused by the model math)
    const float* xmd     = (const float*)d_in[3];
    const float* token_w = (const float*)d_in[4];
    const float* token_b = (const float*)d_in[5];
    const float* temp_w  = (const float*)d_in[6];
    const float* temp_b  = (const float*)d_in[7];
    const float* down_w  = (const float*)d_in[8];
    const float* down_b  = (const float*)d_in[9];
    const float* conv_w  = (const float*)d_in[10];
    const float* conv_b  = (const float*)d_in[11];
    const float* up_w    = (const float*)d_in[12];
    const float* up_b    = (const float*)d_in[13];
    const float* cln_s   = (const float*)d_in[14];
    const float* cln_b   = (const float*)d_in[15];
    const float* Wq      = (const float*)d_in[16];
    const float* Wk      = (const float*)d_in[17];
    const float* Wv      = (const float*)d_in[18];
    const float* Wo      = (const float*)d_in[19];
    const float* bo      = (const float*)d_in[20];
    const float* ln1_s   = (const float*)d_in[21];
    const float* ln1_b   = (const float*)d_in[22];
    const float* W1      = (const float*)d_in[23];
    const float* b1      = (const float*)d_in[24];
    const float* W2      = (const float*)d_in[25];
    const float* b2      = (const float*)d_in[26];
    const float* ln2_s   = (const float*)d_in[27];
    const float* ln2_b   = (const float*)d_in[28];
    const float* pred_w  = (const float*)d_in[29];

    float *emb, *d0, *cc, *pyr, *seq, *qkv, *tmp;
    uint32_t *seqr_h, *o_h, *ffn_h, *wqkvh, *woh, *w1h, *w2h;
    cudaGetSymbolAddress((void**)&emb,  g_emb);
    cudaGetSymbolAddress((void**)&d0,   g_d0);
    cudaGetSymbolAddress((void**)&cc,   g_cc);
    cudaGetSymbolAddress((void**)&pyr,  g_pyr);
    cudaGetSymbolAddress((void**)&seq,  g_seq);
    cudaGetSymbolAddress((void**)&qkv,  g_qkv);
    cudaGetSymbolAddress((void**)&tmp,  g_tmp);
    cudaGetSymbolAddress((void**)&seqr_h, g_seqr_h);
    cudaGetSymbolAddress((void**)&o_h,    g_o_h);
    cudaGetSymbolAddress((void**)&ffn_h,  g_ffn_h);
    cudaGetSymbolAddress((void**)&wqkvh,  g_wqkvh);
    cudaGetSymbolAddress((void**)&woh,    g_woh);
    cudaGetSymbolAddress((void**)&w1h,    g_w1h);
    cudaGetSymbolAddress((void**)&w2h,    g_w2h);

    cudaFuncSetAttribute(hgemm_kernel<0,0>, cudaFuncAttributeMaxDynamicSharedMemorySize, HG_SMEM);
    cudaFuncSetAttribute(hgemm_kernel<1,1>, cudaFuncAttributeMaxDynamicSharedMemorySize, HG_SMEM);

    // 0) pack all encoder weights to fp16 pair layout [K/2][N] (vectorized)
    pack_qkvh<<<(4*256*384 + 255)/256, 256>>>(Wq, Wk, Wv, wqkvh);
    packh<<<(4*256*128 + 255)/256, 256>>>(Wo, woh, 512, 512, 4*256*128);
    packh<<<(4*256*512 + 255)/256, 256>>>(W1, w1h, 512, 2048, 4*256*512);
    packh<<<(4*1024*128 + 255)/256, 256>>>(W2, w2h, 2048, 512, 4*1024*128);

    // 1) embedding
    embed_kernel<<<dim3(LL, BB), 128>>>(x_enc, xme, xmd, token_w, token_b, temp_w, temp_b);

    // 2) bottleneck down-projection (tf32 path)
    launch_tf32(emb, down_w, down_b, d0, BB*LL, 128, DD);

    // 3) pyramid convs (8 outputs per block)
    conv_kernel<<<dim3(32, BB), 128>>>(d0, LL, 0,   conv_w,               conv_b,       cc, 0);
    conv_kernel<<<dim3(8,  BB), 128>>>(cc, 336, 0,  conv_w + 128*128*4,   conv_b + 128, cc, 256);
    conv_kernel<<<dim3(2,  BB), 128>>>(cc, 336, 256,conv_w + 2*128*128*4, conv_b + 256, cc, 320);

    // 4) up-projection (tf32 path)
    launch_tf32(cc, up_w, up_b, pyr, BB*336, DD, 128);

    // 5) concat + LayerNorm -> seq (+ half copy)
    concat_ln_kernel<<<MROWS, 256>>>(cln_s, cln_b);

    // 6) encoder layers (fp16 GEMMs, cp.async 4-stage)
    const int MT = (MROWS + 127) / 128;   // 43
    for (int i = 0; i < 4; i++) {
        hgemm_kernel<0,0><<<dim3(12, MT), 256, HG_SMEM>>>(
            seqr_h, wqkvh + (size_t)i*256*1536, nullptr, qkv, MROWS, 1536, 512);

        attn_kernel<<<dim3(NT, BB), 256>>>();

        hgemm_kernel<0,0><<<dim3(4, MT), 256, HG_SMEM>>>(
            o_h, woh + (size_t)i*256*512, bo + i*DD, tmp, MROWS, 512, 512);
        add_ln_kernel<<<MROWS, 256>>>(ln1_s + i*DD, ln1_b + i*DD);

        hgemm_kernel<1,1><<<dim3(16, MT), 256, HG_SMEM>>>(
            seqr_h, w1h + (size_t)i*256*2048, b1 + i*DFF, ffn_h, MROWS, 2048, 512);
        hgemm_kernel<0,0><<<dim3(4, MT), 256, HG_SMEM>>>(
            ffn_h, w2h + (size_t)i*1024*512, b2 + i*DD, tmp, MROWS, 512, 2048);
        add_ln_kernel<<<MROWS, 256>>>(ln2_s + i*DD, ln2_b + i*DD);
    }

    // 7) gather + prediction head (split partials, deterministic reduce)
    pred_part<<<dim3(BB, 8), 672>>>(pred_w);
    pred_reduce<<<(BB*672 + 255)/256, 256>>>((float*)d_out);
}

// round 14
// speedup vs baseline: 2.1166x; 1.0073x over previous
#include <cuda_runtime.h>
#include <cuda_fp16.h>
#include <math.h>
#include <stdint.h>

#define BB 4
#define LL 1025
#define NT 1361
#define DD 512
#define HH 8
#define DFF 2048
#define MROWS (BB*NT)         // 5444

// ---------------- scratch (static device allocations) ----------------
__device__ float g_emb [BB*LL*DD];
__device__ float g_d0  [BB*LL*128];
__device__ float g_cc  [BB*336*128];
__device__ float g_pyr [BB*336*DD];
__device__ float g_seq [BB*NT*DD];
__device__ float g_tmp [BB*NT*DD];
__device__ float g_predp[BB*8*672];
// fp16 activations (uint4 arrays => 16B alignment guaranteed)
__device__ uint4 g_seqr_h[MROWS*DD/8];     // half copy of seq (GEMM A)
__device__ uint4 g_qkv_h [MROWS*1536/8];   // QKV output (half)
__device__ uint4 g_o_h   [MROWS*DD/8];     // attention output (half)
__device__ uint4 g_ffn_h [MROWS*DFF/8];    // W1+gelu output (half)
// fp16 weight packs: uint32 pairs, layout [K/2][N] per layer
__device__ uint4 g_wqkvh[4*256*1536/4];
__device__ uint4 g_woh  [4*256*512/4];
__device__ uint4 g_w1h  [4*256*2048/4];
__device__ uint4 g_w2h  [4*1024*512/4];

// ---------------- helpers ----------------
__device__ __forceinline__ uint32_t f2tf(float x) {
    uint32_t r;
    asm("cvt.rna.tf32.f32 %0, %1;" : "=r"(r) : "f"(x));
    return r;
}
__device__ __forceinline__ float gelu_exact(float x) {
    return 0.5f * x * (1.0f + erff(x * 0.70710678118654752f));
}
__device__ __forceinline__ uint32_t packh2(float a, float b) {
    __half2 h = __halves2half2(__float2half_rn(a), __float2half_rn(b));
    return *(uint32_t*)&h;
}
__device__ __forceinline__ void mma_tf32(float c[4], const uint32_t a[4], const uint32_t b[2]) {
    asm volatile(
        "mma.sync.aligned.m16n8k8.row.col.f32.tf32.tf32.f32 "
        "{%0,%1,%2,%3}, {%4,%5,%6,%7}, {%8,%9}, {%0,%1,%2,%3};\n"
        : "+f"(c[0]), "+f"(c[1]), "+f"(c[2]), "+f"(c[3])
        : "r"(a[0]), "r"(a[1]), "r"(a[2]), "r"(a[3]), "r"(b[0]), "r"(b[1]));
}
__device__ __forceinline__ void mma_f16(float c[4], const uint32_t a[4], const uint32_t b[2]) {
    asm volatile(
        "mma.sync.aligned.m16n8k16.row.col.f32.f16.f16.f32 "
        "{%0,%1,%2,%3}, {%4,%5,%6,%7}, {%8,%9}, {%0,%1,%2,%3};\n"
        : "+f"(c[0]), "+f"(c[1]), "+f"(c[2]), "+f"(c[3])
        : "r"(a[0]), "r"(a[1]), "r"(a[2]), "r"(a[3]), "r"(b[0]), "r"(b[1]));
}
__device__ __forceinline__ void cp16(uint32_t dst, const void* src, bool v) {
    int sz = v ? 16 : 0;
    asm volatile("cp.async.cg.shared.global [%0], [%1], 16, %2;"
                 :: "r"(dst), "l"(src), "r"(sz));
}
#define CP_COMMIT()  asm volatile("cp.async.commit_group;" ::: "memory")
#define CP_WAIT(n)   asm volatile("cp.async.wait_group %0;" :: "n"(n) : "memory")

// ---------------- fp16 weight packing (vectorized, 4 outputs/thread) -------------
__global__ void packh(const float* __restrict__ in, uint32_t* __restrict__ out,
                      int K, int N, int total4) {
    int idx = blockIdx.x*blockDim.x + threadIdx.x;   // over total/4
    if (idx >= total4) return;
    int K2 = K >> 1, N4 = N >> 2;
    int n4 = idx % N4;
    int k2 = (idx / N4) % K2;
    int l  = idx / (N4 * K2);
    const float* src = in + ((size_t)l*K + 2*k2)*N + n4*4;
    float4 r0 = *(const float4*)src;
    float4 r1 = *(const float4*)(src + N);
    uint4 o;
    o.x = packh2(r0.x, r1.x); o.y = packh2(r0.y, r1.y);
    o.z = packh2(r0.z, r1.z); o.w = packh2(r0.w, r1.w);
    *(uint4*)(out + (size_t)idx*4) = o;
}
__global__ void pack_qkvh(const float* __restrict__ Wq,
                          const float* __restrict__ Wk,
                          const float* __restrict__ Wv,
                          uint32_t* __restrict__ out) {
    int idx = blockIdx.x*blockDim.x + threadIdx.x;   // 4*256*384
    if (idx >= 4*256*384) return;
    int n4 = idx % 384;
    int t  = idx / 384;         // l*256 + k2
    int k2 = t & 255;
    int l  = t >> 8;
    int n  = n4 * 4;
    const float* src = (n < 512) ? Wq : (n < 1024) ? Wk : Wv;
    int nn = n & 511;
    size_t base = ((size_t)l*512 + 2*k2)*512 + nn;
    float4 r0 = *(const float4*)(src + base);
    float4 r1 = *(const float4*)(src + base + 512);
    uint4 o;
    o.x = packh2(r0.x, r1.x); o.y = packh2(r0.y, r1.y);
    o.z = packh2(r0.z, r1.z); o.w = packh2(r0.w, r1.w);
    *(uint4*)(out + (size_t)idx*4) = o;
}

// ---------------- FP16 mma.sync GEMM, 4-stage cp.async pipeline -----------------
// BM=BN=128, BK=32 halfs; 256 thr = 8 warps (4M x 2N), warp 32x64.
// A smem m-major [m][k2] stride 20 (conflict-free); B smem [k2][n] stride 136.
#define HG_STG   4736
#define HG_ASZ   2560
#define HG_SMEM  (4*HG_STG*4)
template<int ACT, int OUTH>
__global__ __launch_bounds__(256)
void hgemm_kernel(const uint32_t* __restrict__ A32, const uint32_t* __restrict__ Bw,
                  const float* __restrict__ bias, void* __restrict__ Cv,
                  int M, int N, int K) {
    extern __shared__ uint32_t sm[];
    uint32_t smbase;
    asm("{ .reg .u64 t; cvta.to.shared.u64 t, %1; cvt.u32.u64 %0, t; }"
        : "=r"(smbase) : "l"(sm));
    int tid = threadIdx.x;
    int bx = blockIdx.x, by = blockIdx.y;
    int w = tid >> 5, lane = tid & 31;
    int wm = w & 3, wn = w >> 2;
    int g = lane >> 2, t4 = lane & 3;
    int K2 = K >> 1;

    float c[2][8][4];
    #pragma unroll
    for (int mt = 0; mt < 2; mt++)
        #pragma unroll
        for (int nt = 0; nt < 8; nt++)
            #pragma unroll
            for (int r = 0; r < 4; r++) c[mt][nt][r] = 0.f;

    int am = tid >> 2;            // 0..63
    int aq = (tid & 3) * 4;       // 0,4,8,12
    int arow0 = by*128 + am, arow1 = arow0 + 64;
    bool v0 = (arow0 < M), v1 = (arow1 < M);
    const uint32_t* Ap0 = A32 + (size_t)(v0 ? arow0 : 0) * K2 + aq;
    const uint32_t* Ap1 = A32 + (size_t)(v1 ? arow1 : 0) * K2 + aq;

    int br = tid >> 4;            // 0..15
    int bu = (tid & 15) * 4;      // 0..60
    const uint32_t* Bp = Bw + (size_t)br * N + bx*128 + bu;

    uint32_t adst0 = smbase + (am*20 + aq)*4;
    uint32_t adst1 = smbase + ((am+64)*20 + aq)*4;
    uint32_t bdst0 = smbase + (HG_ASZ + br*136 + bu)*4;
    uint32_t bdst1 = bdst0 + 64*4;
    const uint32_t STGB = HG_STG*4;

    int nk = K2 >> 4;

    #define HG_ISSUE(T_) do { \
        int _t = (T_); \
        if (_t < nk) { \
            uint32_t off = (uint32_t)(_t & 3) * STGB; \
            cp16(adst0 + off, Ap0 + _t*16, v0); \
            cp16(adst1 + off, Ap1 + _t*16, v1); \
            cp16(bdst0 + off, Bp + (size_t)(_t*16)*N, true); \
            cp16(bdst1 + off, Bp + (size_t)(_t*16)*N + 64, true); \
        } \
        CP_COMMIT(); \
    } while (0)

    HG_ISSUE(0); HG_ISSUE(1); HG_ISSUE(2);

    int mb = wm*32 + g;
    int nb = wn*64 + g;
    for (int t = 0; t < nk; t++) {
        CP_WAIT(2);
        __syncthreads();
        HG_ISSUE(t + 3);
        const uint32_t* Sa = sm + (t & 3)*HG_STG;
        const uint32_t* Sb = Sa + HG_ASZ;
        #pragma unroll
        for (int ks = 0; ks < 16; ks += 8) {
            uint32_t af[2][4], bf[8][2];
            #pragma unroll
            for (int mt = 0; mt < 2; mt++) {
                int mrow = mb + mt*16;
                af[mt][0] = Sa[(mrow  )*20 + ks+t4  ];
                af[mt][1] = Sa[(mrow+8)*20 + ks+t4  ];
                af[mt][2] = Sa[(mrow  )*20 + ks+t4+4];
                af[mt][3] = Sa[(mrow+8)*20 + ks+t4+4];
            }
            #pragma unroll
            for (int nt = 0; nt < 8; nt++) {
                bf[nt][0] = Sb[(ks+t4  )*136 + nb + nt*8];
                bf[nt][1] = Sb[(ks+t4+4)*136 + nb + nt*8];
            }
            #pragma unroll
            for (int mt = 0; mt < 2; mt++)
                #pragma unroll
                for (int nt = 0; nt < 8; nt++)
                    mma_f16(c[mt][nt], af[mt], bf[nt]);
        }
    }
    #undef HG_ISSUE

    // epilogue
    #pragma unroll
    for (int mt = 0; mt < 2; mt++) {
        int row0 = by*128 + wm*32 + mt*16 + g;
        int row1 = row0 + 8;
        #pragma unroll
        for (int nt = 0; nt < 8; nt++) {
            int col = bx*128 + wn*64 + nt*8 + 2*t4;
            float x0 = c[mt][nt][0], x1 = c[mt][nt][1];
            float y0 = c[mt][nt][2], y1 = c[mt][nt][3];
            if (bias) {
                float bx0 = bias[col], bx1 = bias[col+1];
                x0 += bx0; x1 += bx1; y0 += bx0; y1 += bx1;
            }
            if (ACT == 1) {
                x0 = gelu_exact(x0); x1 = gelu_exact(x1);
                y0 = gelu_exact(y0); y1 = gelu_exact(y1);
            }
            if (OUTH) {
                uint32_t* Ch = (uint32_t*)Cv;
                if (row0 < M) Ch[((size_t)row0*N + col) >> 1] = packh2(x0, x1);
                if (row1 < M) Ch[((size_t)row1*N + col) >> 1] = packh2(y0, y1);
            } else {
                float* Cf = (float*)Cv;
                if (row0 < M) { float2 v; v.x = x0; v.y = x1; *(float2*)&Cf[(size_t)row0*N + col] = v; }
                if (row1 < M) { float2 v; v.x = y0; v.y = y1; *(float2*)&Cf[(size_t)row1*N + col] = v; }
            }
        }
    }
}

// ---------------- TF32 mma.sync GEMM (down/up projections) ----------------------
template<int ACT>
__global__ __launch_bounds__(256)
void tgemm_kernel(const float* __restrict__ A, const float* __restrict__ Bm,
                  const float* __restrict__ bias, float* __restrict__ C,
                  int M, int N, int K) {
    __shared__ uint32_t As[2][16][136];
    __shared__ uint32_t Bs[2][16][136];
    int tid = threadIdx.x;
    int bx = blockIdx.x, by = blockIdx.y;
    int w = tid >> 5, lane = tid & 31;
    int wm = w & 3, wn = w >> 2;
    int g = lane >> 2, t4 = lane & 3;

    float c[2][8][4];
    #pragma unroll
    for (int mt = 0; mt < 2; mt++)
        #pragma unroll
        for (int nt = 0; nt < 8; nt++)
            #pragma unroll
            for (int r = 0; r < 4; r++) c[mt][nt][r] = 0.f;

    int am = tid >> 2;
    int ak = (tid & 3) * 4;
    int arow0 = by*128 + am;
    int arow1 = arow0 + 64;
    const float* Ap0 = A + (size_t)arow0 * K + ak;
    const float* Ap1 = A + (size_t)arow1 * K + ak;
    bool v0 = (arow0 < M), v1 = (arow1 < M);

    int bk = tid >> 5;
    int bn = (tid & 31) * 4;
    const float* Bp = Bm + (size_t)bk * N + bx*128 + bn;

    int nk = K >> 4;
    float4 a0, a1, b0, b1;

    a0 = v0 ? *(const float4*)(Ap0) : make_float4(0,0,0,0);
    a1 = v1 ? *(const float4*)(Ap1) : make_float4(0,0,0,0);
    b0 = *(const float4*)(Bp);
    b1 = *(const float4*)(Bp + (size_t)8*N);
    As[0][ak+0][am] = f2tf(a0.x); As[0][ak+1][am] = f2tf(a0.y);
    As[0][ak+2][am] = f2tf(a0.z); As[0][ak+3][am] = f2tf(a0.w);
    As[0][ak+0][am+64] = f2tf(a1.x); As[0][ak+1][am+64] = f2tf(a1.y);
    As[0][ak+2][am+64] = f2tf(a1.z); As[0][ak+3][am+64] = f2tf(a1.w);
    Bs[0][bk][bn+0] = f2tf(b0.x); Bs[0][bk][bn+1] = f2tf(b0.y);
    Bs[0][bk][bn+2] = f2tf(b0.z); Bs[0][bk][bn+3] = f2tf(b0.w);
    Bs[0][bk+8][bn+0] = f2tf(b1.x); Bs[0][bk+8][bn+1] = f2tf(b1.y);
    Bs[0][bk+8][bn+2] = f2tf(b1.z); Bs[0][bk+8][bn+3] = f2tf(b1.w);
    __syncthreads();

    int mb = wm*32 + g;
    int nb = wn*64 + g;
    int buf = 0;
    for (int tile = 1; tile < nk; tile++) {
        const float* ap0 = Ap0 + tile*16;
        const float* ap1 = Ap1 + tile*16;
        const float* bp  = Bp + (size_t)(tile*16) * N;
        a0 = v0 ? *(const float4*)(ap0) : make_float4(0,0,0,0);
        a1 = v1 ? *(const float4*)(ap1) : make_float4(0,0,0,0);
        b0 = *(const float4*)(bp);
        b1 = *(const float4*)(bp + (size_t)8*N);

        #pragma unroll
        for (int ks = 0; ks < 16; ks += 8) {
            uint32_t af[2][4], bf[8][2];
            #pragma unroll
            for (int mt = 0; mt < 2; mt++) {
                af[mt][0] = As[buf][ks+t4  ][mb + mt*16];
                af[mt][1] = As[buf][ks+t4  ][mb + mt*16 + 8];
                af[mt][2] = As[buf][ks+t4+4][mb + mt*16];
                af[mt][3] = As[buf][ks+t4+4][mb + mt*16 + 8];
            }
            #pragma unroll
            for (int nt = 0; nt < 8; nt++) {
                bf[nt][0] = Bs[buf][ks+t4  ][nb + nt*8];
                bf[nt][1] = Bs[buf][ks+t4+4][nb + nt*8];
            }
            #pragma unroll
            for (int mt = 0; mt < 2; mt++)
                #pragma unroll
                for (int nt = 0; nt < 8; nt++)
                    mma_tf32(c[mt][nt], af[mt], bf[nt]);
        }

        int nbuf = buf ^ 1;
        As[nbuf][ak+0][am] = f2tf(a0.x); As[nbuf][ak+1][am] = f2tf(a0.y);
        As[nbuf][ak+2][am] = f2tf(a0.z); As[nbuf][ak+3][am] = f2tf(a0.w);
        As[nbuf][ak+0][am+64] = f2tf(a1.x); As[nbuf][ak+1][am+64] = f2tf(a1.y);
        As[nbuf][ak+2][am+64] = f2tf(a1.z); As[nbuf][ak+3][am+64] = f2tf(a1.w);
        Bs[nbuf][bk][bn+0] = f2tf(b0.x); Bs[nbuf][bk][bn+1] = f2tf(b0.y);
        Bs[nbuf][bk][bn+2] = f2tf(b0.z); Bs[nbuf][bk][bn+3] = f2tf(b0.w);
        Bs[nbuf][bk+8][bn+0] = f2tf(b1.x); Bs[nbuf][bk+8][bn+1] = f2tf(b1.y);
        Bs[nbuf][bk+8][bn+2] = f2tf(b1.z); Bs[nbuf][bk+8][bn+3] = f2tf(b1.w);
        __syncthreads();
        buf = nbuf;
    }

    #pragma unroll
    for (int ks = 0; ks < 16; ks += 8) {
        uint32_t af[2][4], bf[8][2];
        #pragma unroll
        for (int mt = 0; mt < 2; mt++) {
            af[mt][0] = As[buf][ks+t4  ][mb + mt*16];
            af[mt][1] = As[buf][ks+t4  ][mb + mt*16 + 8];
            af[mt][2] = As[buf][ks+t4+4][mb + mt*16];
            af[mt][3] = As[buf][ks+t4+4][mb + mt*16 + 8];
        }
        #pragma unroll
        for (int nt = 0; nt < 8; nt++) {
            bf[nt][0] = Bs[buf][ks+t4  ][nb + nt*8];
            bf[nt][1] = Bs[buf][ks+t4+4][nb + nt*8];
        }
        #pragma unroll
        for (int mt = 0; mt < 2; mt++)
            #pragma unroll
            for (int nt = 0; nt < 8; nt++)
                mma_tf32(c[mt][nt], af[mt], bf[nt]);
    }

    #pragma unroll
    for (int mt = 0; mt < 2; mt++) {
        int row0 = by*128 + wm*32 + mt*16 + g;
        int row1 = row0 + 8;
        #pragma unroll
        for (int nt = 0; nt < 8; nt++) {
            int col = bx*128 + wn*64 + nt*8 + 2*t4;
            float2 v0o, v1o;
            v0o.x = c[mt][nt][0]; v0o.y = c[mt][nt][1];
            v1o.x = c[mt][nt][2]; v1o.y = c[mt][nt][3];
            if (bias) {
                float bx0 = bias[col], bx1 = bias[col+1];
                v0o.x += bx0; v0o.y += bx1; v1o.x += bx0; v1o.y += bx1;
            }
            if (ACT == 1) {
                v0o.x = gelu_exact(v0o.x); v0o.y = gelu_exact(v0o.y);
                v1o.x = gelu_exact(v1o.x); v1o.y = gelu_exact(v1o.y);
            }
            if (row0 < M) *(float2*)&C[(size_t)row0*N + col] = v0o;
            if (row1 < M) *(float2*)&C[(size_t)row1*N + col] = v1o;
        }
    }
}

// ---------------- embedding ----------------
__global__ void embed_kernel(const float* __restrict__ x_enc,
                             const float* __restrict__ xme,
                             const float* __restrict__ xmd,
                             const float* __restrict__ tw,
                             const float* __restrict__ tb,
                             const float* __restrict__ tempw,
                             const float* __restrict__ tempb) {
    int t = blockIdx.x, b = blockIdx.y;
    __shared__ float xv[3][7];
    __shared__ float xm[4];
    int tid = threadIdx.x;   // 128
    if (tid < 21) {
        int k = tid / 7, i = tid % 7;
        int r = t - 1 + k;
        int rr = (r + 1025) % 1025;
        float val = 0.f;
        if (rr < 1024) val = x_enc[((size_t)b*1024 + rr)*7 + i];
        xv[k][i] = val;
    }
    if (tid >= 32 && tid < 36) {
        int m = tid - 32;
        xm[m] = (t < 1024) ? xme[((size_t)b*1024 + t)*4 + m]
                           : xmd[((size_t)b*96)*4 + m];
    }
    __syncthreads();
    for (int d = tid; d < DD; d += 128) {
        float acc = tb[d];
        #pragma unroll
        for (int i = 0; i < 7; i++)
            #pragma unroll
            for (int k = 0; k < 3; k++)
                acc += xv[k][i] * tw[(d*7 + i)*3 + k];
        acc += tempb[d];
        #pragma unroll
        for (int m = 0; m < 4; m++) acc += xm[m] * tempw[m*DD + d];
        int m2 = d & ~1;
        float div = expf(-9.210340371976184f / 512.0f * (float)m2);
        float arg = (float)t * div;
        acc += (d & 1) ? cosf(arg) : sinf(arg);
        g_emb[((size_t)b*LL + t)*DD + d] = acc;
    }
}

// ---------------- conv (stride-4, kernel-4, ELU): 8 outputs per block ----------
__global__ void conv_kernel(const float* __restrict__ in, int ibs, int inOff,
                            const float* __restrict__ w, const float* __restrict__ bias,
                            float* __restrict__ out, int outOff) {
    int t0 = blockIdx.x * 8, b = blockIdx.y;
    int tid = threadIdx.x;   // 128 (= oc)
    __shared__ float si[8*512];
    const float* ip = in + (size_t)(b*ibs + inOff + 4*t0) * 128;
    #pragma unroll
    for (int i = 0; i < 32; i++) si[i*128 + tid] = ip[i*128 + tid];
    __syncthreads();
    float bv = bias[tid];
    float acc[8];
    #pragma unroll
    for (int t = 0; t < 8; t++) acc[t] = bv;
    #pragma unroll 2
    for (int ic = 0; ic < 128; ic++) {
        float4 w4 = *(const float4*)&w[((size_t)tid*128 + ic)*4];
        #pragma unroll
        for (int t = 0; t < 8; t++) {
            const float* s = si + t*512;
            acc[t] += s[ic]*w4.x + s[128+ic]*w4.y + s[256+ic]*w4.z + s[384+ic]*w4.w;
        }
    }
    #pragma unroll
    for (int t = 0; t < 8; t++) {
        float a = acc[t];
        a = (a > 0.f) ? a : expm1f(a);
        out[(size_t)(b*336 + outOff + t0 + t)*128 + tid] = a;
    }
}

// ---------------- layernorm (512 wide, 256 threads) + half copy ----------------
__device__ __forceinline__ void ln_core(const float* __restrict__ x0,
                                        const float* __restrict__ x1,
                                        const float* __restrict__ sc,
                                        const float* __restrict__ bb,
                                        float* __restrict__ out,
                                        __half* __restrict__ out_h) {
    __shared__ float red[8];
    int tid = threadIdx.x;
    float v0 = x0[tid]       + (x1 ? x1[tid]       : 0.f);
    float v1 = x0[tid + 256] + (x1 ? x1[tid + 256] : 0.f);
    float sum = v0 + v1;
    #pragma unroll
    for (int o = 16; o; o >>= 1) sum += __shfl_xor_sync(0xffffffffu, sum, o);
    if ((tid & 31) == 0) red[tid >> 5] = sum;
    __syncthreads();
    float tot = 0.f;
    #pragma unroll
    for (int w = 0; w < 8; w++) tot += red[w];
    float mean = tot * (1.0f/512.0f);
    __syncthreads();
    float d0 = v0 - mean, d1 = v1 - mean;
    float sq = d0*d0 + d1*d1;
    #pragma unroll
    for (int o = 16; o; o >>= 1) sq += __shfl_xor_sync(0xffffffffu, sq, o);
    if ((tid & 31) == 0) red[tid >> 5] = sq;
    __syncthreads();
    float vtot = 0.f;
    #pragma unroll
    for (int w = 0; w < 8; w++) vtot += red[w];
    float inv = rsqrtf(vtot * (1.0f/512.0f) + 1e-5f);
    float o0 = d0 * inv * sc[tid]       + bb[tid];
    float o1 = d1 * inv * sc[tid + 256] + bb[tid + 256];
    out[tid]       = o0;
    out[tid + 256] = o1;
    out_h[tid]       = __float2half_rn(o0);
    out_h[tid + 256] = __float2half_rn(o1);
}

__global__ void concat_ln_kernel(const float* __restrict__ sc, const float* __restrict__ bb) {
    int row = blockIdx.x;
    int b = row / NT, n = row % NT;
    const float* src = (n < LL) ? &g_emb[((size_t)b*LL + n)*DD]
                                : &g_pyr[((size_t)b*336 + (n - LL))*DD];
    ln_core(src, nullptr, sc, bb, &g_seq[(size_t)row*DD],
            (__half*)g_seqr_h + (size_t)row*DD);
}

__global__ void add_ln_kernel(const float* __restrict__ sc, const float* __restrict__ bb) {
    size_t row = blockIdx.x;
    ln_core(&g_seq[row*DD], &g_tmp[row*DD], sc, bb, &g_seq[row*DD],
            (__half*)g_seqr_h + row*DD);
}

// ---------------- fused sparse attention (fp16 qkv in, fp32 math, half out) ----
#define MAXN 12
__global__ __launch_bounds__(256)
void attn_kernel() {
    int i = blockIdx.x, b = blockIdx.y;
    __shared__ int s_nbr[MAXN];
    __shared__ int s_nn;
    int tid = threadIdx.x;
    if (tid == 0) {
        const int starts[5] = {0, 1025, 1281, 1345, 1361};
        int li = (i < 1025) ? 0 : (i < 1281) ? 1 : (i < 1345) ? 2 : 3;
        int s = starts[li], e = starts[li+1];
        int nn = 0;
        int jlo = (i - 2 > s) ? i - 2 : s;
        int jhi = (i + 2 < e - 1) ? i + 2 : e - 1;
        for (int j = jlo; j <= jhi; j++) s_nbr[nn++] = j;
        if (li > 0) {
            int ps = starts[li-1];
            int qq = i - s;
            int lo = ps + qq * 4;
            int hi = (i == e - 1) ? s : ps + (qq + 1) * 4;
            for (int j = lo; j < hi; j++) s_nbr[nn++] = j;
        }
        if (li < 3) {
            int su = starts[li+1];
            int szu = starts[li+2] - su;
            int qq = (i - s) / 4;
            s_nbr[nn++] = su + ((qq < szu - 1) ? qq : szu - 1);
        }
        s_nn = nn;
        for (int j = nn; j < MAXN; j++) s_nbr[j] = i;
    }
    __syncthreads();
    int nn = s_nn;
    int h = tid >> 5, lane = tid & 31;
    const uint32_t* qkvh = (const uint32_t*)g_qkv_h;   // half2 units, row stride 768
    size_t rowu = ((size_t)b*NT + i)*768;
    uint32_t qu = qkvh[rowu + h*32 + lane];
    float2 qf = __half22float2(*(__half2*)&qu);

    float dots[MAXN];
    #pragma unroll
    for (int jj = 0; jj < MAXN; jj++) {
        size_t ku = ((size_t)b*NT + s_nbr[jj])*768 + 256 + h*32 + lane;
        uint32_t kk = qkvh[ku];
        float2 kf = __half22float2(*(__half2*)&kk);
        float p = qf.x*kf.x + qf.y*kf.y;
        #pragma unroll
        for (int o = 16; o; o >>= 1) p += __shfl_xor_sync(0xffffffffu, p, o);
        dots[jj] = (jj < nn) ? p * 0.125f : -1e30f;
    }
    float mx = -1e30f;
    #pragma unroll
    for (int jj = 0; jj < MAXN; jj++) mx = fmaxf(mx, dots[jj]);
    float sum = 0.f;
    #pragma unroll
    for (int jj = 0; jj < MAXN; jj++) { dots[jj] = expf(dots[jj] - mx); sum += dots[jj]; }
    float inv = 1.f / sum;
    float o0 = 0.f, o1 = 0.f;
    #pragma unroll
    for (int jj = 0; jj < MAXN; jj++) {
        size_t vu = ((size_t)b*NT + s_nbr[jj])*768 + 512 + h*32 + lane;
        uint32_t vv = qkvh[vu];
        float2 vf = __half22float2(*(__half2*)&vv);
        float w = dots[jj] * inv;
        o0 += w * vf.x;
        o1 += w * vf.y;
    }
    // output dims (2*lane, 2*lane+1) of head h
    uint32_t* oh = (uint32_t*)g_o_h;
    oh[((size_t)b*NT + i)*256 + h*32 + lane] = packh2(o0, o1);
}

// ---------------- gather + prediction head (split-r partials + reduce) ---------
__global__ void pred_part(const float* __restrict__ pw) {
    int b = blockIdx.x, ch = blockIdx.y;   // 8 chunks of 256 rows
    __shared__ float gv[256];
    const int rows[4] = {1024, 1280, 1344, 1360};
    int tid = threadIdx.x;   // 672
    if (tid < 256) {
        int r = ch*256 + tid;
        int wch = r >> 9, d = r & 511;
        gv[tid] = g_seq[((size_t)b*NT + rows[wch])*DD + d];
    }
    __syncthreads();
    float acc = 0.f;
    const float* p = pw + (size_t)(ch*256)*672 + tid;
    #pragma unroll 8
    for (int j = 0; j < 256; j++) acc += gv[j] * p[(size_t)j*672];
    g_predp[(b*8 + ch)*672 + tid] = acc;
}
__global__ void pred_reduce(float* __restrict__ out) {
    int idx = blockIdx.x*blockDim.x + threadIdx.x;   // BB*672
    if (idx >= BB*672) return;
    int b = idx / 672, c = idx % 672;
    float s = 0.f;
    #pragma unroll
    for (int ch = 0; ch < 8; ch++) s += g_predp[(b*8 + ch)*672 + c];
    out[idx] = s;
}

// ---------------- host ----------------
static void launch_tf32(const float* A, const float* Bm, const float* bias,
                        float* C, int M, int N, int K) {
    dim3 grid(N / 128, (M + 127) / 128);
    tgemm_kernel<0><<<grid, 256>>>(A, Bm, bias, C, M, N, K);
}

extern "C" void kernel_launch(void* const* d_in, const int* in_sizes, int n_in,
                              void* d_out, int out_size) {
    const float* x_enc   = (const float*)d_in[0];
    const float* xme     = (const float*)d_in[1];
    // d_in[2] = x_dec (unused by the model math)
    const float* xmd     = (const float*)d_in[3];
    const float* token_w = (const float*)d_in[4];
    const float* token_b = (const float*)d_in[5];
    const float* temp_w  = (const float*)d_in[6];
    const float* temp_b  = (const float*)d_in[7];
    const float* down_w  = (const float*)d_in[8];
    const float* down_b  = (const float*)d_in[9];
    const float* conv_w  = (const float*)d_in[10];
    const float* conv_b  = (const float*)d_in[11];
    const float* up_w    = (const float*)d_in[12];
    const float* up_b    = (const float*)d_in[13];
    const float* cln_s   = (const float*)d_in[14];
    const float* cln_b   = (const float*)d_in[15];
    const float* Wq      = (const float*)d_in[16];
    const float* Wk      = (const float*)d_in[17];
    const float* Wv      = (const float*)d_in[18];
    const float* Wo      = (const float*)d_in[19];
    const float* bo      = (const float*)d_in[20];
    const float* ln1_s   = (const float*)d_in[21];
    const float* ln1_b   = (const float*)d_in[22];
    const float* W1      = (const float*)d_in[23];
    const float* b1      = (const float*)d_in[24];
    const float* W2      = (const float*)d_in[25];
    const float* b2      = (const float*)d_in[26];
    const float* ln2_s   = (const float*)d_in[27];
    const float* ln2_b   = (const float*)d_in[28];
    const float* pred_w  = (const float*)d_in[29];

    float *emb, *d0, *cc, *pyr, *seq, *tmp;
    uint32_t *seqr_h, *qkv_h, *o_h, *ffn_h, *wqkvh, *woh, *w1h, *w2h;
    cudaGetSymbolAddress((void**)&emb,  g_emb);
    cudaGetSymbolAddress((void**)&d0,   g_d0);
    cudaGetSymbolAddress((void**)&cc,   g_cc);
    cudaGetSymbolAddress((void**)&pyr,  g_pyr);
    cudaGetSymbolAddress((void**)&seq,  g_seq);
    cudaGetSymbolAddress((void**)&tmp,  g_tmp);
    cudaGetSymbolAddress((void**)&seqr_h, g_seqr_h);
    cudaGetSymbolAddress((void**)&qkv_h,  g_qkv_h);
    cudaGetSymbolAddress((void**)&o_h,    g_o_h);
    cudaGetSymbolAddress((void**)&ffn_h,  g_ffn_h);
    cudaGetSymbolAddress((void**)&wqkvh,  g_wqkvh);
    cudaGetSymbolAddress((void**)&woh,    g_woh);
    cudaGetSymbolAddress((void**)&w1h,    g_w1h);
    cudaGetSymbolAddress((void**)&w2h,    g_w2h);

    cudaFuncSetAttribute(hgemm_kernel<0,0>, cudaFuncAttributeMaxDynamicSharedMemorySize, HG_SMEM);
    cudaFuncSetAttribute(hgemm_kernel<0,1>, cudaFuncAttributeMaxDynamicSharedMemorySize, HG_SMEM);
    cudaFuncSetAttribute(hgemm_kernel<1,1>, cudaFuncAttributeMaxDynamicSharedMemorySize, HG_SMEM);

    // 0) pack all encoder weights to fp16 pair layout [K/2][N] (vectorized)
    pack_qkvh<<<(4*256*384 + 255)/256, 256>>>(Wq, Wk, Wv, wqkvh);
    packh<<<(4*256*128 + 255)/256, 256>>>(Wo, woh, 512, 512, 4*256*128);
    packh<<<(4*256*512 + 255)/256, 256>>>(W1, w1h, 512, 2048, 4*256*512);
    packh<<<(4*1024*128 + 255)/256, 256>>>(W2, w2h, 2048, 512, 4*1024*128);

    // 1) embedding
    embed_kernel<<<dim3(LL, BB), 128>>>(x_enc, xme, xmd, token_w, token_b, temp_w, temp_b);

    // 2) bottleneck down-projection (tf32 path)
    launch_tf32(emb, down_w, down_b, d0, BB*LL, 128, DD);

    // 3) pyramid convs (8 outputs per block)
    conv_kernel<<<dim3(32, BB), 128>>>(d0, LL, 0,   conv_w,               conv_b,       cc, 0);
    conv_kernel<<<dim3(8,  BB), 128>>>(cc, 336, 0,  conv_w + 128*128*4,   conv_b + 128, cc, 256);
    conv_kernel<<<dim3(2,  BB), 128>>>(cc, 336, 256,conv_w + 2*128*128*4, conv_b + 256, cc, 320);

    // 4) up-projection (tf32 path)
    launch_tf32(cc, up_w, up_b, pyr, BB*336, DD, 128);

    // 5) concat + LayerNorm -> seq (+ half copy)
    concat_ln_kernel<<<MROWS, 256>>>(cln_s, cln_b);

    // 6) encoder layers (fp16 GEMMs, cp.async 4-stage; qkv stored fp16)
    const int MT = (MROWS + 127) / 128;   // 43
    for (int i = 0; i < 4; i++) {
        hgemm_kernel<0,1><<<dim3(12, MT), 256, HG_SMEM>>>(
            seqr_h, wqkvh + (size_t)i*256*1536, nullptr, qkv_h, MROWS, 1536, 512);

        attn_kernel<<<dim3(NT, BB), 256>>>();

        hgemm_kernel<0,0><<<dim3(4, MT), 256, HG_SMEM>>>(
            o_h, woh + (size_t)i*256*512, bo + i*DD, tmp, MROWS, 512, 512);
        add_ln_kernel<<<MROWS, 256>>>(ln1_s + i*DD, ln1_b + i*DD);

        hgemm_kernel<1,1><<<dim3(16, MT), 256, HG_SMEM>>>(
            seqr_h, w1h + (size_t)i*256*2048, b1 + i*DFF, ffn_h, MROWS, 2048, 512);
        hgemm_kernel<0,0><<<dim3(4, MT), 256, HG_SMEM>>>(
            ffn_h, w2h + (size_t)i*1024*512, b2 + i*DD, tmp, MROWS, 512, 2048);
        add_ln_kernel<<<MROWS, 256>>>(ln2_s + i*DD, ln2_b + i*DD);
    }

    // 7) gather + prediction head (split partials, deterministic reduce)
    pred_part<<<dim3(BB, 8), 672>>>(pred_w);
    pred_reduce<<<(BB*672 + 255)/256, 256>>>((float*)d_out);
}

// round 15
// speedup vs baseline: 2.1709x; 1.0257x over previous
#include <cuda_runtime.h>
#include <cuda_fp16.h>
#include <math.h>
#include <stdint.h>

#define BB 4
#define LL 1025
#define NT 1361
#define DD 512
#define HH 8
#define DFF 2048
#define MROWS (BB*NT)         // 5444

// ---------------- scratch (static device allocations) ----------------
__device__ float g_emb [BB*LL*DD];
__device__ float g_d0  [BB*LL*128];
__device__ float g_cc  [BB*336*128];
__device__ float g_pyr [BB*336*DD];
__device__ float g_seq [BB*NT*DD];
__device__ float g_tmp [BB*NT*DD];
__device__ float g_predp[BB*8*672];
// fp16 activations (uint4 arrays => 16B alignment guaranteed)
__device__ uint4 g_seqr_h[MROWS*DD/8];     // half copy of seq (GEMM A)
__device__ uint4 g_qkv_h [MROWS*1536/8];   // QKV output (half)
__device__ uint4 g_o_h   [MROWS*DD/8];     // attention output (half)
__device__ uint4 g_ffn_h [MROWS*DFF/8];    // W1+gelu output (half)
// fp16 weight packs: uint32 pairs, layout [K/2][N] per layer
__device__ uint4 g_wqkvh[4*256*1536/4];
__device__ uint4 g_woh  [4*256*512/4];
__device__ uint4 g_w1h  [4*256*2048/4];
__device__ uint4 g_w2h  [4*1024*512/4];

// ---------------- helpers ----------------
__device__ __forceinline__ uint32_t f2tf(float x) {
    uint32_t r;
    asm("cvt.rna.tf32.f32 %0, %1;" : "=r"(r) : "f"(x));
    return r;
}
__device__ __forceinline__ float gelu_exact(float x) {
    return 0.5f * x * (1.0f + erff(x * 0.70710678118654752f));
}
__device__ __forceinline__ uint32_t packh2(float a, float b) {
    __half2 h = __halves2half2(__float2half_rn(a), __float2half_rn(b));
    return *(uint32_t*)&h;
}
__device__ __forceinline__ void mma_tf32(float c[4], const uint32_t a[4], const uint32_t b[2]) {
    asm volatile(
        "mma.sync.aligned.m16n8k8.row.col.f32.tf32.tf32.f32 "
        "{%0,%1,%2,%3}, {%4,%5,%6,%7}, {%8,%9}, {%0,%1,%2,%3};\n"
        : "+f"(c[0]), "+f"(c[1]), "+f"(c[2]), "+f"(c[3])
        : "r"(a[0]), "r"(a[1]), "r"(a[2]), "r"(a[3]), "r"(b[0]), "r"(b[1]));
}
__device__ __forceinline__ void mma_f16(float c[4], const uint32_t a[4], const uint32_t b[2]) {
    asm volatile(
        "mma.sync.aligned.m16n8k16.row.col.f32.f16.f16.f32 "
        "{%0,%1,%2,%3}, {%4,%5,%6,%7}, {%8,%9}, {%0,%1,%2,%3};\n"
        : "+f"(c[0]), "+f"(c[1]), "+f"(c[2]), "+f"(c[3])
        : "r"(a[0]), "r"(a[1]), "r"(a[2]), "r"(a[3]), "r"(b[0]), "r"(b[1]));
}
__device__ __forceinline__ void cp16(uint32_t dst, const void* src, bool v) {
    int sz = v ? 16 : 0;
    asm volatile("cp.async.cg.shared.global [%0], [%1], 16, %2;"
                 :: "r"(dst), "l"(src), "r"(sz));
}
#define CP_COMMIT()  asm volatile("cp.async.commit_group;" ::: "memory")
#define CP_WAIT(n)   asm volatile("cp.async.wait_group %0;" :: "n"(n) : "memory")

// ---------------- fp16 weight packing (vectorized, 4 outputs/thread) -------------
__global__ void packh(const float* __restrict__ in, uint32_t* __restrict__ out,
                      int K, int N, int total4) {
    int idx = blockIdx.x*blockDim.x + threadIdx.x;   // over total/4
    if (idx >= total4) return;
    int K2 = K >> 1, N4 = N >> 2;
    int n4 = idx % N4;
    int k2 = (idx / N4) % K2;
    int l  = idx / (N4 * K2);
    const float* src = in + ((size_t)l*K + 2*k2)*N + n4*4;
    float4 r0 = *(const float4*)src;
    float4 r1 = *(const float4*)(src + N);
    uint4 o;
    o.x = packh2(r0.x, r1.x); o.y = packh2(r0.y, r1.y);
    o.z = packh2(r0.z, r1.z); o.w = packh2(r0.w, r1.w);
    *(uint4*)(out + (size_t)idx*4) = o;
}
__global__ void pack_qkvh(const float* __restrict__ Wq,
                          const float* __restrict__ Wk,
                          const float* __restrict__ Wv,
                          uint32_t* __restrict__ out) {
    int idx = blockIdx.x*blockDim.x + threadIdx.x;   // 4*256*384
    if (idx >= 4*256*384) return;
    int n4 = idx % 384;
    int t  = idx / 384;         // l*256 + k2
    int k2 = t & 255;
    int l  = t >> 8;
    int n  = n4 * 4;
    const float* src = (n < 512) ? Wq : (n < 1024) ? Wk : Wv;
    int nn = n & 511;
    size_t base = ((size_t)l*512 + 2*k2)*512 + nn;
    float4 r0 = *(const float4*)(src + base);
    float4 r1 = *(const float4*)(src + base + 512);
    uint4 o;
    o.x = packh2(r0.x, r1.x); o.y = packh2(r0.y, r1.y);
    o.z = packh2(r0.z, r1.z); o.w = packh2(r0.w, r1.w);
    *(uint4*)(out + (size_t)idx*4) = o;
}

// ---------------- FP16 mma.sync GEMM, 4-stage cp.async pipeline -----------------
// BM=BN=128, BK=32 halfs; 256 thr = 8 warps (4M x 2N), warp 32x64.
// A smem m-major [m][k2] stride 20 (conflict-free); B smem [k2][n] stride 136.
#define HG_STG   4736
#define HG_ASZ   2560
#define HG_SMEM  (4*HG_STG*4)
template<int ACT, int OUTH>
__global__ __launch_bounds__(256)
void hgemm_kernel(const uint32_t* __restrict__ A32, const uint32_t* __restrict__ Bw,
                  const float* __restrict__ bias, void* __restrict__ Cv,
                  int M, int N, int K) {
    extern __shared__ uint32_t sm[];
    uint32_t smbase;
    asm("{ .reg .u64 t; cvta.to.shared.u64 t, %1; cvt.u32.u64 %0, t; }"
        : "=r"(smbase) : "l"(sm));
    int tid = threadIdx.x;
    int bx = blockIdx.x, by = blockIdx.y;
    int w = tid >> 5, lane = tid & 31;
    int wm = w & 3, wn = w >> 2;
    int g = lane >> 2, t4 = lane & 3;
    int K2 = K >> 1;

    float c[2][8][4];
    #pragma unroll
    for (int mt = 0; mt < 2; mt++)
        #pragma unroll
        for (int nt = 0; nt < 8; nt++)
            #pragma unroll
            for (int r = 0; r < 4; r++) c[mt][nt][r] = 0.f;

    int am = tid >> 2;            // 0..63
    int aq = (tid & 3) * 4;       // 0,4,8,12
    int arow0 = by*128 + am, arow1 = arow0 + 64;
    bool v0 = (arow0 < M), v1 = (arow1 < M);
    const uint32_t* Ap0 = A32 + (size_t)(v0 ? arow0 : 0) * K2 + aq;
    const uint32_t* Ap1 = A32 + (size_t)(v1 ? arow1 : 0) * K2 + aq;

    int br = tid >> 4;            // 0..15
    int bu = (tid & 15) * 4;      // 0..60
    const uint32_t* Bp = Bw + (size_t)br * N + bx*128 + bu;

    uint32_t adst0 = smbase + (am*20 + aq)*4;
    uint32_t adst1 = smbase + ((am+64)*20 + aq)*4;
    uint32_t bdst0 = smbase + (HG_ASZ + br*136 + bu)*4;
    uint32_t bdst1 = bdst0 + 64*4;
    const uint32_t STGB = HG_STG*4;

    int nk = K2 >> 4;

    #define HG_ISSUE(T_) do { \
        int _t = (T_); \
        if (_t < nk) { \
            uint32_t off = (uint32_t)(_t & 3) * STGB; \
            cp16(adst0 + off, Ap0 + _t*16, v0); \
            cp16(adst1 + off, Ap1 + _t*16, v1); \
            cp16(bdst0 + off, Bp + (size_t)(_t*16)*N, true); \
            cp16(bdst1 + off, Bp + (size_t)(_t*16)*N + 64, true); \
        } \
        CP_COMMIT(); \
    } while (0)

    HG_ISSUE(0); HG_ISSUE(1); HG_ISSUE(2);

    int mb = wm*32 + g;
    int nb = wn*64 + g;
    for (int t = 0; t < nk; t++) {
        CP_WAIT(2);
        __syncthreads();
        HG_ISSUE(t + 3);
        const uint32_t* Sa = sm + (t & 3)*HG_STG;
        const uint32_t* Sb = Sa + HG_ASZ;
        #pragma unroll
        for (int ks = 0; ks < 16; ks += 8) {
            uint32_t af[2][4], bf[8][2];
            #pragma unroll
            for (int mt = 0; mt < 2; mt++) {
                int mrow = mb + mt*16;
                af[mt][0] = Sa[(mrow  )*20 + ks+t4  ];
                af[mt][1] = Sa[(mrow+8)*20 + ks+t4  ];
                af[mt][2] = Sa[(mrow  )*20 + ks+t4+4];
                af[mt][3] = Sa[(mrow+8)*20 + ks+t4+4];
            }
            #pragma unroll
            for (int nt = 0; nt < 8; nt++) {
                bf[nt][0] = Sb[(ks+t4  )*136 + nb + nt*8];
                bf[nt][1] = Sb[(ks+t4+4)*136 + nb + nt*8];
            }
            #pragma unroll
            for (int mt = 0; mt < 2; mt++)
                #pragma unroll
                for (int nt = 0; nt < 8; nt++)
                    mma_f16(c[mt][nt], af[mt], bf[nt]);
        }
    }
    #undef HG_ISSUE

    // epilogue
    #pragma unroll
    for (int mt = 0; mt < 2; mt++) {
        int row0 = by*128 + wm*32 + mt*16 + g;
        int row1 = row0 + 8;
        #pragma unroll
        for (int nt = 0; nt < 8; nt++) {
            int col = bx*128 + wn*64 + nt*8 + 2*t4;
            float x0 = c[mt][nt][0], x1 = c[mt][nt][1];
            float y0 = c[mt][nt][2], y1 = c[mt][nt][3];
            if (bias) {
                float bx0 = bias[col], bx1 = bias[col+1];
                x0 += bx0; x1 += bx1; y0 += bx0; y1 += bx1;
            }
            if (ACT == 1) {
                x0 = gelu_exact(x0); x1 = gelu_exact(x1);
                y0 = gelu_exact(y0); y1 = gelu_exact(y1);
            }
            if (OUTH) {
                uint32_t* Ch = (uint32_t*)Cv;
                if (row0 < M) Ch[((size_t)row0*N + col) >> 1] = packh2(x0, x1);
                if (row1 < M) Ch[((size_t)row1*N + col) >> 1] = packh2(y0, y1);
            } else {
                float* Cf = (float*)Cv;
                if (row0 < M) { float2 v; v.x = x0; v.y = x1; *(float2*)&Cf[(size_t)row0*N + col] = v; }
                if (row1 < M) { float2 v; v.x = y0; v.y = y1; *(float2*)&Cf[(size_t)row1*N + col] = v; }
            }
        }
    }
}

// ---------------- TF32 mma.sync GEMM (down/up projections) ----------------------
template<int ACT>
__global__ __launch_bounds__(256)
void tgemm_kernel(const float* __restrict__ A, const float* __restrict__ Bm,
                  const float* __restrict__ bias, float* __restrict__ C,
                  int M, int N, int K) {
    __shared__ uint32_t As[2][16][136];
    __shared__ uint32_t Bs[2][16][136];
    int tid = threadIdx.x;
    int bx = blockIdx.x, by = blockIdx.y;
    int w = tid >> 5, lane = tid & 31;
    int wm = w & 3, wn = w >> 2;
    int g = lane >> 2, t4 = lane & 3;

    float c[2][8][4];
    #pragma unroll
    for (int mt = 0; mt < 2; mt++)
        #pragma unroll
        for (int nt = 0; nt < 8; nt++)
            #pragma unroll
            for (int r = 0; r < 4; r++) c[mt][nt][r] = 0.f;

    int am = tid >> 2;
    int ak = (tid & 3) * 4;
    int arow0 = by*128 + am;
    int arow1 = arow0 + 64;
    const float* Ap0 = A + (size_t)arow0 * K + ak;
    const float* Ap1 = A + (size_t)arow1 * K + ak;
    bool v0 = (arow0 < M), v1 = (arow1 < M);

    int bk = tid >> 5;
    int bn = (tid & 31) * 4;
    const float* Bp = Bm + (size_t)bk * N + bx*128 + bn;

    int nk = K >> 4;
    float4 a0, a1, b0, b1;

    a0 = v0 ? *(const float4*)(Ap0) : make_float4(0,0,0,0);
    a1 = v1 ? *(const float4*)(Ap1) : make_float4(0,0,0,0);
    b0 = *(const float4*)(Bp);
    b1 = *(const float4*)(Bp + (size_t)8*N);
    As[0][ak+0][am] = f2tf(a0.x); As[0][ak+1][am] = f2tf(a0.y);
    As[0][ak+2][am] = f2tf(a0.z); As[0][ak+3][am] = f2tf(a0.w);
    As[0][ak+0][am+64] = f2tf(a1.x); As[0][ak+1][am+64] = f2tf(a1.y);
    As[0][ak+2][am+64] = f2tf(a1.z); As[0][ak+3][am+64] = f2tf(a1.w);
    Bs[0][bk][bn+0] = f2tf(b0.x); Bs[0][bk][bn+1] = f2tf(b0.y);
    Bs[0][bk][bn+2] = f2tf(b0.z); Bs[0][bk][bn+3] = f2tf(b0.w);
    Bs[0][bk+8][bn+0] = f2tf(b1.x); Bs[0][bk+8][bn+1] = f2tf(b1.y);
    Bs[0][bk+8][bn+2] = f2tf(b1.z); Bs[0][bk+8][bn+3] = f2tf(b1.w);
    __syncthreads();

    int mb = wm*32 + g;
    int nb = wn*64 + g;
    int buf = 0;
    for (int tile = 1; tile < nk; tile++) {
        const float* ap0 = Ap0 + tile*16;
        const float* ap1 = Ap1 + tile*16;
        const float* bp  = Bp + (size_t)(tile*16) * N;
        a0 = v0 ? *(const float4*)(ap0) : make_float4(0,0,0,0);
        a1 = v1 ? *(const float4*)(ap1) : make_float4(0,0,0,0);
        b0 = *(const float4*)(bp);
        b1 = *(const float4*)(bp + (size_t)8*N);

        #pragma unroll
        for (int ks = 0; ks < 16; ks += 8) {
            uint32_t af[2][4], bf[8][2];
            #pragma unroll
            for (int mt = 0; mt < 2; mt++) {
                af[mt][0] = As[buf][ks+t4  ][mb + mt*16];
                af[mt][1] = As[buf][ks+t4  ][mb + mt*16 + 8];
                af[mt][2] = As[buf][ks+t4+4][mb + mt*16];
                af[mt][3] = As[buf][ks+t4+4][mb + mt*16 + 8];
            }
            #pragma unroll
            for (int nt = 0; nt < 8; nt++) {
                bf[nt][0] = Bs[buf][ks+t4  ][nb + nt*8];
                bf[nt][1] = Bs[buf][ks+t4+4][nb + nt*8];
            }
            #pragma unroll
            for (int mt = 0; mt < 2; mt++)
                #pragma unroll
                for (int nt = 0; nt < 8; nt++)
                    mma_tf32(c[mt][nt], af[mt], bf[nt]);
        }

        int nbuf = buf ^ 1;
        As[nbuf][ak+0][am] = f2tf(a0.x); As[nbuf][ak+1][am] = f2tf(a0.y);
        As[nbuf][ak+2][am] = f2tf(a0.z); As[nbuf][ak+3][am] = f2tf(a0.w);
        As[nbuf][ak+0][am+64] = f2tf(a1.x); As[nbuf][ak+1][am+64] = f2tf(a1.y);
        As[nbuf][ak+2][am+64] = f2tf(a1.z); As[nbuf][ak+3][am+64] = f2tf(a1.w);
        Bs[nbuf][bk][bn+0] = f2tf(b0.x); Bs[nbuf][bk][bn+1] = f2tf(b0.y);
        Bs[nbuf][bk][bn+2] = f2tf(b0.z); Bs[nbuf][bk][bn+3] = f2tf(b0.w);
        Bs[nbuf][bk+8][bn+0] = f2tf(b1.x); Bs[nbuf][bk+8][bn+1] = f2tf(b1.y);
        Bs[nbuf][bk+8][bn+2] = f2tf(b1.z); Bs[nbuf][bk+8][bn+3] = f2tf(b1.w);
        __syncthreads();
        buf = nbuf;
    }

    #pragma unroll
    for (int ks = 0; ks < 16; ks += 8) {
        uint32_t af[2][4], bf[8][2];
        #pragma unroll
        for (int mt = 0; mt < 2; mt++) {
            af[mt][0] = As[buf][ks+t4  ][mb + mt*16];
            af[mt][1] = As[buf][ks+t4  ][mb + mt*16 + 8];
            af[mt][2] = As[buf][ks+t4+4][mb + mt*16];
            af[mt][3] = As[buf][ks+t4+4][mb + mt*16 + 8];
        }
        #pragma unroll
        for (int nt = 0; nt < 8; nt++) {
            bf[nt][0] = Bs[buf][ks+t4  ][nb + nt*8];
            bf[nt][1] = Bs[buf][ks+t4+4][nb + nt*8];
        }
        #pragma unroll
        for (int mt = 0; mt < 2; mt++)
            #pragma unroll
            for (int nt = 0; nt < 8; nt++)
                mma_tf32(c[mt][nt], af[mt], bf[nt]);
    }

    #pragma unroll
    for (int mt = 0; mt < 2; mt++) {
        int row0 = by*128 + wm*32 + mt*16 + g;
        int row1 = row0 + 8;
        #pragma unroll
        for (int nt = 0; nt < 8; nt++) {
            int col = bx*128 + wn*64 + nt*8 + 2*t4;
            float2 v0o, v1o;
            v0o.x = c[mt][nt][0]; v0o.y = c[mt][nt][1];
            v1o.x = c[mt][nt][2]; v1o.y = c[mt][nt][3];
            if (bias) {
                float bx0 = bias[col], bx1 = bias[col+1];
                v0o.x += bx0; v0o.y += bx1; v1o.x += bx0; v1o.y += bx1;
            }
            if (ACT == 1) {
                v0o.x = gelu_exact(v0o.x); v0o.y = gelu_exact(v0o.y);
                v1o.x = gelu_exact(v1o.x); v1o.y = gelu_exact(v1o.y);
            }
            if (row0 < M) *(float2*)&C[(size_t)row0*N + col] = v0o;
            if (row1 < M) *(float2*)&C[(size_t)row1*N + col] = v1o;
        }
    }
}

// ---------------- embedding ----------------
__global__ void embed_kernel(const float* __restrict__ x_enc,
                             const float* __restrict__ xme,
                             const float* __restrict__ xmd,
                             const float* __restrict__ tw,
                             const float* __restrict__ tb,
                             const float* __restrict__ tempw,
                             const float* __restrict__ tempb) {
    int t = blockIdx.x, b = blockIdx.y;
    __shared__ float xv[3][7];
    __shared__ float xm[4];
    int tid = threadIdx.x;   // 128
    if (tid < 21) {
        int k = tid / 7, i = tid % 7;
        int r = t - 1 + k;
        int rr = (r + 1025) % 1025;
        float val = 0.f;
        if (rr < 1024) val = x_enc[((size_t)b*1024 + rr)*7 + i];
        xv[k][i] = val;
    }
    if (tid >= 32 && tid < 36) {
        int m = tid - 32;
        xm[m] = (t < 1024) ? xme[((size_t)b*1024 + t)*4 + m]
                           : xmd[((size_t)b*96)*4 + m];
    }
    __syncthreads();
    for (int d = tid; d < DD; d += 128) {
        float acc = tb[d];
        #pragma unroll
        for (int i = 0; i < 7; i++)
            #pragma unroll
            for (int k = 0; k < 3; k++)
                acc += xv[k][i] * tw[(d*7 + i)*3 + k];
        acc += tempb[d];
        #pragma unroll
        for (int m = 0; m < 4; m++) acc += xm[m] * tempw[m*DD + d];
        int m2 = d & ~1;
        float div = expf(-9.210340371976184f / 512.0f * (float)m2);
        float arg = (float)t * div;
        acc += (d & 1) ? cosf(arg) : sinf(arg);
        g_emb[((size_t)b*LL + t)*DD + d] = acc;
    }
}

// ---------------- conv (stride-4, kernel-4, ELU): 8 outputs per block ----------
__global__ void conv_kernel(const float* __restrict__ in, int ibs, int inOff,
                            const float* __restrict__ w, const float* __restrict__ bias,
                            float* __restrict__ out, int outOff) {
    int t0 = blockIdx.x * 8, b = blockIdx.y;
    int tid = threadIdx.x;   // 128 (= oc)
    __shared__ float si[8*512];
    const float* ip = in + (size_t)(b*ibs + inOff + 4*t0) * 128;
    #pragma unroll
    for (int i = 0; i < 32; i++) si[i*128 + tid] = ip[i*128 + tid];
    __syncthreads();
    float bv = bias[tid];
    float acc[8];
    #pragma unroll
    for (int t = 0; t < 8; t++) acc[t] = bv;
    #pragma unroll 2
    for (int ic = 0; ic < 128; ic++) {
        float4 w4 = *(const float4*)&w[((size_t)tid*128 + ic)*4];
        #pragma unroll
        for (int t = 0; t < 8; t++) {
            const float* s = si + t*512;
            acc[t] += s[ic]*w4.x + s[128+ic]*w4.y + s[256+ic]*w4.z + s[384+ic]*w4.w;
        }
    }
    #pragma unroll
    for (int t = 0; t < 8; t++) {
        float a = acc[t];
        a = (a > 0.f) ? a : expm1f(a);
        out[(size_t)(b*336 + outOff + t0 + t)*128 + tid] = a;
    }
}

// ---------------- LayerNorm: warp-per-row, 8 rows/block, no barriers -----------
__device__ __forceinline__ void ln_row_warp(const float* __restrict__ x0,
                                            const float* __restrict__ x1,
                                            const float* __restrict__ sc,
                                            const float* __restrict__ bb,
                                            float* __restrict__ out,
                                            uint32_t* __restrict__ out_h,
                                            int lane) {
    // lane owns 16 floats: 4x float4 at lane*4 + j*128
    float4 v[4];
    float sum = 0.f;
    #pragma unroll
    for (int j = 0; j < 4; j++) {
        float4 a = *(const float4*)(x0 + lane*4 + j*128);
        if (x1) {
            float4 b = *(const float4*)(x1 + lane*4 + j*128);
            a.x += b.x; a.y += b.y; a.z += b.z; a.w += b.w;
        }
        v[j] = a;
        sum += a.x + a.y + a.z + a.w;
    }
    #pragma unroll
    for (int o = 16; o; o >>= 1) sum += __shfl_xor_sync(0xffffffffu, sum, o);
    float mean = sum * (1.0f/512.0f);
    float sq = 0.f;
    #pragma unroll
    for (int j = 0; j < 4; j++) {
        v[j].x -= mean; v[j].y -= mean; v[j].z -= mean; v[j].w -= mean;
        sq += v[j].x*v[j].x + v[j].y*v[j].y + v[j].z*v[j].z + v[j].w*v[j].w;
    }
    #pragma unroll
    for (int o = 16; o; o >>= 1) sq += __shfl_xor_sync(0xffffffffu, sq, o);
    float inv = rsqrtf(sq * (1.0f/512.0f) + 1e-5f);
    #pragma unroll
    for (int j = 0; j < 4; j++) {
        int idx = lane*4 + j*128;
        float4 s4 = *(const float4*)(sc + idx);
        float4 b4 = *(const float4*)(bb + idx);
        float4 o4;
        o4.x = v[j].x * inv * s4.x + b4.x;
        o4.y = v[j].y * inv * s4.y + b4.y;
        o4.z = v[j].z * inv * s4.z + b4.z;
        o4.w = v[j].w * inv * s4.w + b4.w;
        *(float4*)(out + idx) = o4;
        uint2 h2;
        h2.x = packh2(o4.x, o4.y);
        h2.y = packh2(o4.z, o4.w);
        *(uint2*)(out_h + (idx >> 1)) = h2;
    }
}

__global__ void concat_ln_kernel(const float* __restrict__ sc, const float* __restrict__ bb) {
    int row = blockIdx.x*8 + (threadIdx.x >> 5);
    if (row >= MROWS) return;
    int lane = threadIdx.x & 31;
    int b = row / NT, n = row % NT;
    const float* src = (n < LL) ? &g_emb[((size_t)b*LL + n)*DD]
                                : &g_pyr[((size_t)b*336 + (n - LL))*DD];
    ln_row_warp(src, nullptr, sc, bb, &g_seq[(size_t)row*DD],
                (uint32_t*)g_seqr_h + (size_t)row*(DD/2), lane);
}

__global__ void add_ln_kernel(const float* __restrict__ sc, const float* __restrict__ bb) {
    int row = blockIdx.x*8 + (threadIdx.x >> 5);
    if (row >= MROWS) return;
    int lane = threadIdx.x & 31;
    ln_row_warp(&g_seq[(size_t)row*DD], &g_tmp[(size_t)row*DD], sc, bb,
                &g_seq[(size_t)row*DD],
                (uint32_t*)g_seqr_h + (size_t)row*(DD/2), lane);
}

// ---------------- fused sparse attention (fp16 qkv in, fp32 math, half out) ----
#define MAXN 12
__global__ __launch_bounds__(256)
void attn_kernel() {
    int i = blockIdx.x, b = blockIdx.y;
    __shared__ int s_nbr[MAXN];
    __shared__ int s_nn;
    int tid = threadIdx.x;
    if (tid == 0) {
        const int starts[5] = {0, 1025, 1281, 1345, 1361};
        int li = (i < 1025) ? 0 : (i < 1281) ? 1 : (i < 1345) ? 2 : 3;
        int s = starts[li], e = starts[li+1];
        int nn = 0;
        int jlo = (i - 2 > s) ? i - 2 : s;
        int jhi = (i + 2 < e - 1) ? i + 2 : e - 1;
        for (int j = jlo; j <= jhi; j++) s_nbr[nn++] = j;
        if (li > 0) {
            int ps = starts[li-1];
            int qq = i - s;
            int lo = ps + qq * 4;
            int hi = (i == e - 1) ? s : ps + (qq + 1) * 4;
            for (int j = lo; j < hi; j++) s_nbr[nn++] = j;
        }
        if (li < 3) {
            int su = starts[li+1];
            int szu = starts[li+2] - su;
            int qq = (i - s) / 4;
            s_nbr[nn++] = su + ((qq < szu - 1) ? qq : szu - 1);
        }
        s_nn = nn;
        for (int j = nn; j < MAXN; j++) s_nbr[j] = i;
    }
    __syncthreads();
    int nn = s_nn;
    int h = tid >> 5, lane = tid & 31;
    const uint32_t* qkvh = (const uint32_t*)g_qkv_h;   // half2 units, row stride 768
    size_t rowu = ((size_t)b*NT + i)*768;
    uint32_t qu = qkvh[rowu + h*32 + lane];
    float2 qf = __half22float2(*(__half2*)&qu);

    float dots[MAXN];
    #pragma unroll
    for (int jj = 0; jj < MAXN; jj++) {
        size_t ku = ((size_t)b*NT + s_nbr[jj])*768 + 256 + h*32 + lane;
        uint32_t kk = qkvh[ku];
        float2 kf = __half22float2(*(__half2*)&kk);
        float p = qf.x*kf.x + qf.y*kf.y;
        #pragma unroll
        for (int o = 16; o; o >>= 1) p += __shfl_xor_sync(0xffffffffu, p, o);
        dots[jj] = (jj < nn) ? p * 0.125f : -1e30f;
    }
    float mx = -1e30f;
    #pragma unroll
    for (int jj = 0; jj < MAXN; jj++) mx = fmaxf(mx, dots[jj]);
    float sum = 0.f;
    #pragma unroll
    for (int jj = 0; jj < MAXN; jj++) { dots[jj] = expf(dots[jj] - mx); sum += dots[jj]; }
    float inv = 1.f / sum;
    float o0 = 0.f, o1 = 0.f;
    #pragma unroll
    for (int jj = 0; jj < MAXN; jj++) {
        size_t vu = ((size_t)b*NT + s_nbr[jj])*768 + 512 + h*32 + lane;
        uint32_t vv = qkvh[vu];
        float2 vf = __half22float2(*(__half2*)&vv);
        float w = dots[jj] * inv;
        o0 += w * vf.x;
        o1 += w * vf.y;
    }
    uint32_t* oh = (uint32_t*)g_o_h;
    oh[((size_t)b*NT + i)*256 + h*32 + lane] = packh2(o0, o1);
}

// ---------------- gather + prediction head (split-r partials + reduce) ---------
__global__ void pred_part(const float* __restrict__ pw) {
    int b = blockIdx.x, ch = blockIdx.y;   // 8 chunks of 256 rows
    __shared__ float gv[256];
    const int rows[4] = {1024, 1280, 1344, 1360};
    int tid = threadIdx.x;   // 672
    if (tid < 256) {
        int r = ch*256 + tid;
        int wch = r >> 9, d = r & 511;
        gv[tid] = g_seq[((size_t)b*NT + rows[wch])*DD + d];
    }
    __syncthreads();
    float acc = 0.f;
    const float* p = pw + (size_t)(ch*256)*672 + tid;
    #pragma unroll 8
    for (int j = 0; j < 256; j++) acc += gv[j] * p[(size_t)j*672];
    g_predp[(b*8 + ch)*672 + tid] = acc;
}
__global__ void pred_reduce(float* __restrict__ out) {
    int idx = blockIdx.x*blockDim.x + threadIdx.x;   // BB*672
    if (idx >= BB*672) return;
    int b = idx / 672, c = idx % 672;
    float s = 0.f;
    #pragma unroll
    for (int ch = 0; ch < 8; ch++) s += g_predp[(b*8 + ch)*672 + c];
    out[idx] = s;
}

// ---------------- host ----------------
static void launch_tf32(const float* A, const float* Bm, const float* bias,
                        float* C, int M, int N, int K) {
    dim3 grid(N / 128, (M + 127) / 128);
    tgemm_kernel<0><<<grid, 256>>>(A, Bm, bias, C, M, N, K);
}

extern "C" void kernel_launch(void* const* d_in, const int* in_sizes, int n_in,
                              void* d_out, int out_size) {
    const float* x_enc   = (const float*)d_in[0];
    const float* xme     = (const float*)d_in[1];
    // d_in[2] = x_dec (unused by the model math)
    const float* xmd     = (const float*)d_in[3];
    const float* token_w = (const float*)d_in[4];
    const float* token_b = (const float*)d_in[5];
    const float* temp_w  = (const float*)d_in[6];
    const float* temp_b  = (const float*)d_in[7];
    const float* down_w  = (const float*)d_in[8];
    const float* down_b  = (const float*)d_in[9];
    const float* conv_w  = (const float*)d_in[10];
    const float* conv_b  = (const float*)d_in[11];
    const float* up_w    = (const float*)d_in[12];
    const float* up_b    = (const float*)d_in[13];
    const float* cln_s   = (const float*)d_in[14];
    const float* cln_b   = (const float*)d_in[15];
    const float* Wq      = (const float*)d_in[16];
    const float* Wk      = (const float*)d_in[17];
    const float* Wv      = (const float*)d_in[18];
    const float* Wo      = (const float*)d_in[19];
    const float* bo      = (const float*)d_in[20];
    const float* ln1_s   = (const float*)d_in[21];
    const float* ln1_b   = (const float*)d_in[22];
    const float* W1      = (const float*)d_in[23];
    const float* b1      = (const float*)d_in[24];
    const float* W2      = (const float*)d_in[25];
    const float* b2      = (const float*)d_in[26];
    const float* ln2_s   = (const float*)d_in[27];
    const float* ln2_b   = (const float*)d_in[28];
    const float* pred_w  = (const float*)d_in[29];

    float *emb, *d0, *cc, *pyr, *seq, *tmp;
    uint32_t *seqr_h, *qkv_h, *o_h, *ffn_h, *wqkvh, *woh, *w1h, *w2h;
    cudaGetSymbolAddress((void**)&emb,  g_emb);
    cudaGetSymbolAddress((void**)&d0,   g_d0);
    cudaGetSymbolAddress((void**)&cc,   g_cc);
    cudaGetSymbolAddress((void**)&pyr,  g_pyr);
    cudaGetSymbolAddress((void**)&seq,  g_seq);
    cudaGetSymbolAddress((void**)&tmp,  g_tmp);
    cudaGetSymbolAddress((void**)&seqr_h, g_seqr_h);
    cudaGetSymbolAddress((void**)&qkv_h,  g_qkv_h);
    cudaGetSymbolAddress((void**)&o_h,    g_o_h);
    cudaGetSymbolAddress((void**)&ffn_h,  g_ffn_h);
    cudaGetSymbolAddress((void**)&wqkvh,  g_wqkvh);
    cudaGetSymbolAddress((void**)&woh,    g_woh);
    cudaGetSymbolAddress((void**)&w1h,    g_w1h);
    cudaGetSymbolAddress((void**)&w2h,    g_w2h);

    cudaFuncSetAttribute(hgemm_kernel<0,0>, cudaFuncAttributeMaxDynamicSharedMemorySize, HG_SMEM);
    cudaFuncSetAttribute(hgemm_kernel<0,1>, cudaFuncAttributeMaxDynamicSharedMemorySize, HG_SMEM);
    cudaFuncSetAttribute(hgemm_kernel<1,1>, cudaFuncAttributeMaxDynamicSharedMemorySize, HG_SMEM);

    // 0) pack all encoder weights to fp16 pair layout [K/2][N] (vectorized)
    pack_qkvh<<<(4*256*384 + 255)/256, 256>>>(Wq, Wk, Wv, wqkvh);
    packh<<<(4*256*128 + 255)/256, 256>>>(Wo, woh, 512, 512, 4*256*128);
    packh<<<(4*256*512 + 255)/256, 256>>>(W1, w1h, 512, 2048, 4*256*512);
    packh<<<(4*1024*128 + 255)/256, 256>>>(W2, w2h, 2048, 512, 4*1024*128);

    // 1) embedding
    embed_kernel<<<dim3(LL, BB), 128>>>(x_enc, xme, xmd, token_w, token_b, temp_w, temp_b);

    // 2) bottleneck down-projection (tf32 path)
    launch_tf32(emb, down_w, down_b, d0, BB*LL, 128, DD);

    // 3) pyramid convs (8 outputs per block)
    conv_kernel<<<dim3(32, BB), 128>>>(d0, LL, 0,   conv_w,               conv_b,       cc, 0);
    conv_kernel<<<dim3(8,  BB), 128>>>(cc, 336, 0,  conv_w + 128*128*4,   conv_b + 128, cc, 256);
    conv_kernel<<<dim3(2,  BB), 128>>>(cc, 336, 256,conv_w + 2*128*128*4, conv_b + 256, cc, 320);

    // 4) up-projection (tf32 path)
    launch_tf32(cc, up_w, up_b, pyr, BB*336, DD, 128);

    // 5) concat + LayerNorm -> seq (+ half copy); warp-per-row
    const int LNB = (MROWS + 7) / 8;   // 681
    concat_ln_kernel<<<LNB, 256>>>(cln_s, cln_b);

    // 6) encoder layers (fp16 GEMMs, cp.async 4-stage; qkv stored fp16)
    const int MT = (MROWS + 127) / 128;   // 43
    for (int i = 0; i < 4; i++) {
        hgemm_kernel<0,1><<<dim3(12, MT), 256, HG_SMEM>>>(
            seqr_h, wqkvh + (size_t)i*256*1536, nullptr, qkv_h, MROWS, 1536, 512);

        attn_kernel<<<dim3(NT, BB), 256>>>();

        hgemm_kernel<0,0><<<dim3(4, MT), 256, HG_SMEM>>>(
            o_h, woh + (size_t)i*256*512, bo + i*DD, tmp, MROWS, 512, 512);
        add_ln_kernel<<<LNB, 256>>>(ln1_s + i*DD, ln1_b + i*DD);

        hgemm_kernel<1,1><<<dim3(16, MT), 256, HG_SMEM>>>(
            seqr_h, w1h + (size_t)i*256*2048, b1 + i*DFF, ffn_h, MROWS, 2048, 512);
        hgemm_kernel<0,0><<<dim3(4, MT), 256, HG_SMEM>>>(
            ffn_h, w2h + (size_t)i*1024*512, b2 + i*DD, tmp, MROWS, 512, 2048);
        add_ln_kernel<<<LNB, 256>>>(ln2_s + i*DD, ln2_b + i*DD);
    }

    // 7) gather + prediction head (split partials, deterministic reduce)
    pred_part<<<dim3(BB, 8), 672>>>(pred_w);
    pred_reduce<<<(BB*672 + 255)/256, 256>>>((float*)d_out);
}